// round 8
// baseline (speedup 1.0000x reference)
#include <cuda_runtime.h>
#include <cuda_fp16.h>
#include <cstdint>

#define B_  4
#define S_  2048
#define DM_ 512
#define H_  8
#define D_  64
#define K2_ 1024            // 2x hi/lo expanded K
#define NCHUNK 16           // K2_/64

// ================= helpers =================
__device__ __forceinline__ uint32_t smem_u32(const void* p) {
    uint32_t a;
    asm("{ .reg .u64 t; cvta.to.shared.u64 t, %1; cvt.u32.u64 %0, t; }" : "=r"(a) : "l"(p));
    return a;
}
#define SWZ128(off) ((off) ^ (((off) >> 3) & 0x70))

__device__ __forceinline__ void cp_async16(uint32_t dst, const void* src) {
    asm volatile("cp.async.cg.shared.global [%0], [%1], 16;" :: "r"(dst), "l"(src));
}
__device__ __forceinline__ void cp_async16z(uint32_t dst, const void* src, uint32_t n) {
    asm volatile("cp.async.cg.shared.global [%0], [%1], 16, %2;" :: "r"(dst), "l"(src), "r"(n));
}
#define CP_COMMIT() asm volatile("cp.async.commit_group;" ::: "memory")
#define CP_WAIT(n)  asm volatile("cp.async.wait_group %0;" :: "n"(n) : "memory")

__device__ __forceinline__ void ldmx4(uint32_t& r0, uint32_t& r1, uint32_t& r2, uint32_t& r3,
                                      uint32_t addr) {
    asm volatile("ldmatrix.sync.aligned.m8n8.x4.shared.b16 {%0,%1,%2,%3}, [%4];"
                 : "=r"(r0), "=r"(r1), "=r"(r2), "=r"(r3) : "r"(addr));
}
__device__ __forceinline__ void mma16816(float* c, const uint32_t* a, uint32_t b0, uint32_t b1) {
    asm volatile(
        "mma.sync.aligned.m16n8k16.row.col.f32.f16.f16.f32 "
        "{%0,%1,%2,%3}, {%4,%5,%6,%7}, {%8,%9}, {%0,%1,%2,%3};"
        : "+f"(c[0]), "+f"(c[1]), "+f"(c[2]), "+f"(c[3])
        : "r"(a[0]), "r"(a[1]), "r"(a[2]), "r"(a[3]), "r"(b0), "r"(b1));
}
// A-side pair: (hi, lo)
__device__ __forceinline__ void pack2A(float a, float b, uint32_t* w) {
    const __half ha = __float2half_rn(a);
    const __half la = __float2half_rn(a - __half2float(ha));
    const __half hb = __float2half_rn(b);
    const __half lb = __float2half_rn(b - __half2float(hb));
    w[0] = (uint32_t)__half_as_ushort(ha) | ((uint32_t)__half_as_ushort(la) << 16);
    w[1] = (uint32_t)__half_as_ushort(hb) | ((uint32_t)__half_as_ushort(lb) << 16);
}
// B-side pair: (hi, hi)
__device__ __forceinline__ void pack2B(float a, float b, uint32_t* w) {
    const uint32_t ha = __half_as_ushort(__float2half_rn(a));
    const uint32_t hb = __half_as_ushort(__float2half_rn(b));
    w[0] = ha | (ha << 16);
    w[1] = hb | (hb << 16);
}

// ================= scratch =================
__device__ float g_v[B_ * S_ * DM_];
__device__ float g_part[B_ * 64 * DM_];
__device__ float g_vmean[B_ * DM_];
__device__ __half g_x2[B_ * S_ * K2_];        // x pairs (A), later ctx pairs (A)
__device__ __half g_q2[B_ * S_ * K2_];        // q pairs (A)
__device__ __half g_k2[B_ * S_ * K2_];        // k pairs (B)
__device__ __half g_w2t[4 * DM_ * K2_];       // weights (B), [N,K2]
__device__ __half g_v2t[2048 * 4608];         // V dims-major pairs (B), tokens padded

// ================= split kernels =================
__global__ __launch_bounds__(256) void split_act2(const float* __restrict__ X,
                                                  __half* __restrict__ X2) {
    const int idx = blockIdx.x * 256 + threadIdx.x;
    const int m = idx >> 6, g = idx & 63;
    const float4 f0 = *(const float4*)(X + (size_t)m * 512 + g * 8);
    const float4 f1 = *(const float4*)(X + (size_t)m * 512 + g * 8 + 4);
    float v[8] = {f0.x, f0.y, f0.z, f0.w, f1.x, f1.y, f1.z, f1.w};
    uint32_t w[8];
#pragma unroll
    for (int i = 0; i < 4; i++) pack2A(v[2 * i], v[2 * i + 1], w + 2 * i);
    uint4* dst = (uint4*)(X2 + (size_t)m * K2_ + g * 16);
    dst[0] = ((uint4*)w)[0]; dst[1] = ((uint4*)w)[1];
}

__global__ __launch_bounds__(1024) void split_w4(const float* __restrict__ W0,
                                                 const float* __restrict__ W1,
                                                 const float* __restrict__ W2,
                                                 const float* __restrict__ W3,
                                                 __half* __restrict__ W2T) {
    __shared__ float t[32][33];
    const int z = blockIdx.z;
    const float* W = (z == 0) ? W0 : (z == 1) ? W1 : (z == 2) ? W2 : W3;
    const int k0 = blockIdx.y * 32, n0 = blockIdx.x * 32;
    const int tx = threadIdx.x, ty = threadIdx.y;
    t[ty][tx] = W[(size_t)(k0 + ty) * 512 + n0 + tx];
    __syncthreads();
    const float v = t[tx][ty];
    const uint32_t h = __half_as_ushort(__float2half_rn(v));
    uint32_t* dst = (uint32_t*)W2T + (size_t)z * DM_ * 512 + (size_t)(n0 + ty) * 512 + (k0 + tx);
    *dst = h | (h << 16);
}

// ================= 256x128 HMMA GEMM mainloop =================
#define GEMM_SMEM (3 * 49152 + 1024)

#define GEMM_MAINLOOP256(A2, B2)                                                          \
    extern __shared__ char smraw[];                                                       \
    const uint32_t sbase = (smem_u32(smraw) + 1023) & ~1023u;                             \
    const int tid = threadIdx.x;                                                          \
    const int wid = tid >> 5, lane = tid & 31;                                            \
    const int bm = blockIdx.x * 256, bn = blockIdx.y * 128;                               \
    const int wm0 = (wid & 3) * 64, wn0 = (wid >> 2) * 64;                                \
    const __half* l_srcA = A2 + (size_t)(bm + tid) * K2_;                                 \
    const __half* l_srcB = B2 + (size_t)(bn + (tid >> 1)) * K2_ + (tid & 1) * 32;         \
    const uint32_t a_doff = SWZ128(tid * 128);                                            \
    const uint32_t b_doff = 49152 - 16384 + SWZ128((tid >> 1) * 128 + (tid & 1) * 64);    \
    float acc[4][8][4];                                                                   \
    _Pragma("unroll")                                                                     \
    for (int a = 0; a < 4; a++)                                                           \
        _Pragma("unroll")                                                                 \
        for (int b = 0; b < 8; b++)                                                       \
            _Pragma("unroll")                                                             \
            for (int c = 0; c < 4; c++) acc[a][b][c] = 0.f;                               \
    _Pragma("unroll")                                                                     \
    for (int c = 0; c < 2; c++) {                                                         \
        const uint32_t st = sbase + c * 49152;                                            \
        _Pragma("unroll")                                                                 \
        for (int seg = 0; seg < 8; seg++)                                                 \
            cp_async16(st + (a_doff ^ (seg * 16)), l_srcA + c * 64 + seg * 8);            \
        _Pragma("unroll")                                                                 \
        for (int u = 0; u < 4; u++)                                                       \
            cp_async16(st + (b_doff ^ (u * 16)), l_srcB + c * 64 + u * 8);                \
        CP_COMMIT();                                                                      \
    }                                                                                     \
    for (int c = 0; c < NCHUNK; c++) {                                                    \
        CP_WAIT(1);                                                                       \
        __syncthreads();                                                                  \
        if (c + 2 < NCHUNK) {                                                             \
            const uint32_t st = sbase + ((c + 2) % 3) * 49152;                            \
            _Pragma("unroll")                                                             \
            for (int seg = 0; seg < 8; seg++)                                             \
                cp_async16(st + (a_doff ^ (seg * 16)), l_srcA + (c + 2) * 64 + seg * 8);  \
            _Pragma("unroll")                                                             \
            for (int u = 0; u < 4; u++)                                                   \
                cp_async16(st + (b_doff ^ (u * 16)), l_srcB + (c + 2) * 64 + u * 8);      \
        }                                                                                 \
        CP_COMMIT();                                                                      \
        const uint32_t abuf = sbase + (c % 3) * 49152;                                    \
        const uint32_t bbuf = abuf + 32768;                                               \
        _Pragma("unroll")                                                                 \
        for (int ks = 0; ks < 4; ks++) {                                                  \
            const int cb = ks * 32 + ((lane >> 4) * 16);                                  \
            uint32_t bf[4][4];                                                            \
            _Pragma("unroll")                                                             \
            for (int bh = 0; bh < 4; bh++) {                                              \
                const int r = wn0 + bh * 16 + (lane & 15);                                \
                ldmx4(bf[bh][0], bf[bh][1], bf[bh][2], bf[bh][3],                         \
                      bbuf + SWZ128(r * 128 + cb));                                       \
            }                                                                             \
            _Pragma("unroll")                                                             \
            for (int mf = 0; mf < 4; mf++) {                                              \
                uint32_t a[4];                                                            \
                const int r = wm0 + mf * 16 + (lane & 15);                                \
                ldmx4(a[0], a[1], a[2], a[3], abuf + SWZ128(r * 128 + cb));               \
                _Pragma("unroll")                                                         \
                for (int nf = 0; nf < 8; nf++) {                                          \
                    const uint32_t b0 = bf[nf >> 1][(nf & 1)];                            \
                    const uint32_t b1 = bf[nf >> 1][(nf & 1) + 2];                        \
                    mma16816(acc[mf][nf], a, b0, b1);                                     \
                }                                                                         \
            }                                                                             \
        }                                                                                 \
    }                                                                                     \
    const int qr = lane >> 2, qc = (lane & 3) * 2;

// unified QKV: z=0 -> Q pairs(A), z=1 -> K pairs(B), z=2 -> V fp32
__global__ __launch_bounds__(256, 1) void gemm_qkv(const __half* __restrict__ A2,
                                                   const __half* __restrict__ W2T,
                                                   const float* __restrict__ bq,
                                                   const float* __restrict__ bk,
                                                   const float* __restrict__ bv,
                                                   __half* __restrict__ Q2,
                                                   __half* __restrict__ K2,
                                                   float* __restrict__ Vf) {
    const int z = blockIdx.z;
    const __half* B2 = W2T + (size_t)z * DM_ * K2_;
    GEMM_MAINLOOP256(A2, B2)
    const float* bias = (z == 0) ? bq : (z == 1) ? bk : bv;
    if (z == 2) {
#pragma unroll
        for (int mf = 0; mf < 4; mf++) {
            const int row = bm + wm0 + mf * 16 + qr;
#pragma unroll
            for (int nf = 0; nf < 8; nf++) {
                const int col = bn + wn0 + nf * 8 + qc;
                const float b0 = bias[col], b1 = bias[col + 1];
                float2 lo, hi;
                lo.x = acc[mf][nf][0] + b0; lo.y = acc[mf][nf][1] + b1;
                hi.x = acc[mf][nf][2] + b0; hi.y = acc[mf][nf][3] + b1;
                *(float2*)(Vf + (size_t)row * 512 + col) = lo;
                *(float2*)(Vf + (size_t)(row + 8) * 512 + col) = hi;
            }
        }
    } else {
        uint32_t* t32 = (uint32_t*)((z == 0) ? Q2 : K2);
#pragma unroll
        for (int mf = 0; mf < 4; mf++) {
            const int row = bm + wm0 + mf * 16 + qr;
#pragma unroll
            for (int nf = 0; nf < 8; nf++) {
                const int col = bn + wn0 + nf * 8 + qc;
                const float b0 = bias[col], b1 = bias[col + 1];
                uint32_t w[2];
                const uint32_t idx0 = (uint32_t)row * 512 + col;
                const uint32_t idx1 = idx0 + 8 * 512;
                if (z == 0) pack2A(acc[mf][nf][0] + b0, acc[mf][nf][1] + b1, w);
                else        pack2B(acc[mf][nf][0] + b0, acc[mf][nf][1] + b1, w);
                t32[idx0] = w[0]; t32[idx0 + 1] = w[1];
                if (z == 0) pack2A(acc[mf][nf][2] + b0, acc[mf][nf][3] + b1, w);
                else        pack2B(acc[mf][nf][2] + b0, acc[mf][nf][3] + b1, w);
                t32[idx1] = w[0]; t32[idx1 + 1] = w[1];
            }
        }
    }
}

// output projection: fp32 out
__global__ __launch_bounds__(256, 1) void gemm_out(const __half* __restrict__ A2,
                                                   const __half* __restrict__ B2,
                                                   const float* __restrict__ bias,
                                                   float* __restrict__ C) {
    GEMM_MAINLOOP256(A2, B2)
#pragma unroll
    for (int mf = 0; mf < 4; mf++) {
        const int row = bm + wm0 + mf * 16 + qr;
#pragma unroll
        for (int nf = 0; nf < 8; nf++) {
            const int col = bn + wn0 + nf * 8 + qc;
            const float b0 = bias[col], b1 = bias[col + 1];
            float2 lo, hi;
            lo.x = acc[mf][nf][0] + b0; lo.y = acc[mf][nf][1] + b1;
            hi.x = acc[mf][nf][2] + b0; hi.y = acc[mf][nf][3] + b1;
            *(float2*)(C + (size_t)row * 512 + col) = lo;
            *(float2*)(C + (size_t)(row + 8) * 512 + col) = hi;
        }
    }
}

// ================= V transpose->pair build =================
__global__ __launch_bounds__(256) void v2t_build(const float* __restrict__ V,
                                                 __half* __restrict__ V2T) {
    __shared__ float tr[64][65];
    const int cx = blockIdx.x;
    const int h = blockIdx.y, b = blockIdx.z;
    const int tid = threadIdx.x;
    const int t0 = cx * 64 - 128;
    const bool inr = (t0 >= 0) && (t0 + 64 <= S_);

    if (inr) {
        const int i = tid >> 2, dg = tid & 3;
        const float* vrow = V + ((size_t)(b * S_ + t0 + i)) * DM_ + h * D_ + dg * 16;
#pragma unroll
        for (int u = 0; u < 4; u++) {
            float4 f = *(const float4*)(vrow + u * 4);
            tr[dg * 16 + u * 4 + 0][i] = f.x;
            tr[dg * 16 + u * 4 + 1][i] = f.y;
            tr[dg * 16 + u * 4 + 2][i] = f.z;
            tr[dg * 16 + u * 4 + 3][i] = f.w;
        }
        __syncthreads();
    }

    const int d = tid >> 2, jg = tid & 3;
    uint32_t w[16];
    if (inr) {
#pragma unroll
        for (int t = 0; t < 8; t++)
            pack2B(tr[d][jg * 16 + 2 * t], tr[d][jg * 16 + 2 * t + 1], w + 2 * t);
    } else {
#pragma unroll
        for (int t = 0; t < 16; t++) w[t] = 0;
    }
    uint4* dst = (uint4*)((char*)V2T + ((size_t)((b * 8 + h) * 64 + d) * 4608) * 2
                          + (size_t)cx * 256 + jg * 64);
#pragma unroll
    for (int u = 0; u < 4; u++) dst[u] = ((uint4*)w)[u];
}

// ================= V mean =================
__global__ void vmean_partial(const float* __restrict__ V, float* __restrict__ part) {
    const int b = blockIdx.y, sc = blockIdx.x, c = threadIdx.x;
    const float* p = V + ((size_t)b * S_ + sc * 32) * DM_ + c;
    float s = 0.f;
#pragma unroll 8
    for (int t = 0; t < 32; t++) s += p[(size_t)t * DM_];
    part[((size_t)b * 64 + sc) * DM_ + c] = s;
}
__global__ void vmean_final(const float* __restrict__ part, float* __restrict__ vm) {
    const int b = blockIdx.x, c = threadIdx.x;
    const float* p = part + (size_t)b * 64 * DM_ + c;
    float s = 0.f;
#pragma unroll
    for (int t = 0; t < 64; t++) s += p[(size_t)t * DM_];
    vm[b * DM_ + c] = s * (1.0f / 2048.0f);
}

// ================= flash-style banded attention (fp16 pairs, online softmax) =================
// 128 queries/block, 8 warps x 16 queries, 6 key chunks of 64.
// smem: QP buf (Q then P, warp-local reuse) 128x272, K dbl 2x64x272, V dbl 2x64x272.
#define FA_QP 0
#define FA_K0 34816
#define FA_K1 52224
#define FA_V0 69632
#define FA_V1 87040
#define FA_SMEM 104512

__global__ __launch_bounds__(256, 1) void attn_fa(const __half* __restrict__ Q2,
                                                  const __half* __restrict__ K2,
                                                  const __half* __restrict__ V2T,
                                                  const float* __restrict__ VMEAN,
                                                  const int* __restrict__ XLEN,
                                                  __half* __restrict__ C2) {
    extern __shared__ char smc[];
    const uint32_t sb = smem_u32(smc);

    const int tid = threadIdx.x;
    const int wid = tid >> 5, lane = tid & 31;
    const int q0 = blockIdx.x * 128;
    const int h = blockIdx.y;
    const int b = blockIdx.z;
    const int xl = XLEN[b];

    const int wm = wid * 16;
    const int qr = lane >> 2, qc = (lane & 3) * 2;
    const int kbase0 = q0 - 128;

    const int lrowK = tid >> 2;           // 0..63 (K/V rows)
    const int lcsK = (tid & 3) * 4;       // 4 segs of 16B

    // ---- issue Q (128 rows x 16 segs) + K0 + V0 as group 0 ----
    {
        const int r = tid >> 1;
        const int s0 = (tid & 1) * 8;
        const char* qsrc = (const char*)Q2 + ((size_t)(b * S_ + q0 + r) * K2_ + h * 128) * 2;
#pragma unroll
        for (int u = 0; u < 8; u++)
            cp_async16(sb + FA_QP + r * 272 + (s0 + u) * 16, qsrc + (s0 + u) * 16);
    }
#pragma unroll
    for (int c = 0; c < 2; c++) {
        const int jabs = kbase0 + c * 64 + lrowK;
        const bool valid = (jabs >= 0) && (jabs < S_);
        const char* ksrc = (const char*)K2 + ((size_t)(b * S_ + (valid ? jabs : 0)) * K2_ + h * 128) * 2;
        const uint32_t kb2 = sb + (c ? FA_K1 : FA_K0);
        const uint32_t n = valid ? 16u : 0u;
#pragma unroll
        for (int u = 0; u < 4; u++)
            cp_async16z(kb2 + lrowK * 272 + (lcsK + u) * 16, ksrc + (lcsK + u) * 16, n);
        const char* vsrc = (const char*)V2T + ((size_t)((b * 8 + h) * 64 + lrowK) * 4608) * 2
                           + (size_t)(q0 + c * 64) * 4;
        const uint32_t vb2 = sb + (c ? FA_V1 : FA_V0);
#pragma unroll
        for (int u = 0; u < 4; u++)
            cp_async16(vb2 + lrowK * 272 + (lcsK + u) * 16, vsrc + (lcsK + u) * 16);
        CP_COMMIT();
    }

    uint32_t qf[8][4];
    float oacc[8][4];
#pragma unroll
    for (int nf = 0; nf < 8; nf++)
#pragma unroll
        for (int u = 0; u < 4; u++) oacc[nf][u] = 0.f;
    float m0 = -1e30f, m1 = -1e30f, l0 = 0.f, l1 = 0.f;

    const int iabs0 = q0 + wm + qr;
    const int iabs1 = iabs0 + 8;

#pragma unroll
    for (int c = 0; c < 6; c++) {
        CP_WAIT(1);
        __syncthreads();
        if (c == 0) {
            // load Q fragments once; QP buffer becomes the P buffer afterwards
#pragma unroll
            for (int ks = 0; ks < 8; ks++) {
                const int cb = ks * 32 + (lane >> 4) * 16;
                ldmx4(qf[ks][0], qf[ks][1], qf[ks][2], qf[ks][3],
                      sb + FA_QP + (wm + (lane & 15)) * 272 + cb);
            }
            __syncwarp();
        }
        const uint32_t kbuf = sb + ((c & 1) ? FA_K1 : FA_K0);
        const uint32_t vbuf = sb + ((c & 1) ? FA_V1 : FA_V0);
        const int kb = kbase0 + c * 64;

        // ---- QK chunk ----
        float acc[8][4];
#pragma unroll
        for (int nf = 0; nf < 8; nf++)
#pragma unroll
            for (int u = 0; u < 4; u++) acc[nf][u] = 0.f;
#pragma unroll
        for (int ks = 0; ks < 8; ks++) {
            const int cb = ks * 32 + (lane >> 4) * 16;
            uint32_t bf[4][4];
#pragma unroll
            for (int bh = 0; bh < 4; bh++) {
                const int r = bh * 16 + (lane & 15);
                ldmx4(bf[bh][0], bf[bh][1], bf[bh][2], bf[bh][3], kbuf + r * 272 + cb);
            }
#pragma unroll
            for (int nf = 0; nf < 8; nf++) {
                const uint32_t b0 = bf[nf >> 1][(nf & 1)];
                const uint32_t b1 = bf[nf >> 1][(nf & 1) + 2];
                mma16816(acc[nf], qf[ks], b0, b1);
            }
        }

        // ---- mask + online softmax (registers) ----
        float cm0 = -1e30f, cm1 = -1e30f;
#pragma unroll
        for (int nf = 0; nf < 8; nf++) {
#pragma unroll
            for (int cc = 0; cc < 2; cc++) {
                const int jabs = kb + nf * 8 + qc + cc;
                const bool jok = (jabs >= 0) && (jabs < xl);
                const bool v0 = jok && (jabs - iabs0 <= 128) && (iabs0 - jabs <= 128);
                const bool v1 = jok && (jabs - iabs1 <= 128) && (iabs1 - jabs <= 128);
                acc[nf][cc]     = v0 ? acc[nf][cc] * 0.125f     : -1e30f;
                acc[nf][cc + 2] = v1 ? acc[nf][cc + 2] * 0.125f : -1e30f;
                cm0 = fmaxf(cm0, acc[nf][cc]);
                cm1 = fmaxf(cm1, acc[nf][cc + 2]);
            }
        }
        cm0 = fmaxf(cm0, __shfl_xor_sync(0xffffffffu, cm0, 1));
        cm0 = fmaxf(cm0, __shfl_xor_sync(0xffffffffu, cm0, 2));
        cm1 = fmaxf(cm1, __shfl_xor_sync(0xffffffffu, cm1, 1));
        cm1 = fmaxf(cm1, __shfl_xor_sync(0xffffffffu, cm1, 2));
        const float m0n = fmaxf(m0, cm0);
        const float m1n = fmaxf(m1, cm1);
        const float sc0 = __expf(m0 - m0n);
        const float sc1 = __expf(m1 - m1n);
        float rs0 = 0.f, rs1 = 0.f;
#pragma unroll
        for (int nf = 0; nf < 8; nf++) {
            float p[4];
#pragma unroll
            for (int cc = 0; cc < 2; cc++) {
                p[cc]     = (acc[nf][cc]     == -1e30f) ? 0.f : __expf(acc[nf][cc]     - m0n);
                p[cc + 2] = (acc[nf][cc + 2] == -1e30f) ? 0.f : __expf(acc[nf][cc + 2] - m1n);
                rs0 += p[cc]; rs1 += p[cc + 2];
            }
            // store P pairs (A pattern) into warp-local rows of the QP buffer
            uint32_t w[2];
            pack2A(p[0], p[1], w);
            *(uint2*)(smc + FA_QP + (wm + qr) * 272 + (nf * 8 + qc) * 4) = make_uint2(w[0], w[1]);
            pack2A(p[2], p[3], w);
            *(uint2*)(smc + FA_QP + (wm + qr + 8) * 272 + (nf * 8 + qc) * 4) = make_uint2(w[0], w[1]);
        }
        rs0 += __shfl_xor_sync(0xffffffffu, rs0, 1);
        rs0 += __shfl_xor_sync(0xffffffffu, rs0, 2);
        rs1 += __shfl_xor_sync(0xffffffffu, rs1, 1);
        rs1 += __shfl_xor_sync(0xffffffffu, rs1, 2);
        l0 = l0 * sc0 + rs0;
        l1 = l1 * sc1 + rs1;
        m0 = m0n; m1 = m1n;
#pragma unroll
        for (int nf = 0; nf < 8; nf++) {
            oacc[nf][0] *= sc0; oacc[nf][1] *= sc0;
            oacc[nf][2] *= sc1; oacc[nf][3] *= sc1;
        }
        __syncwarp();   // P stores visible to this warp's ldmatrix

        // ---- AV chunk ----
#pragma unroll
        for (int ks = 0; ks < 8; ks++) {
            const int cb = ks * 32 + (lane >> 4) * 16;
            uint32_t a[4];
            ldmx4(a[0], a[1], a[2], a[3], sb + FA_QP + (wm + (lane & 15)) * 272 + cb);
            uint32_t bf[4][4];
#pragma unroll
            for (int bh = 0; bh < 4; bh++) {
                const int r = bh * 16 + (lane & 15);
                ldmx4(bf[bh][0], bf[bh][1], bf[bh][2], bf[bh][3], vbuf + r * 272 + cb);
            }
#pragma unroll
            for (int nf = 0; nf < 8; nf++) {
                const uint32_t b0 = bf[nf >> 1][(nf & 1)];
                const uint32_t b1 = bf[nf >> 1][(nf & 1) + 2];
                mma16816(oacc[nf], a, b0, b1);
            }
        }

        __syncthreads();   // all warps done reading K/V buffers before refill
        if (c + 2 < 6) {
            const int cc2 = c + 2;
            const int jabs = kbase0 + cc2 * 64 + lrowK;
            const bool valid = (jabs >= 0) && (jabs < S_);
            const char* ksrc = (const char*)K2 + ((size_t)(b * S_ + (valid ? jabs : 0)) * K2_ + h * 128) * 2;
            const uint32_t kb2 = sb + ((cc2 & 1) ? FA_K1 : FA_K0);
            const uint32_t n = valid ? 16u : 0u;
#pragma unroll
            for (int u = 0; u < 4; u++)
                cp_async16z(kb2 + lrowK * 272 + (lcsK + u) * 16, ksrc + (lcsK + u) * 16, n);
            const char* vsrc = (const char*)V2T + ((size_t)((b * 8 + h) * 64 + lrowK) * 4608) * 2
                               + (size_t)(q0 + cc2 * 64) * 4;
            const uint32_t vb2 = sb + ((cc2 & 1) ? FA_V1 : FA_V0);
#pragma unroll
            for (int u = 0; u < 4; u++)
                cp_async16(vb2 + lrowK * 272 + (lcsK + u) * 16, vsrc + (lcsK + u) * 16);
        }
        CP_COMMIT();
    }

    // ---- final write: normalize, pack pairs (A pattern), deg override ----
    {
        const float il0 = 1.0f / l0;
        const float il1 = 1.0f / l1;
        int lo0 = iabs0 - 128; if (lo0 < 0) lo0 = 0;
        int lo1 = iabs1 - 128; if (lo1 < 0) lo1 = 0;
        const bool deg0 = (lo0 >= xl);
        const bool deg1 = (lo1 >= xl);
        uint32_t* crow0 = (uint32_t*)C2 + (size_t)(b * S_ + iabs0) * 512 + h * 64;
        uint32_t* crow1 = (uint32_t*)C2 + (size_t)(b * S_ + iabs1) * 512 + h * 64;
        const float* vm = VMEAN + b * 512 + h * 64;
#pragma unroll
        for (int nf = 0; nf < 8; nf++) {
            const int col = nf * 8 + qc;
            uint32_t w[2];
            const float a0 = deg0 ? vm[col]     : oacc[nf][0] * il0;
            const float a1 = deg0 ? vm[col + 1] : oacc[nf][1] * il0;
            pack2A(a0, a1, w);
            crow0[col] = w[0]; crow0[col + 1] = w[1];
            const float b0v = deg1 ? vm[col]     : oacc[nf][2] * il1;
            const float b1v = deg1 ? vm[col + 1] : oacc[nf][3] * il1;
            pack2A(b0v, b1v, w);
            crow1[col] = w[0]; crow1[col + 1] = w[1];
        }
    }
}

// ================= launch =================
extern "C" void kernel_launch(void* const* d_in, const int* in_sizes, int n_in,
                              void* d_out, int out_size) {
    const float* x  = (const float*)d_in[0];
    const float* Wq = (const float*)d_in[1];
    const float* bq = (const float*)d_in[2];
    const float* Wk = (const float*)d_in[3];
    const float* bk = (const float*)d_in[4];
    const float* Wv = (const float*)d_in[5];
    const float* bv = (const float*)d_in[6];
    const float* Wo = (const float*)d_in[7];
    const float* bo = (const float*)d_in[8];
    const int* xlen = (const int*)d_in[9];
    float* out = (float*)d_out;

    float *v, *part, *vmean;
    __half *x2, *q2, *k2, *w2t, *v2t;
    cudaGetSymbolAddress((void**)&v, g_v);
    cudaGetSymbolAddress((void**)&part, g_part);
    cudaGetSymbolAddress((void**)&vmean, g_vmean);
    cudaGetSymbolAddress((void**)&x2, g_x2);
    cudaGetSymbolAddress((void**)&q2, g_q2);
    cudaGetSymbolAddress((void**)&k2, g_k2);
    cudaGetSymbolAddress((void**)&w2t, g_w2t);
    cudaGetSymbolAddress((void**)&v2t, g_v2t);

    cudaFuncSetAttribute(gemm_qkv, cudaFuncAttributeMaxDynamicSharedMemorySize, GEMM_SMEM);
    cudaFuncSetAttribute(gemm_out, cudaFuncAttributeMaxDynamicSharedMemorySize, GEMM_SMEM);
    cudaFuncSetAttribute(attn_fa, cudaFuncAttributeMaxDynamicSharedMemorySize, FA_SMEM);

    const dim3 qkv_grid(B_ * S_ / 256, DM_ / 128, 3);
    const dim3 out_grid(B_ * S_ / 256, DM_ / 128);

    split_act2<<<B_ * S_ * 64 / 256, 256>>>(x, x2);
    split_w4<<<dim3(16, 16, 4), dim3(32, 32)>>>(Wq, Wk, Wv, Wo, w2t);

    gemm_qkv<<<qkv_grid, 256, GEMM_SMEM>>>(x2, w2t, bq, bk, bv, q2, k2, v);

    v2t_build<<<dim3(36, H_, B_), 256>>>(v, v2t);
    vmean_partial<<<dim3(64, B_), DM_>>>(v, part);
    vmean_final<<<B_, DM_>>>(part, vmean);

    attn_fa<<<dim3(S_ / 128, H_, B_), 256, FA_SMEM>>>(q2, k2, v2t, vmean, xlen, x2);

    gemm_out<<<out_grid, 256, GEMM_SMEM>>>(x2, w2t + 3 * (size_t)DM_ * K2_, bo, out);
}

// round 9
// speedup vs baseline: 1.0856x; 1.0856x over previous
#include <cuda_runtime.h>
#include <cuda_fp16.h>
#include <cstdint>

#define B_  4
#define S_  2048
#define DM_ 512
#define H_  8
#define D_  64
#define K2_ 1024            // 2x hi/lo expanded K
#define NCHUNK 16           // K2_/64

// ================= helpers =================
__device__ __forceinline__ uint32_t smem_u32(const void* p) {
    uint32_t a;
    asm("{ .reg .u64 t; cvta.to.shared.u64 t, %1; cvt.u32.u64 %0, t; }" : "=r"(a) : "l"(p));
    return a;
}
#define SWZ128(off) ((off) ^ (((off) >> 3) & 0x70))

__device__ __forceinline__ void cp_async16(uint32_t dst, const void* src) {
    asm volatile("cp.async.cg.shared.global [%0], [%1], 16;" :: "r"(dst), "l"(src));
}
__device__ __forceinline__ void cp_async16z(uint32_t dst, const void* src, uint32_t n) {
    asm volatile("cp.async.cg.shared.global [%0], [%1], 16, %2;" :: "r"(dst), "l"(src), "r"(n));
}
#define CP_COMMIT() asm volatile("cp.async.commit_group;" ::: "memory")
#define CP_WAIT(n)  asm volatile("cp.async.wait_group %0;" :: "n"(n) : "memory")

__device__ __forceinline__ void ldmx4(uint32_t& r0, uint32_t& r1, uint32_t& r2, uint32_t& r3,
                                      uint32_t addr) {
    asm volatile("ldmatrix.sync.aligned.m8n8.x4.shared.b16 {%0,%1,%2,%3}, [%4];"
                 : "=r"(r0), "=r"(r1), "=r"(r2), "=r"(r3) : "r"(addr));
}
__device__ __forceinline__ void mma16816(float* c, const uint32_t* a, uint32_t b0, uint32_t b1) {
    asm volatile(
        "mma.sync.aligned.m16n8k16.row.col.f32.f16.f16.f32 "
        "{%0,%1,%2,%3}, {%4,%5,%6,%7}, {%8,%9}, {%0,%1,%2,%3};"
        : "+f"(c[0]), "+f"(c[1]), "+f"(c[2]), "+f"(c[3])
        : "r"(a[0]), "r"(a[1]), "r"(a[2]), "r"(a[3]), "r"(b0), "r"(b1));
}
// A-side pair: (hi, lo)
__device__ __forceinline__ void pack2A(float a, float b, uint32_t* w) {
    const __half ha = __float2half_rn(a);
    const __half la = __float2half_rn(a - __half2float(ha));
    const __half hb = __float2half_rn(b);
    const __half lb = __float2half_rn(b - __half2float(hb));
    w[0] = (uint32_t)__half_as_ushort(ha) | ((uint32_t)__half_as_ushort(la) << 16);
    w[1] = (uint32_t)__half_as_ushort(hb) | ((uint32_t)__half_as_ushort(lb) << 16);
}
// B-side pair: (hi, hi)
__device__ __forceinline__ void pack2B(float a, float b, uint32_t* w) {
    const uint32_t ha = __half_as_ushort(__float2half_rn(a));
    const uint32_t hb = __half_as_ushort(__float2half_rn(b));
    w[0] = ha | (ha << 16);
    w[1] = hb | (hb << 16);
}

// ================= scratch =================
__device__ float g_v[B_ * S_ * DM_];
__device__ float g_part[B_ * DM_ * 36];       // per-chunk vmean partials
__device__ float g_vmean[B_ * DM_];
__device__ __half g_x2[B_ * S_ * K2_];        // x pairs (A), later ctx pairs (A)
__device__ __half g_q2[B_ * S_ * K2_];        // q pairs (A)
__device__ __half g_k2[B_ * S_ * K2_];        // k pairs (B)
__device__ __half g_w2t[4 * DM_ * K2_];       // weights (B), [N,K2]
__device__ __half g_v2t[2048 * 4608];         // V dims-major pairs (B), tokens padded

// ================= split kernels =================
__global__ __launch_bounds__(256) void split_act2(const float* __restrict__ X,
                                                  __half* __restrict__ X2) {
    const int idx = blockIdx.x * 256 + threadIdx.x;
    const int m = idx >> 6, g = idx & 63;
    const float4 f0 = *(const float4*)(X + (size_t)m * 512 + g * 8);
    const float4 f1 = *(const float4*)(X + (size_t)m * 512 + g * 8 + 4);
    float v[8] = {f0.x, f0.y, f0.z, f0.w, f1.x, f1.y, f1.z, f1.w};
    uint32_t w[8];
#pragma unroll
    for (int i = 0; i < 4; i++) pack2A(v[2 * i], v[2 * i + 1], w + 2 * i);
    uint4* dst = (uint4*)(X2 + (size_t)m * K2_ + g * 16);
    dst[0] = ((uint4*)w)[0]; dst[1] = ((uint4*)w)[1];
}

__global__ __launch_bounds__(1024) void split_w4(const float* __restrict__ W0,
                                                 const float* __restrict__ W1,
                                                 const float* __restrict__ W2,
                                                 const float* __restrict__ W3,
                                                 __half* __restrict__ W2T) {
    __shared__ float t[32][33];
    const int z = blockIdx.z;
    const float* W = (z == 0) ? W0 : (z == 1) ? W1 : (z == 2) ? W2 : W3;
    const int k0 = blockIdx.y * 32, n0 = blockIdx.x * 32;
    const int tx = threadIdx.x, ty = threadIdx.y;
    t[ty][tx] = W[(size_t)(k0 + ty) * 512 + n0 + tx];
    __syncthreads();
    const float v = t[tx][ty];
    const uint32_t h = __half_as_ushort(__float2half_rn(v));
    uint32_t* dst = (uint32_t*)W2T + (size_t)z * DM_ * 512 + (size_t)(n0 + ty) * 512 + (k0 + tx);
    *dst = h | (h << 16);
}

// ================= 256x128 HMMA GEMM mainloop =================
#define GEMM_SMEM (3 * 49152 + 1024)

#define GEMM_MAINLOOP256(A2, B2)                                                          \
    extern __shared__ char smraw[];                                                       \
    const uint32_t sbase = (smem_u32(smraw) + 1023) & ~1023u;                             \
    const int tid = threadIdx.x;                                                          \
    const int wid = tid >> 5, lane = tid & 31;                                            \
    const int bm = blockIdx.x * 256, bn = blockIdx.y * 128;                               \
    const int wm0 = (wid & 3) * 64, wn0 = (wid >> 2) * 64;                                \
    const __half* l_srcA = A2 + (size_t)(bm + tid) * K2_;                                 \
    const __half* l_srcB = B2 + (size_t)(bn + (tid >> 1)) * K2_ + (tid & 1) * 32;         \
    const uint32_t a_doff = SWZ128(tid * 128);                                            \
    const uint32_t b_doff = 49152 - 16384 + SWZ128((tid >> 1) * 128 + (tid & 1) * 64);    \
    float acc[4][8][4];                                                                   \
    _Pragma("unroll")                                                                     \
    for (int a = 0; a < 4; a++)                                                           \
        _Pragma("unroll")                                                                 \
        for (int b = 0; b < 8; b++)                                                       \
            _Pragma("unroll")                                                             \
            for (int c = 0; c < 4; c++) acc[a][b][c] = 0.f;                               \
    _Pragma("unroll")                                                                     \
    for (int c = 0; c < 2; c++) {                                                         \
        const uint32_t st = sbase + c * 49152;                                            \
        _Pragma("unroll")                                                                 \
        for (int seg = 0; seg < 8; seg++)                                                 \
            cp_async16(st + (a_doff ^ (seg * 16)), l_srcA + c * 64 + seg * 8);            \
        _Pragma("unroll")                                                                 \
        for (int u = 0; u < 4; u++)                                                       \
            cp_async16(st + (b_doff ^ (u * 16)), l_srcB + c * 64 + u * 8);                \
        CP_COMMIT();                                                                      \
    }                                                                                     \
    for (int c = 0; c < NCHUNK; c++) {                                                    \
        CP_WAIT(1);                                                                       \
        __syncthreads();                                                                  \
        if (c + 2 < NCHUNK) {                                                             \
            const uint32_t st = sbase + ((c + 2) % 3) * 49152;                            \
            _Pragma("unroll")                                                             \
            for (int seg = 0; seg < 8; seg++)                                             \
                cp_async16(st + (a_doff ^ (seg * 16)), l_srcA + (c + 2) * 64 + seg * 8);  \
            _Pragma("unroll")                                                             \
            for (int u = 0; u < 4; u++)                                                   \
                cp_async16(st + (b_doff ^ (u * 16)), l_srcB + (c + 2) * 64 + u * 8);      \
        }                                                                                 \
        CP_COMMIT();                                                                      \
        const uint32_t abuf = sbase + (c % 3) * 49152;                                    \
        const uint32_t bbuf = abuf + 32768;                                               \
        _Pragma("unroll")                                                                 \
        for (int ks = 0; ks < 4; ks++) {                                                  \
            const int cb = ks * 32 + ((lane >> 4) * 16);                                  \
            uint32_t bf[4][4];                                                            \
            _Pragma("unroll")                                                             \
            for (int bh = 0; bh < 4; bh++) {                                              \
                const int r = wn0 + bh * 16 + (lane & 15);                                \
                ldmx4(bf[bh][0], bf[bh][1], bf[bh][2], bf[bh][3],                         \
                      bbuf + SWZ128(r * 128 + cb));                                       \
            }                                                                             \
            _Pragma("unroll")                                                             \
            for (int mf = 0; mf < 4; mf++) {                                              \
                uint32_t a[4];                                                            \
                const int r = wm0 + mf * 16 + (lane & 15);                                \
                ldmx4(a[0], a[1], a[2], a[3], abuf + SWZ128(r * 128 + cb));               \
                _Pragma("unroll")                                                         \
                for (int nf = 0; nf < 8; nf++) {                                          \
                    const uint32_t b0 = bf[nf >> 1][(nf & 1)];                            \
                    const uint32_t b1 = bf[nf >> 1][(nf & 1) + 2];                        \
                    mma16816(acc[mf][nf], a, b0, b1);                                     \
                }                                                                         \
            }                                                                             \
        }                                                                                 \
    }                                                                                     \
    const int qr = lane >> 2, qc = (lane & 3) * 2;

// unified QKV: z=0 -> Q pairs(A), z=1 -> K pairs(B), z=2 -> V fp32
__global__ __launch_bounds__(256, 1) void gemm_qkv(const __half* __restrict__ A2,
                                                   const __half* __restrict__ W2T,
                                                   const float* __restrict__ bq,
                                                   const float* __restrict__ bk,
                                                   const float* __restrict__ bv,
                                                   __half* __restrict__ Q2,
                                                   __half* __restrict__ K2,
                                                   float* __restrict__ Vf) {
    const int z = blockIdx.z;
    const __half* B2 = W2T + (size_t)z * DM_ * K2_;
    GEMM_MAINLOOP256(A2, B2)
    const float* bias = (z == 0) ? bq : (z == 1) ? bk : bv;
    if (z == 2) {
#pragma unroll
        for (int mf = 0; mf < 4; mf++) {
            const int row = bm + wm0 + mf * 16 + qr;
#pragma unroll
            for (int nf = 0; nf < 8; nf++) {
                const int col = bn + wn0 + nf * 8 + qc;
                const float b0 = bias[col], b1 = bias[col + 1];
                float2 lo, hi;
                lo.x = acc[mf][nf][0] + b0; lo.y = acc[mf][nf][1] + b1;
                hi.x = acc[mf][nf][2] + b0; hi.y = acc[mf][nf][3] + b1;
                *(float2*)(Vf + (size_t)row * 512 + col) = lo;
                *(float2*)(Vf + (size_t)(row + 8) * 512 + col) = hi;
            }
        }
    } else {
        uint32_t* t32 = (uint32_t*)((z == 0) ? Q2 : K2);
#pragma unroll
        for (int mf = 0; mf < 4; mf++) {
            const int row = bm + wm0 + mf * 16 + qr;
#pragma unroll
            for (int nf = 0; nf < 8; nf++) {
                const int col = bn + wn0 + nf * 8 + qc;
                const float b0 = bias[col], b1 = bias[col + 1];
                uint32_t w[2];
                const uint32_t idx0 = (uint32_t)row * 512 + col;
                const uint32_t idx1 = idx0 + 8 * 512;
                if (z == 0) pack2A(acc[mf][nf][0] + b0, acc[mf][nf][1] + b1, w);
                else        pack2B(acc[mf][nf][0] + b0, acc[mf][nf][1] + b1, w);
                t32[idx0] = w[0]; t32[idx0 + 1] = w[1];
                if (z == 0) pack2A(acc[mf][nf][2] + b0, acc[mf][nf][3] + b1, w);
                else        pack2B(acc[mf][nf][2] + b0, acc[mf][nf][3] + b1, w);
                t32[idx1] = w[0]; t32[idx1 + 1] = w[1];
            }
        }
    }
}

// output projection: fp32 out
__global__ __launch_bounds__(256, 1) void gemm_out(const __half* __restrict__ A2,
                                                   const __half* __restrict__ B2,
                                                   const float* __restrict__ bias,
                                                   float* __restrict__ C) {
    GEMM_MAINLOOP256(A2, B2)
#pragma unroll
    for (int mf = 0; mf < 4; mf++) {
        const int row = bm + wm0 + mf * 16 + qr;
#pragma unroll
        for (int nf = 0; nf < 8; nf++) {
            const int col = bn + wn0 + nf * 8 + qc;
            const float b0 = bias[col], b1 = bias[col + 1];
            float2 lo, hi;
            lo.x = acc[mf][nf][0] + b0; lo.y = acc[mf][nf][1] + b1;
            hi.x = acc[mf][nf][2] + b0; hi.y = acc[mf][nf][3] + b1;
            *(float2*)(C + (size_t)row * 512 + col) = lo;
            *(float2*)(C + (size_t)(row + 8) * 512 + col) = hi;
        }
    }
}

// ================= V transpose->pair build + vmean partials =================
__global__ __launch_bounds__(256) void v2t_build(const float* __restrict__ V,
                                                 __half* __restrict__ V2T,
                                                 float* __restrict__ part) {
    __shared__ float tr[64][65];
    const int cx = blockIdx.x;
    const int h = blockIdx.y, b = blockIdx.z;
    const int tid = threadIdx.x;
    const int t0 = cx * 64 - 128;
    const bool inr = (t0 >= 0) && (t0 + 64 <= S_);

    if (inr) {
        const int i = tid >> 2, dg = tid & 3;
        const float* vrow = V + ((size_t)(b * S_ + t0 + i)) * DM_ + h * D_ + dg * 16;
#pragma unroll
        for (int u = 0; u < 4; u++) {
            float4 f = *(const float4*)(vrow + u * 4);
            tr[dg * 16 + u * 4 + 0][i] = f.x;
            tr[dg * 16 + u * 4 + 1][i] = f.y;
            tr[dg * 16 + u * 4 + 2][i] = f.z;
            tr[dg * 16 + u * 4 + 3][i] = f.w;
        }
        __syncthreads();
    }

    const int d = tid >> 2, jg = tid & 3;
    uint32_t w[16];
    float s = 0.f;
    if (inr) {
#pragma unroll
        for (int t = 0; t < 8; t++) {
            const float va = tr[d][jg * 16 + 2 * t];
            const float vb = tr[d][jg * 16 + 2 * t + 1];
            pack2B(va, vb, w + 2 * t);
            s += va + vb;
        }
    } else {
#pragma unroll
        for (int t = 0; t < 16; t++) w[t] = 0;
    }
    uint4* dst = (uint4*)((char*)V2T + ((size_t)((b * 8 + h) * 64 + d) * 4608) * 2
                          + (size_t)cx * 256 + jg * 64);
#pragma unroll
    for (int u = 0; u < 4; u++) dst[u] = ((uint4*)w)[u];

    // deterministic vmean partial: sum of this chunk's 64 tokens for dim d
    s += __shfl_xor_sync(0xffffffffu, s, 1);
    s += __shfl_xor_sync(0xffffffffu, s, 2);
    if (jg == 0)
        part[((size_t)(b * 512 + h * 64 + d)) * 36 + cx] = s;
}

__global__ __launch_bounds__(512) void vmean_final2(const float* __restrict__ part,
                                                    float* __restrict__ vm) {
    const int b = blockIdx.x, t = threadIdx.x;   // t = h*64+d
    const float* p = part + ((size_t)(b * 512 + t)) * 36;
    float s = 0.f;
#pragma unroll
    for (int cx = 0; cx < 36; cx++) s += p[cx];
    vm[b * 512 + t] = s * (1.0f / 2048.0f);
}

// ================= HMMA banded attention (fp16 pairs, R7 3-phase) =================
#define AQ2 0
#define AK2 17408
#define AV2 34816
#define ASF 52224
#define AIL 135424
#define ATT_SMEM 135680

__global__ __launch_bounds__(256, 1) void attn_mma2(const __half* __restrict__ Q2,
                                                    const __half* __restrict__ K2,
                                                    const __half* __restrict__ V2T,
                                                    const float* __restrict__ VMEAN,
                                                    const int* __restrict__ XLEN,
                                                    __half* __restrict__ C2) {
    extern __shared__ char smc[];
    const uint32_t sb = smem_u32(smc);
    float* Ss = (float*)(smc + ASF);
    float* invl = (float*)(smc + AIL);

    const int tid = threadIdx.x;
    const int wid = tid >> 5, lane = tid & 31;
    const int q0 = blockIdx.x * 64;
    const int h = blockIdx.y;
    const int b = blockIdx.z;
    const int xl = XLEN[b];

    const int wm = (wid & 3) * 16;
    const int wn = (wid >> 2) * 32;
    const int qr = lane >> 2, qc = (lane & 3) * 2;
    const int kbase0 = q0 - 128;

    const int lrow = tid >> 2;
    const int lcs = (tid & 3) * 4;

    {
        const char* qsrc = (const char*)Q2 + ((size_t)(b * S_ + q0 + lrow) * K2_ + h * 128) * 2;
#pragma unroll
        for (int u = 0; u < 4; u++)
            cp_async16(sb + AQ2 + lrow * 272 + (lcs + u) * 16, qsrc + (lcs + u) * 16);
    }
#pragma unroll
    for (int c = 0; c < 2; c++) {
        const int jabs = kbase0 + c * 64 + lrow;
        const bool valid = (jabs >= 0) && (jabs < S_);
        const char* ksrc = (const char*)K2 + ((size_t)(b * S_ + (valid ? jabs : 0)) * K2_ + h * 128) * 2;
        const uint32_t buf = sb + (c ? AV2 : AK2);
        const uint32_t n = valid ? 16u : 0u;
#pragma unroll
        for (int u = 0; u < 4; u++)
            cp_async16z(buf + lrow * 272 + (lcs + u) * 16, ksrc + (lcs + u) * 16, n);
        CP_COMMIT();
    }

#pragma unroll
    for (int c = 0; c < 5; c++) {
        if (c < 4) { CP_WAIT(1); } else { CP_WAIT(0); }
        __syncthreads();
        const uint32_t kbuf = sb + ((c & 1) ? AV2 : AK2);
        const int kb = kbase0 + c * 64;

        float acc[4][4];
#pragma unroll
        for (int nf = 0; nf < 4; nf++)
#pragma unroll
            for (int u = 0; u < 4; u++) acc[nf][u] = 0.f;

#pragma unroll
        for (int ks = 0; ks < 8; ks++) {
            const int cb = ks * 32 + (lane >> 4) * 16;
            uint32_t a[4];
            ldmx4(a[0], a[1], a[2], a[3], sb + AQ2 + (wm + (lane & 15)) * 272 + cb);
            uint32_t bf[2][4];
#pragma unroll
            for (int nh = 0; nh < 2; nh++) {
                const int r = wn + nh * 16 + (lane & 15);
                ldmx4(bf[nh][0], bf[nh][1], bf[nh][2], bf[nh][3], kbuf + r * 272 + cb);
            }
#pragma unroll
            for (int nf = 0; nf < 4; nf++) {
                const uint32_t b0 = bf[nf >> 1][(nf & 1)];
                const uint32_t b1 = bf[nf >> 1][(nf & 1) + 2];
                mma16816(acc[nf], a, b0, b1);
            }
        }

        const int i0 = wm + qr, iabs0 = q0 + i0;
        const int i1 = i0 + 8,  iabs1 = iabs0 + 8;
#pragma unroll
        for (int nf = 0; nf < 4; nf++) {
#pragma unroll
            for (int cc = 0; cc < 2; cc++) {
                const int col = wn + nf * 8 + qc + cc;
                const int jabs = kb + col;
                const bool jok = (jabs >= 0) && (jabs < xl);
                const bool v0 = jok && (jabs - iabs0 <= 128) && (iabs0 - jabs <= 128);
                const bool v1 = jok && (jabs - iabs1 <= 128) && (iabs1 - jabs <= 128);
                Ss[i0 * 325 + c * 64 + col] = v0 ? acc[nf][cc] * 0.125f : -1e30f;
                Ss[i1 * 325 + c * 64 + col] = v1 ? acc[nf][cc + 2] * 0.125f : -1e30f;
            }
        }
        __syncthreads();
        if (c + 2 < 5) {
            const int jabs = kbase0 + (c + 2) * 64 + lrow;
            const bool valid = (jabs >= 0) && (jabs < S_);
            const char* ksrc = (const char*)K2 + ((size_t)(b * S_ + (valid ? jabs : 0)) * K2_ + h * 128) * 2;
            const uint32_t buf = sb + ((c & 1) ? AV2 : AK2);
            const uint32_t n = valid ? 16u : 0u;
#pragma unroll
            for (int u = 0; u < 4; u++)
                cp_async16z(buf + lrow * 272 + (lcs + u) * 16, ksrc + (lcs + u) * 16, n);
        }
        CP_COMMIT();
    }

#pragma unroll
    for (int c = 0; c < 2; c++) {
        const char* vsrc = (const char*)V2T + ((size_t)((b * 8 + h) * 64 + lrow) * 4608) * 2
                           + (size_t)(q0 + c * 64) * 4;
        const uint32_t buf = sb + (c ? AV2 : AK2);
#pragma unroll
        for (int u = 0; u < 4; u++)
            cp_async16(buf + lrow * 272 + (lcs + u) * 16, vsrc + (lcs + u) * 16);
        CP_COMMIT();
    }

    {
        for (int rr = 0; rr < 8; rr++) {
            const int i = wid * 8 + rr;
            float* row = Ss + i * 325;
            float vals[10];
            float m = -3.0e38f;
#pragma unroll
            for (int t = 0; t < 10; t++) {
                vals[t] = row[lane + 32 * t];
                m = fmaxf(m, vals[t]);
            }
#pragma unroll
            for (int o = 16; o; o >>= 1) m = fmaxf(m, __shfl_xor_sync(0xffffffffu, m, o));
            float l = 0.f;
#pragma unroll
            for (int t = 0; t < 10; t++) {
                const float p = __expf(vals[t] - m);
                row[lane + 32 * t] = p;
                l += p;
            }
#pragma unroll
            for (int o = 16; o; o >>= 1) l += __shfl_xor_sync(0xffffffffu, l, o);
            if (lane == 0) invl[i] = 1.0f / l;
        }
    }
    __syncthreads();

    float oacc[4][4];
#pragma unroll
    for (int nf = 0; nf < 4; nf++)
#pragma unroll
        for (int u = 0; u < 4; u++) oacc[nf][u] = 0.f;

#pragma unroll
    for (int c = 0; c < 5; c++) {
        {
            const int row = tid & 63, jg = tid >> 6;
            const float* srow = Ss + row * 325 + c * 64 + jg * 16;
            uint32_t w[16];
#pragma unroll
            for (int t = 0; t < 8; t++) pack2A(srow[2 * t], srow[2 * t + 1], w + 2 * t);
            uint4* dst = (uint4*)(smc + AQ2 + row * 272 + jg * 64);
#pragma unroll
            for (int u = 0; u < 4; u++) dst[u] = ((uint4*)w)[u];
        }
        if (c < 4) { CP_WAIT(1); } else { CP_WAIT(0); }
        __syncthreads();

        const uint32_t vbuf = sb + ((c & 1) ? AV2 : AK2);
#pragma unroll
        for (int ks = 0; ks < 8; ks++) {
            const int cb = ks * 32 + (lane >> 4) * 16;
            uint32_t a[4];
            ldmx4(a[0], a[1], a[2], a[3], sb + AQ2 + (wm + (lane & 15)) * 272 + cb);
            uint32_t bf[2][4];
#pragma unroll
            for (int nh = 0; nh < 2; nh++) {
                const int r = wn + nh * 16 + (lane & 15);
                ldmx4(bf[nh][0], bf[nh][1], bf[nh][2], bf[nh][3], vbuf + r * 272 + cb);
            }
#pragma unroll
            for (int nf = 0; nf < 4; nf++) {
                const uint32_t b0 = bf[nf >> 1][(nf & 1)];
                const uint32_t b1 = bf[nf >> 1][(nf & 1) + 2];
                mma16816(oacc[nf], a, b0, b1);
            }
        }
        __syncthreads();
        if (c + 2 < 5) {
            const char* vsrc = (const char*)V2T + ((size_t)((b * 8 + h) * 64 + lrow) * 4608) * 2
                               + (size_t)(q0 + (c + 2) * 64) * 4;
            const uint32_t buf = sb + ((c & 1) ? AV2 : AK2);
#pragma unroll
            for (int u = 0; u < 4; u++)
                cp_async16(buf + lrow * 272 + (lcs + u) * 16, vsrc + (lcs + u) * 16);
        }
        CP_COMMIT();
    }

    {
        const int i0 = wm + qr;
#pragma unroll
        for (int half = 0; half < 2; half++) {
            const int i = i0 + half * 8;
            const int iabs = q0 + i;
            int lo2 = iabs - 128;
            if (lo2 < 0) lo2 = 0;
            const bool deg = (lo2 >= xl);
            const float il = invl[i];
            uint32_t* crow = (uint32_t*)C2 + (size_t)(b * S_ + iabs) * 512 + h * 64;
            const float* vm = VMEAN + b * 512 + h * 64;
#pragma unroll
            for (int nf = 0; nf < 4; nf++) {
                const int col = wn + nf * 8 + qc;
                const float a = deg ? vm[col]      : oacc[nf][half * 2] * il;
                const float bb = deg ? vm[col + 1] : oacc[nf][half * 2 + 1] * il;
                uint32_t w[2];
                pack2A(a, bb, w);
                crow[col] = w[0]; crow[col + 1] = w[1];
            }
        }
    }
}

// ================= launch =================
extern "C" void kernel_launch(void* const* d_in, const int* in_sizes, int n_in,
                              void* d_out, int out_size) {
    const float* x  = (const float*)d_in[0];
    const float* Wq = (const float*)d_in[1];
    const float* bq = (const float*)d_in[2];
    const float* Wk = (const float*)d_in[3];
    const float* bk = (const float*)d_in[4];
    const float* Wv = (const float*)d_in[5];
    const float* bv = (const float*)d_in[6];
    const float* Wo = (const float*)d_in[7];
    const float* bo = (const float*)d_in[8];
    const int* xlen = (const int*)d_in[9];
    float* out = (float*)d_out;

    float *v, *part, *vmean;
    __half *x2, *q2, *k2, *w2t, *v2t;
    cudaGetSymbolAddress((void**)&v, g_v);
    cudaGetSymbolAddress((void**)&part, g_part);
    cudaGetSymbolAddress((void**)&vmean, g_vmean);
    cudaGetSymbolAddress((void**)&x2, g_x2);
    cudaGetSymbolAddress((void**)&q2, g_q2);
    cudaGetSymbolAddress((void**)&k2, g_k2);
    cudaGetSymbolAddress((void**)&w2t, g_w2t);
    cudaGetSymbolAddress((void**)&v2t, g_v2t);

    cudaFuncSetAttribute(gemm_qkv, cudaFuncAttributeMaxDynamicSharedMemorySize, GEMM_SMEM);
    cudaFuncSetAttribute(gemm_out, cudaFuncAttributeMaxDynamicSharedMemorySize, GEMM_SMEM);
    cudaFuncSetAttribute(attn_mma2, cudaFuncAttributeMaxDynamicSharedMemorySize, ATT_SMEM);

    const dim3 qkv_grid(B_ * S_ / 256, DM_ / 128, 3);
    const dim3 out_grid(B_ * S_ / 256, DM_ / 128);

    split_act2<<<B_ * S_ * 64 / 256, 256>>>(x, x2);
    split_w4<<<dim3(16, 16, 4), dim3(32, 32)>>>(Wq, Wk, Wv, Wo, w2t);

    gemm_qkv<<<qkv_grid, 256, GEMM_SMEM>>>(x2, w2t, bq, bk, bv, q2, k2, v);

    v2t_build<<<dim3(36, H_, B_), 256>>>(v, v2t, part);
    vmean_final2<<<B_, 512>>>(part, vmean);

    attn_mma2<<<dim3(S_ / 64, H_, B_), 256, ATT_SMEM>>>(q2, k2, v2t, vmean, xlen, x2);

    gemm_out<<<out_grid, 256, GEMM_SMEM>>>(x2, w2t + 3 * (size_t)DM_ * K2_, bo, out);
}

// round 10
// speedup vs baseline: 1.3233x; 1.2190x over previous
#include <cuda_runtime.h>
#include <cuda_fp16.h>
#include <cstdint>

#define B_  4
#define S_  2048
#define DM_ 512
#define H_  8
#define D_  64
#define K2_ 1024            // 2x hi/lo expanded K (GEMMs only)
#define NCHUNK 16           // K2_/64

// ================= helpers =================
__device__ __forceinline__ uint32_t smem_u32(const void* p) {
    uint32_t a;
    asm("{ .reg .u64 t; cvta.to.shared.u64 t, %1; cvt.u32.u64 %0, t; }" : "=r"(a) : "l"(p));
    return a;
}
#define SWZ128(off) ((off) ^ (((off) >> 3) & 0x70))

__device__ __forceinline__ void cp_async16(uint32_t dst, const void* src) {
    asm volatile("cp.async.cg.shared.global [%0], [%1], 16;" :: "r"(dst), "l"(src));
}
__device__ __forceinline__ void cp_async16z(uint32_t dst, const void* src, uint32_t n) {
    asm volatile("cp.async.cg.shared.global [%0], [%1], 16, %2;" :: "r"(dst), "l"(src), "r"(n));
}
#define CP_COMMIT() asm volatile("cp.async.commit_group;" ::: "memory")
#define CP_WAIT(n)  asm volatile("cp.async.wait_group %0;" :: "n"(n) : "memory")

__device__ __forceinline__ void ldmx4(uint32_t& r0, uint32_t& r1, uint32_t& r2, uint32_t& r3,
                                      uint32_t addr) {
    asm volatile("ldmatrix.sync.aligned.m8n8.x4.shared.b16 {%0,%1,%2,%3}, [%4];"
                 : "=r"(r0), "=r"(r1), "=r"(r2), "=r"(r3) : "r"(addr));
}
__device__ __forceinline__ void mma16816(float* c, const uint32_t* a, uint32_t b0, uint32_t b1) {
    asm volatile(
        "mma.sync.aligned.m16n8k16.row.col.f32.f16.f16.f32 "
        "{%0,%1,%2,%3}, {%4,%5,%6,%7}, {%8,%9}, {%0,%1,%2,%3};"
        : "+f"(c[0]), "+f"(c[1]), "+f"(c[2]), "+f"(c[3])
        : "r"(a[0]), "r"(a[1]), "r"(a[2]), "r"(a[3]), "r"(b0), "r"(b1));
}
// A-side pair: (hi, lo)
__device__ __forceinline__ void pack2A(float a, float b, uint32_t* w) {
    const __half ha = __float2half_rn(a);
    const __half la = __float2half_rn(a - __half2float(ha));
    const __half hb = __float2half_rn(b);
    const __half lb = __float2half_rn(b - __half2float(hb));
    w[0] = (uint32_t)__half_as_ushort(ha) | ((uint32_t)__half_as_ushort(la) << 16);
    w[1] = (uint32_t)__half_as_ushort(hb) | ((uint32_t)__half_as_ushort(lb) << 16);
}
// single fp16 pair of values packed into one u32
__device__ __forceinline__ uint32_t pack1(float a, float b) {
    return (uint32_t)__half_as_ushort(__float2half_rn(a)) |
           ((uint32_t)__half_as_ushort(__float2half_rn(b)) << 16);
}

// ================= scratch =================
__device__ float g_v[B_ * S_ * DM_];
__device__ float g_part[B_ * DM_ * 36];       // per-chunk vmean partials
__device__ float g_vmean[B_ * DM_];
__device__ __half g_x2[B_ * S_ * K2_];        // x pairs (A) for GEMMs; later ctx pairs (A)
__device__ __half g_q2h[B_ * S_ * DM_];       // q plain fp16
__device__ __half g_k2h[B_ * S_ * DM_];       // k plain fp16
__device__ __half g_w2t[4 * DM_ * K2_];       // weights (B pattern), [N,K2]
__device__ __half g_v2t[2048 * 2304];         // V dims-major plain fp16, tokens padded [-128,2176)

// ================= split kernels =================
__global__ __launch_bounds__(256) void split_act2(const float* __restrict__ X,
                                                  __half* __restrict__ X2) {
    const int idx = blockIdx.x * 256 + threadIdx.x;
    const int m = idx >> 6, g = idx & 63;
    const float4 f0 = *(const float4*)(X + (size_t)m * 512 + g * 8);
    const float4 f1 = *(const float4*)(X + (size_t)m * 512 + g * 8 + 4);
    float v[8] = {f0.x, f0.y, f0.z, f0.w, f1.x, f1.y, f1.z, f1.w};
    uint32_t w[8];
#pragma unroll
    for (int i = 0; i < 4; i++) pack2A(v[2 * i], v[2 * i + 1], w + 2 * i);
    uint4* dst = (uint4*)(X2 + (size_t)m * K2_ + g * 16);
    dst[0] = ((uint4*)w)[0]; dst[1] = ((uint4*)w)[1];
}

__global__ __launch_bounds__(1024) void split_w4(const float* __restrict__ W0,
                                                 const float* __restrict__ W1,
                                                 const float* __restrict__ W2,
                                                 const float* __restrict__ W3,
                                                 __half* __restrict__ W2T) {
    __shared__ float t[32][33];
    const int z = blockIdx.z;
    const float* W = (z == 0) ? W0 : (z == 1) ? W1 : (z == 2) ? W2 : W3;
    const int k0 = blockIdx.y * 32, n0 = blockIdx.x * 32;
    const int tx = threadIdx.x, ty = threadIdx.y;
    t[ty][tx] = W[(size_t)(k0 + ty) * 512 + n0 + tx];
    __syncthreads();
    const float v = t[tx][ty];
    const uint32_t h = __half_as_ushort(__float2half_rn(v));
    uint32_t* dst = (uint32_t*)W2T + (size_t)z * DM_ * 512 + (size_t)(n0 + ty) * 512 + (k0 + tx);
    *dst = h | (h << 16);
}

// ================= 256x128 HMMA GEMM mainloop =================
#define GEMM_SMEM (3 * 49152 + 1024)

#define GEMM_MAINLOOP256(A2, B2)                                                          \
    extern __shared__ char smraw[];                                                       \
    const uint32_t sbase = (smem_u32(smraw) + 1023) & ~1023u;                             \
    const int tid = threadIdx.x;                                                          \
    const int wid = tid >> 5, lane = tid & 31;                                            \
    const int bm = blockIdx.x * 256, bn = blockIdx.y * 128;                               \
    const int wm0 = (wid & 3) * 64, wn0 = (wid >> 2) * 64;                                \
    const __half* l_srcA = A2 + (size_t)(bm + tid) * K2_;                                 \
    const __half* l_srcB = B2 + (size_t)(bn + (tid >> 1)) * K2_ + (tid & 1) * 32;         \
    const uint32_t a_doff = SWZ128(tid * 128);                                            \
    const uint32_t b_doff = 49152 - 16384 + SWZ128((tid >> 1) * 128 + (tid & 1) * 64);    \
    float acc[4][8][4];                                                                   \
    _Pragma("unroll")                                                                     \
    for (int a = 0; a < 4; a++)                                                           \
        _Pragma("unroll")                                                                 \
        for (int b = 0; b < 8; b++)                                                       \
            _Pragma("unroll")                                                             \
            for (int c = 0; c < 4; c++) acc[a][b][c] = 0.f;                               \
    _Pragma("unroll")                                                                     \
    for (int c = 0; c < 2; c++) {                                                         \
        const uint32_t st = sbase + c * 49152;                                            \
        _Pragma("unroll")                                                                 \
        for (int seg = 0; seg < 8; seg++)                                                 \
            cp_async16(st + (a_doff ^ (seg * 16)), l_srcA + c * 64 + seg * 8);            \
        _Pragma("unroll")                                                                 \
        for (int u = 0; u < 4; u++)                                                       \
            cp_async16(st + (b_doff ^ (u * 16)), l_srcB + c * 64 + u * 8);                \
        CP_COMMIT();                                                                      \
    }                                                                                     \
    for (int c = 0; c < NCHUNK; c++) {                                                    \
        CP_WAIT(1);                                                                       \
        __syncthreads();                                                                  \
        if (c + 2 < NCHUNK) {                                                             \
            const uint32_t st = sbase + ((c + 2) % 3) * 49152;                            \
            _Pragma("unroll")                                                             \
            for (int seg = 0; seg < 8; seg++)                                             \
                cp_async16(st + (a_doff ^ (seg * 16)), l_srcA + (c + 2) * 64 + seg * 8);  \
            _Pragma("unroll")                                                             \
            for (int u = 0; u < 4; u++)                                                   \
                cp_async16(st + (b_doff ^ (u * 16)), l_srcB + (c + 2) * 64 + u * 8);      \
        }                                                                                 \
        CP_COMMIT();                                                                      \
        const uint32_t abuf = sbase + (c % 3) * 49152;                                    \
        const uint32_t bbuf = abuf + 32768;                                               \
        _Pragma("unroll")                                                                 \
        for (int ks = 0; ks < 4; ks++) {                                                  \
            const int cb = ks * 32 + ((lane >> 4) * 16);                                  \
            uint32_t bf[4][4];                                                            \
            _Pragma("unroll")                                                             \
            for (int bh = 0; bh < 4; bh++) {                                              \
                const int r = wn0 + bh * 16 + (lane & 15);                                \
                ldmx4(bf[bh][0], bf[bh][1], bf[bh][2], bf[bh][3],                         \
                      bbuf + SWZ128(r * 128 + cb));                                       \
            }                                                                             \
            _Pragma("unroll")                                                             \
            for (int mf = 0; mf < 4; mf++) {                                              \
                uint32_t a[4];                                                            \
                const int r = wm0 + mf * 16 + (lane & 15);                                \
                ldmx4(a[0], a[1], a[2], a[3], abuf + SWZ128(r * 128 + cb));               \
                _Pragma("unroll")                                                         \
                for (int nf = 0; nf < 8; nf++) {                                          \
                    const uint32_t b0 = bf[nf >> 1][(nf & 1)];                            \
                    const uint32_t b1 = bf[nf >> 1][(nf & 1) + 2];                        \
                    mma16816(acc[mf][nf], a, b0, b1);                                     \
                }                                                                         \
            }                                                                             \
        }                                                                                 \
    }                                                                                     \
    const int qr = lane >> 2, qc = (lane & 3) * 2;

// unified QKV: z=0 -> Q fp16, z=1 -> K fp16, z=2 -> V fp32
__global__ __launch_bounds__(256, 1) void gemm_qkv(const __half* __restrict__ A2,
                                                   const __half* __restrict__ W2T,
                                                   const float* __restrict__ bq,
                                                   const float* __restrict__ bk,
                                                   const float* __restrict__ bv,
                                                   __half* __restrict__ Q2h,
                                                   __half* __restrict__ K2h,
                                                   float* __restrict__ Vf) {
    const int z = blockIdx.z;
    const __half* B2 = W2T + (size_t)z * DM_ * K2_;
    GEMM_MAINLOOP256(A2, B2)
    const float* bias = (z == 0) ? bq : (z == 1) ? bk : bv;
    if (z == 2) {
#pragma unroll
        for (int mf = 0; mf < 4; mf++) {
            const int row = bm + wm0 + mf * 16 + qr;
#pragma unroll
            for (int nf = 0; nf < 8; nf++) {
                const int col = bn + wn0 + nf * 8 + qc;
                const float b0 = bias[col], b1 = bias[col + 1];
                float2 lo, hi;
                lo.x = acc[mf][nf][0] + b0; lo.y = acc[mf][nf][1] + b1;
                hi.x = acc[mf][nf][2] + b0; hi.y = acc[mf][nf][3] + b1;
                *(float2*)(Vf + (size_t)row * 512 + col) = lo;
                *(float2*)(Vf + (size_t)(row + 8) * 512 + col) = hi;
            }
        }
    } else {
        uint32_t* t32 = (uint32_t*)((z == 0) ? Q2h : K2h);
#pragma unroll
        for (int mf = 0; mf < 4; mf++) {
            const int row = bm + wm0 + mf * 16 + qr;
#pragma unroll
            for (int nf = 0; nf < 8; nf++) {
                const int col = bn + wn0 + nf * 8 + qc;
                const float b0 = bias[col], b1 = bias[col + 1];
                const uint32_t idx0 = (uint32_t)row * 256 + (col >> 1);
                const uint32_t idx1 = idx0 + 8 * 256;
                t32[idx0] = pack1(acc[mf][nf][0] + b0, acc[mf][nf][1] + b1);
                t32[idx1] = pack1(acc[mf][nf][2] + b0, acc[mf][nf][3] + b1);
            }
        }
    }
}

// output projection: fp32 out
__global__ __launch_bounds__(256, 1) void gemm_out(const __half* __restrict__ A2,
                                                   const __half* __restrict__ B2,
                                                   const float* __restrict__ bias,
                                                   float* __restrict__ C) {
    GEMM_MAINLOOP256(A2, B2)
#pragma unroll
    for (int mf = 0; mf < 4; mf++) {
        const int row = bm + wm0 + mf * 16 + qr;
#pragma unroll
        for (int nf = 0; nf < 8; nf++) {
            const int col = bn + wn0 + nf * 8 + qc;
            const float b0 = bias[col], b1 = bias[col + 1];
            float2 lo, hi;
            lo.x = acc[mf][nf][0] + b0; lo.y = acc[mf][nf][1] + b1;
            hi.x = acc[mf][nf][2] + b0; hi.y = acc[mf][nf][3] + b1;
            *(float2*)(C + (size_t)row * 512 + col) = lo;
            *(float2*)(C + (size_t)(row + 8) * 512 + col) = hi;
        }
    }
}

// ================= V transpose->fp16 build + vmean partials =================
__global__ __launch_bounds__(256) void v2t_build(const float* __restrict__ V,
                                                 __half* __restrict__ V2T,
                                                 float* __restrict__ part) {
    __shared__ float tr[64][65];
    const int cx = blockIdx.x;
    const int h = blockIdx.y, b = blockIdx.z;
    const int tid = threadIdx.x;
    const int t0 = cx * 64 - 128;
    const bool inr = (t0 >= 0) && (t0 + 64 <= S_);

    if (inr) {
        const int i = tid >> 2, dg = tid & 3;
        const float* vrow = V + ((size_t)(b * S_ + t0 + i)) * DM_ + h * D_ + dg * 16;
#pragma unroll
        for (int u = 0; u < 4; u++) {
            float4 f = *(const float4*)(vrow + u * 4);
            tr[dg * 16 + u * 4 + 0][i] = f.x;
            tr[dg * 16 + u * 4 + 1][i] = f.y;
            tr[dg * 16 + u * 4 + 2][i] = f.z;
            tr[dg * 16 + u * 4 + 3][i] = f.w;
        }
        __syncthreads();
    }

    const int d = tid >> 2, jg = tid & 3;   // jg: 16 tokens each
    uint32_t w[8];
    float s = 0.f;
    if (inr) {
#pragma unroll
        for (int t = 0; t < 8; t++) {
            const float va = tr[d][jg * 16 + 2 * t];
            const float vb = tr[d][jg * 16 + 2 * t + 1];
            w[t] = pack1(va, vb);
            s += va + vb;
        }
    } else {
#pragma unroll
        for (int t = 0; t < 8; t++) w[t] = 0;
    }
    uint4* dst = (uint4*)((char*)V2T + ((size_t)((b * 8 + h) * 64 + d) * 2304) * 2
                          + (size_t)cx * 128 + jg * 32);
    dst[0] = ((uint4*)w)[0];
    dst[1] = ((uint4*)w)[1];

    s += __shfl_xor_sync(0xffffffffu, s, 1);
    s += __shfl_xor_sync(0xffffffffu, s, 2);
    if (jg == 0)
        part[((size_t)(b * 512 + h * 64 + d)) * 36 + cx] = s;
}

__global__ __launch_bounds__(512) void vmean_final2(const float* __restrict__ part,
                                                    float* __restrict__ vm) {
    const int b = blockIdx.x, t = threadIdx.x;
    const float* p = part + ((size_t)(b * 512 + t)) * 36;
    float s = 0.f;
#pragma unroll
    for (int cx = 0; cx < 36; cx++) s += p[cx];
    vm[b * 512 + t] = s * (1.0f / 2048.0f);
}

// ================= HMMA banded attention (plain fp16, 3-phase) =================
// rows: 64 fp16 = 128B data, stride 144B (ldmatrix conflict-free).
#define AQ2 0
#define AK2 9216
#define AV2 18432
#define ASF 27648
#define AIL 110848
#define ATT_SMEM 111104

__global__ __launch_bounds__(256) void attn_mma2(const __half* __restrict__ Q2h,
                                                 const __half* __restrict__ K2h,
                                                 const __half* __restrict__ V2T,
                                                 const float* __restrict__ VMEAN,
                                                 const int* __restrict__ XLEN,
                                                 __half* __restrict__ C2) {
    extern __shared__ char smc[];
    const uint32_t sb = smem_u32(smc);
    float* Ss = (float*)(smc + ASF);
    float* invl = (float*)(smc + AIL);

    const int tid = threadIdx.x;
    const int wid = tid >> 5, lane = tid & 31;
    const int q0 = blockIdx.x * 64;
    const int h = blockIdx.y;
    const int b = blockIdx.z;
    const int xl = XLEN[b];

    const int wm = (wid & 3) * 16;
    const int wn = (wid >> 2) * 32;
    const int qr = lane >> 2, qc = (lane & 3) * 2;
    const int kbase0 = q0 - 128;

    const int lrow = tid >> 2;            // 0..63
    const int lcs = (tid & 3) * 2;        // 2 segs of 16B each

    // ---- issue Q + K0 (group 0), K1 (group 1) ----
    {
        const char* qsrc = (const char*)Q2h + ((size_t)(b * S_ + q0 + lrow) * DM_ + h * 64) * 2;
#pragma unroll
        for (int u = 0; u < 2; u++)
            cp_async16(sb + AQ2 + lrow * 144 + (lcs + u) * 16, qsrc + (lcs + u) * 16);
    }
#pragma unroll
    for (int c = 0; c < 2; c++) {
        const int jabs = kbase0 + c * 64 + lrow;
        const bool valid = (jabs >= 0) && (jabs < S_);
        const char* ksrc = (const char*)K2h + ((size_t)(b * S_ + (valid ? jabs : 0)) * DM_ + h * 64) * 2;
        const uint32_t buf = sb + (c ? AV2 : AK2);
        const uint32_t n = valid ? 16u : 0u;
#pragma unroll
        for (int u = 0; u < 2; u++)
            cp_async16z(buf + lrow * 144 + (lcs + u) * 16, ksrc + (lcs + u) * 16, n);
        CP_COMMIT();
    }

    // ---- phase 1: energies ----
#pragma unroll
    for (int c = 0; c < 5; c++) {
        if (c < 4) { CP_WAIT(1); } else { CP_WAIT(0); }
        __syncthreads();
        const uint32_t kbuf = sb + ((c & 1) ? AV2 : AK2);
        const int kb = kbase0 + c * 64;

        float acc[4][4];
#pragma unroll
        for (int nf = 0; nf < 4; nf++)
#pragma unroll
            for (int u = 0; u < 4; u++) acc[nf][u] = 0.f;

#pragma unroll
        for (int ks = 0; ks < 4; ks++) {
            const int cb = ks * 32 + (lane >> 4) * 16;
            uint32_t a[4];
            ldmx4(a[0], a[1], a[2], a[3], sb + AQ2 + (wm + (lane & 15)) * 144 + cb);
            uint32_t bf[2][4];
#pragma unroll
            for (int nh = 0; nh < 2; nh++) {
                const int r = wn + nh * 16 + (lane & 15);
                ldmx4(bf[nh][0], bf[nh][1], bf[nh][2], bf[nh][3], kbuf + r * 144 + cb);
            }
#pragma unroll
            for (int nf = 0; nf < 4; nf++) {
                const uint32_t b0 = bf[nf >> 1][(nf & 1)];
                const uint32_t b1 = bf[nf >> 1][(nf & 1) + 2];
                mma16816(acc[nf], a, b0, b1);
            }
        }

        const int i0 = wm + qr, iabs0 = q0 + i0;
        const int i1 = i0 + 8,  iabs1 = iabs0 + 8;
#pragma unroll
        for (int nf = 0; nf < 4; nf++) {
#pragma unroll
            for (int cc = 0; cc < 2; cc++) {
                const int col = wn + nf * 8 + qc + cc;
                const int jabs = kb + col;
                const bool jok = (jabs >= 0) && (jabs < xl);
                const bool v0 = jok && (jabs - iabs0 <= 128) && (iabs0 - jabs <= 128);
                const bool v1 = jok && (jabs - iabs1 <= 128) && (iabs1 - jabs <= 128);
                Ss[i0 * 325 + c * 64 + col] = v0 ? acc[nf][cc] * 0.125f : -1e30f;
                Ss[i1 * 325 + c * 64 + col] = v1 ? acc[nf][cc + 2] * 0.125f : -1e30f;
            }
        }
        __syncthreads();
        if (c + 2 < 5) {
            const int jabs = kbase0 + (c + 2) * 64 + lrow;
            const bool valid = (jabs >= 0) && (jabs < S_);
            const char* ksrc = (const char*)K2h + ((size_t)(b * S_ + (valid ? jabs : 0)) * DM_ + h * 64) * 2;
            const uint32_t buf = sb + ((c & 1) ? AV2 : AK2);
            const uint32_t n = valid ? 16u : 0u;
#pragma unroll
            for (int u = 0; u < 2; u++)
                cp_async16z(buf + lrow * 144 + (lcs + u) * 16, ksrc + (lcs + u) * 16, n);
        }
        CP_COMMIT();
    }

    // ---- preload V chunks 0,1 (overlap with softmax) ----
#pragma unroll
    for (int c = 0; c < 2; c++) {
        const char* vsrc = (const char*)V2T + ((size_t)((b * 8 + h) * 64 + lrow) * 2304) * 2
                           + (size_t)(q0 + c * 64) * 2;
        const uint32_t buf = sb + (c ? AV2 : AK2);
#pragma unroll
        for (int u = 0; u < 2; u++)
            cp_async16(buf + lrow * 144 + (lcs + u) * 16, vsrc + (lcs + u) * 16);
        CP_COMMIT();
    }

    // ---- phase 2: softmax ----
    {
        for (int rr = 0; rr < 8; rr++) {
            const int i = wid * 8 + rr;
            float* row = Ss + i * 325;
            float vals[10];
            float m = -3.0e38f;
#pragma unroll
            for (int t = 0; t < 10; t++) {
                vals[t] = row[lane + 32 * t];
                m = fmaxf(m, vals[t]);
            }
#pragma unroll
            for (int o = 16; o; o >>= 1) m = fmaxf(m, __shfl_xor_sync(0xffffffffu, m, o));
            float l = 0.f;
#pragma unroll
            for (int t = 0; t < 10; t++) {
                const float p = __expf(vals[t] - m);
                row[lane + 32 * t] = p;
                l += p;
            }
#pragma unroll
            for (int o = 16; o; o >>= 1) l += __shfl_xor_sync(0xffffffffu, l, o);
            if (lane == 0) invl[i] = 1.0f / l;
        }
    }
    __syncthreads();

    // ---- phase 3: AV ----
    float oacc[4][4];
#pragma unroll
    for (int nf = 0; nf < 4; nf++)
#pragma unroll
        for (int u = 0; u < 4; u++) oacc[nf][u] = 0.f;

#pragma unroll
    for (int c = 0; c < 5; c++) {
        {
            const int row = tid & 63, jg = tid >> 6;
            const float* srow = Ss + row * 325 + c * 64 + jg * 16;
            uint32_t w[8];
#pragma unroll
            for (int t = 0; t < 8; t++) w[t] = pack1(srow[2 * t], srow[2 * t + 1]);
            uint4* dst = (uint4*)(smc + AQ2 + row * 144 + jg * 32);
            dst[0] = ((uint4*)w)[0];
            dst[1] = ((uint4*)w)[1];
        }
        if (c < 4) { CP_WAIT(1); } else { CP_WAIT(0); }
        __syncthreads();

        const uint32_t vbuf = sb + ((c & 1) ? AV2 : AK2);
#pragma unroll
        for (int ks = 0; ks < 4; ks++) {
            const int cb = ks * 32 + (lane >> 4) * 16;
            uint32_t a[4];
            ldmx4(a[0], a[1], a[2], a[3], sb + AQ2 + (wm + (lane & 15)) * 144 + cb);
            uint32_t bf[2][4];
#pragma unroll
            for (int nh = 0; nh < 2; nh++) {
                const int r = wn + nh * 16 + (lane & 15);
                ldmx4(bf[nh][0], bf[nh][1], bf[nh][2], bf[nh][3], vbuf + r * 144 + cb);
            }
#pragma unroll
            for (int nf = 0; nf < 4; nf++) {
                const uint32_t b0 = bf[nf >> 1][(nf & 1)];
                const uint32_t b1 = bf[nf >> 1][(nf & 1) + 2];
                mma16816(oacc[nf], a, b0, b1);
            }
        }
        __syncthreads();
        if (c + 2 < 5) {
            const char* vsrc = (const char*)V2T + ((size_t)((b * 8 + h) * 64 + lrow) * 2304) * 2
                               + (size_t)(q0 + (c + 2) * 64) * 2;
            const uint32_t buf = sb + ((c & 1) ? AV2 : AK2);
#pragma unroll
            for (int u = 0; u < 2; u++)
                cp_async16(buf + lrow * 144 + (lcs + u) * 16, vsrc + (lcs + u) * 16);
        }
        CP_COMMIT();
    }

    // ---- final write: normalize, pack pairs (A pattern) into C2, deg override ----
    {
        const int i0 = wm + qr;
#pragma unroll
        for (int half = 0; half < 2; half++) {
            const int i = i0 + half * 8;
            const int iabs = q0 + i;
            int lo2 = iabs - 128;
            if (lo2 < 0) lo2 = 0;
            const bool deg = (lo2 >= xl);
            const float il = invl[i];
            uint32_t* crow = (uint32_t*)C2 + (size_t)(b * S_ + iabs) * 512 + h * 64;
            const float* vm = VMEAN + b * 512 + h * 64;
#pragma unroll
            for (int nf = 0; nf < 4; nf++) {
                const int col = wn + nf * 8 + qc;
                const float a = deg ? vm[col]      : oacc[nf][half * 2] * il;
                const float bb = deg ? vm[col + 1] : oacc[nf][half * 2 + 1] * il;
                uint32_t w[2];
                pack2A(a, bb, w);
                crow[col] = w[0]; crow[col + 1] = w[1];
            }
        }
    }
}

// ================= launch =================
extern "C" void kernel_launch(void* const* d_in, const int* in_sizes, int n_in,
                              void* d_out, int out_size) {
    const float* x  = (const float*)d_in[0];
    const float* Wq = (const float*)d_in[1];
    const float* bq = (const float*)d_in[2];
    const float* Wk = (const float*)d_in[3];
    const float* bk = (const float*)d_in[4];
    const float* Wv = (const float*)d_in[5];
    const float* bv = (const float*)d_in[6];
    const float* Wo = (const float*)d_in[7];
    const float* bo = (const float*)d_in[8];
    const int* xlen = (const int*)d_in[9];
    float* out = (float*)d_out;

    float *v, *part, *vmean;
    __half *x2, *q2h, *k2h, *w2t, *v2t;
    cudaGetSymbolAddress((void**)&v, g_v);
    cudaGetSymbolAddress((void**)&part, g_part);
    cudaGetSymbolAddress((void**)&vmean, g_vmean);
    cudaGetSymbolAddress((void**)&x2, g_x2);
    cudaGetSymbolAddress((void**)&q2h, g_q2h);
    cudaGetSymbolAddress((void**)&k2h, g_k2h);
    cudaGetSymbolAddress((void**)&w2t, g_w2t);
    cudaGetSymbolAddress((void**)&v2t, g_v2t);

    cudaFuncSetAttribute(gemm_qkv, cudaFuncAttributeMaxDynamicSharedMemorySize, GEMM_SMEM);
    cudaFuncSetAttribute(gemm_out, cudaFuncAttributeMaxDynamicSharedMemorySize, GEMM_SMEM);
    cudaFuncSetAttribute(attn_mma2, cudaFuncAttributeMaxDynamicSharedMemorySize, ATT_SMEM);

    const dim3 qkv_grid(B_ * S_ / 256, DM_ / 128, 3);
    const dim3 out_grid(B_ * S_ / 256, DM_ / 128);

    split_act2<<<B_ * S_ * 64 / 256, 256>>>(x, x2);
    split_w4<<<dim3(16, 16, 4), dim3(32, 32)>>>(Wq, Wk, Wv, Wo, w2t);

    gemm_qkv<<<qkv_grid, 256, GEMM_SMEM>>>(x2, w2t, bq, bk, bv, q2h, k2h, v);

    v2t_build<<<dim3(36, H_, B_), 256>>>(v, v2t, part);
    vmean_final2<<<B_, 512>>>(part, vmean);

    attn_mma2<<<dim3(S_ / 64, H_, B_), 256, ATT_SMEM>>>(q2h, k2h, v2t, vmean, xlen, x2);

    gemm_out<<<out_grid, 256, GEMM_SMEM>>>(x2, w2t + 3 * (size_t)DM_ * K2_, bo, out);
}

// round 11
// speedup vs baseline: 1.5713x; 1.1874x over previous
#include <cuda_runtime.h>
#include <cuda_fp16.h>
#include <cstdint>

#define B_  4
#define S_  2048
#define DM_ 512
#define H_  8
#define D_  64
#define K2_ 1024            // 2x hi/lo expanded K (V / out GEMMs)

// ================= helpers =================
__device__ __forceinline__ uint32_t smem_u32(const void* p) {
    uint32_t a;
    asm("{ .reg .u64 t; cvta.to.shared.u64 t, %1; cvt.u32.u64 %0, t; }" : "=r"(a) : "l"(p));
    return a;
}
#define SWZ128(off) ((off) ^ (((off) >> 3) & 0x70))

__device__ __forceinline__ void cp_async16(uint32_t dst, const void* src) {
    asm volatile("cp.async.cg.shared.global [%0], [%1], 16;" :: "r"(dst), "l"(src));
}
__device__ __forceinline__ void cp_async16z(uint32_t dst, const void* src, uint32_t n) {
    asm volatile("cp.async.cg.shared.global [%0], [%1], 16, %2;" :: "r"(dst), "l"(src), "r"(n));
}
#define CP_COMMIT() asm volatile("cp.async.commit_group;" ::: "memory")
#define CP_WAIT(n)  asm volatile("cp.async.wait_group %0;" :: "n"(n) : "memory")

__device__ __forceinline__ void ldmx4(uint32_t& r0, uint32_t& r1, uint32_t& r2, uint32_t& r3,
                                      uint32_t addr) {
    asm volatile("ldmatrix.sync.aligned.m8n8.x4.shared.b16 {%0,%1,%2,%3}, [%4];"
                 : "=r"(r0), "=r"(r1), "=r"(r2), "=r"(r3) : "r"(addr));
}
__device__ __forceinline__ void mma16816(float* c, const uint32_t* a, uint32_t b0, uint32_t b1) {
    asm volatile(
        "mma.sync.aligned.m16n8k16.row.col.f32.f16.f16.f32 "
        "{%0,%1,%2,%3}, {%4,%5,%6,%7}, {%8,%9}, {%0,%1,%2,%3};"
        : "+f"(c[0]), "+f"(c[1]), "+f"(c[2]), "+f"(c[3])
        : "r"(a[0]), "r"(a[1]), "r"(a[2]), "r"(a[3]), "r"(b0), "r"(b1));
}
// A-side pair: (hi, lo)
__device__ __forceinline__ void pack2A(float a, float b, uint32_t* w) {
    const __half ha = __float2half_rn(a);
    const __half la = __float2half_rn(a - __half2float(ha));
    const __half hb = __float2half_rn(b);
    const __half lb = __float2half_rn(b - __half2float(hb));
    w[0] = (uint32_t)__half_as_ushort(ha) | ((uint32_t)__half_as_ushort(la) << 16);
    w[1] = (uint32_t)__half_as_ushort(hb) | ((uint32_t)__half_as_ushort(lb) << 16);
}
// single fp16 pair of values packed into one u32
__device__ __forceinline__ uint32_t pack1(float a, float b) {
    return (uint32_t)__half_as_ushort(__float2half_rn(a)) |
           ((uint32_t)__half_as_ushort(__float2half_rn(b)) << 16);
}

// ================= scratch =================
__device__ float g_v[B_ * S_ * DM_];
__device__ float g_part[B_ * DM_ * 36];       // per-chunk vmean partials
__device__ float g_vmean[B_ * DM_];
__device__ __half g_x2[B_ * S_ * K2_];        // x pairs (A) for V GEMM; later ctx pairs for out GEMM
__device__ __half g_xh[B_ * S_ * DM_];        // x plain fp16 (Q/K GEMMs)
__device__ __half g_q2h[B_ * S_ * DM_];       // q plain fp16
__device__ __half g_k2h[B_ * S_ * DM_];       // k plain fp16
__device__ __half g_w1t[2 * DM_ * DM_];       // Wq,Wk plain fp16 transposed [N,512]
__device__ __half g_w2t[2 * DM_ * K2_];       // Wv,Wo pattern-B pairs [N,1024]
__device__ __half g_v2t[2048 * 2304];         // V dims-major plain fp16, tokens padded [-128,2176)

// ================= split kernels =================
__global__ __launch_bounds__(256) void split_act2(const float* __restrict__ X,
                                                  __half* __restrict__ X2,
                                                  __half* __restrict__ XH) {
    const int idx = blockIdx.x * 256 + threadIdx.x;
    const int m = idx >> 6, g = idx & 63;
    const float4 f0 = *(const float4*)(X + (size_t)m * 512 + g * 8);
    const float4 f1 = *(const float4*)(X + (size_t)m * 512 + g * 8 + 4);
    float v[8] = {f0.x, f0.y, f0.z, f0.w, f1.x, f1.y, f1.z, f1.w};
    uint32_t w[8];
#pragma unroll
    for (int i = 0; i < 4; i++) pack2A(v[2 * i], v[2 * i + 1], w + 2 * i);
    uint4* dst = (uint4*)(X2 + (size_t)m * K2_ + g * 16);
    dst[0] = ((uint4*)w)[0]; dst[1] = ((uint4*)w)[1];
    // plain fp16 copy (w[0],w[2],w[4],w[6] low halves hold hi values pairwise)
    uint32_t p[4];
#pragma unroll
    for (int i = 0; i < 4; i++) p[i] = pack1(v[2 * i], v[2 * i + 1]);
    *(uint4*)(XH + (size_t)m * 512 + g * 8) = *(uint4*)p;
}

// z=0,1: Wq,Wk -> plain fp16 transposed [N,512]; z=2,3: Wv,Wo -> pattern-B pairs [N,1024]
__global__ __launch_bounds__(1024) void split_w4(const float* __restrict__ W0,
                                                 const float* __restrict__ W1,
                                                 const float* __restrict__ W2,
                                                 const float* __restrict__ W3,
                                                 __half* __restrict__ W1T,
                                                 __half* __restrict__ W2T) {
    __shared__ float t[32][33];
    const int z = blockIdx.z;
    const float* W = (z == 0) ? W0 : (z == 1) ? W1 : (z == 2) ? W2 : W3;
    const int k0 = blockIdx.y * 32, n0 = blockIdx.x * 32;
    const int tx = threadIdx.x, ty = threadIdx.y;
    t[ty][tx] = W[(size_t)(k0 + ty) * 512 + n0 + tx];
    __syncthreads();
    const float v = t[tx][ty];    // W[k0+tx][n0+ty]
    const uint32_t h = __half_as_ushort(__float2half_rn(v));
    if (z < 2) {
        __half* dst = W1T + (size_t)z * DM_ * DM_ + (size_t)(n0 + ty) * DM_ + (k0 + tx);
        *dst = __ushort_as_half((unsigned short)h);
    } else {
        uint32_t* dst = (uint32_t*)W2T + (size_t)(z - 2) * DM_ * 512
                        + (size_t)(n0 + ty) * 512 + (k0 + tx);
        *dst = h | (h << 16);
    }
}

// ================= 256x128 HMMA GEMM mainloop (runtime K-stride + chunk count) =================
#define GEMM_SMEM (3 * 49152 + 1024)

#define GEMM_MAINLOOP256(APTR, SA, BPTR, SB, NCH)                                         \
    extern __shared__ char smraw[];                                                       \
    const uint32_t sbase = (smem_u32(smraw) + 1023) & ~1023u;                             \
    const int tid = threadIdx.x;                                                          \
    const int wid = tid >> 5, lane = tid & 31;                                            \
    const int bm = blockIdx.x * 256, bn = blockIdx.y * 128;                               \
    const int wm0 = (wid & 3) * 64, wn0 = (wid >> 2) * 64;                                \
    const __half* l_srcA = (APTR) + (size_t)(bm + tid) * (SA);                            \
    const __half* l_srcB = (BPTR) + (size_t)(bn + (tid >> 1)) * (SB) + (tid & 1) * 32;    \
    const uint32_t a_doff = SWZ128(tid * 128);                                            \
    const uint32_t b_doff = 49152 - 16384 + SWZ128((tid >> 1) * 128 + (tid & 1) * 64);    \
    float acc[4][8][4];                                                                   \
    _Pragma("unroll")                                                                     \
    for (int a = 0; a < 4; a++)                                                           \
        _Pragma("unroll")                                                                 \
        for (int b = 0; b < 8; b++)                                                       \
            _Pragma("unroll")                                                             \
            for (int c = 0; c < 4; c++) acc[a][b][c] = 0.f;                               \
    _Pragma("unroll")                                                                     \
    for (int c = 0; c < 2; c++) {                                                         \
        const uint32_t st = sbase + c * 49152;                                            \
        _Pragma("unroll")                                                                 \
        for (int seg = 0; seg < 8; seg++)                                                 \
            cp_async16(st + (a_doff ^ (seg * 16)), l_srcA + c * 64 + seg * 8);            \
        _Pragma("unroll")                                                                 \
        for (int u = 0; u < 4; u++)                                                       \
            cp_async16(st + (b_doff ^ (u * 16)), l_srcB + c * 64 + u * 8);                \
        CP_COMMIT();                                                                      \
    }                                                                                     \
    for (int c = 0; c < (NCH); c++) {                                                     \
        CP_WAIT(1);                                                                       \
        __syncthreads();                                                                  \
        if (c + 2 < (NCH)) {                                                              \
            const uint32_t st = sbase + ((c + 2) % 3) * 49152;                            \
            _Pragma("unroll")                                                             \
            for (int seg = 0; seg < 8; seg++)                                             \
                cp_async16(st + (a_doff ^ (seg * 16)), l_srcA + (c + 2) * 64 + seg * 8);  \
            _Pragma("unroll")                                                             \
            for (int u = 0; u < 4; u++)                                                   \
                cp_async16(st + (b_doff ^ (u * 16)), l_srcB + (c + 2) * 64 + u * 8);      \
        }                                                                                 \
        CP_COMMIT();                                                                      \
        const uint32_t abuf = sbase + (c % 3) * 49152;                                    \
        const uint32_t bbuf = abuf + 32768;                                               \
        _Pragma("unroll")                                                                 \
        for (int ks = 0; ks < 4; ks++) {                                                  \
            const int cb = ks * 32 + ((lane >> 4) * 16);                                  \
            uint32_t bf[4][4];                                                            \
            _Pragma("unroll")                                                             \
            for (int bh = 0; bh < 4; bh++) {                                              \
                const int r = wn0 + bh * 16 + (lane & 15);                                \
                ldmx4(bf[bh][0], bf[bh][1], bf[bh][2], bf[bh][3],                         \
                      bbuf + SWZ128(r * 128 + cb));                                       \
            }                                                                             \
            _Pragma("unroll")                                                             \
            for (int mf = 0; mf < 4; mf++) {                                              \
                uint32_t a[4];                                                            \
                const int r = wm0 + mf * 16 + (lane & 15);                                \
                ldmx4(a[0], a[1], a[2], a[3], abuf + SWZ128(r * 128 + cb));               \
                _Pragma("unroll")                                                         \
                for (int nf = 0; nf < 8; nf++) {                                          \
                    const uint32_t b0 = bf[nf >> 1][(nf & 1)];                            \
                    const uint32_t b1 = bf[nf >> 1][(nf & 1) + 2];                        \
                    mma16816(acc[mf][nf], a, b0, b1);                                     \
                }                                                                         \
            }                                                                             \
        }                                                                                 \
    }                                                                                     \
    const int qr = lane >> 2, qc = (lane & 3) * 2;

// unified QKV: z=0 -> Q fp16 (K=512 single), z=1 -> K fp16 (K=512 single), z=2 -> V fp32 (K=1024 pairs)
__global__ __launch_bounds__(256, 1) void gemm_qkv(const __half* __restrict__ X2,
                                                   const __half* __restrict__ XH,
                                                   const __half* __restrict__ W1T,
                                                   const __half* __restrict__ W2T,
                                                   const float* __restrict__ bq,
                                                   const float* __restrict__ bk,
                                                   const float* __restrict__ bv,
                                                   __half* __restrict__ Q2h,
                                                   __half* __restrict__ K2h,
                                                   float* __restrict__ Vf) {
    const int z = blockIdx.z;
    const __half* Ap = (z == 2) ? X2 : XH;
    const int sA = (z == 2) ? K2_ : DM_;
    const __half* Bp = (z == 2) ? W2T : (W1T + (size_t)z * DM_ * DM_);
    const int sB = sA;
    const int nch = (z == 2) ? 16 : 8;
    GEMM_MAINLOOP256(Ap, sA, Bp, sB, nch)
    const float* bias = (z == 0) ? bq : (z == 1) ? bk : bv;
    if (z == 2) {
#pragma unroll
        for (int mf = 0; mf < 4; mf++) {
            const int row = bm + wm0 + mf * 16 + qr;
#pragma unroll
            for (int nf = 0; nf < 8; nf++) {
                const int col = bn + wn0 + nf * 8 + qc;
                const float b0 = bias[col], b1 = bias[col + 1];
                float2 lo, hi;
                lo.x = acc[mf][nf][0] + b0; lo.y = acc[mf][nf][1] + b1;
                hi.x = acc[mf][nf][2] + b0; hi.y = acc[mf][nf][3] + b1;
                *(float2*)(Vf + (size_t)row * 512 + col) = lo;
                *(float2*)(Vf + (size_t)(row + 8) * 512 + col) = hi;
            }
        }
    } else {
        uint32_t* t32 = (uint32_t*)((z == 0) ? Q2h : K2h);
#pragma unroll
        for (int mf = 0; mf < 4; mf++) {
            const int row = bm + wm0 + mf * 16 + qr;
#pragma unroll
            for (int nf = 0; nf < 8; nf++) {
                const int col = bn + wn0 + nf * 8 + qc;
                const float b0 = bias[col], b1 = bias[col + 1];
                const uint32_t idx0 = (uint32_t)row * 256 + (col >> 1);
                const uint32_t idx1 = idx0 + 8 * 256;
                t32[idx0] = pack1(acc[mf][nf][0] + b0, acc[mf][nf][1] + b1);
                t32[idx1] = pack1(acc[mf][nf][2] + b0, acc[mf][nf][3] + b1);
            }
        }
    }
}

// output projection: ctx pairs @ Wo pairs -> fp32 out
__global__ __launch_bounds__(256, 1) void gemm_out(const __half* __restrict__ A2,
                                                   const __half* __restrict__ B2,
                                                   const float* __restrict__ bias,
                                                   float* __restrict__ C) {
    GEMM_MAINLOOP256(A2, K2_, B2, K2_, 16)
#pragma unroll
    for (int mf = 0; mf < 4; mf++) {
        const int row = bm + wm0 + mf * 16 + qr;
#pragma unroll
        for (int nf = 0; nf < 8; nf++) {
            const int col = bn + wn0 + nf * 8 + qc;
            const float b0 = bias[col], b1 = bias[col + 1];
            float2 lo, hi;
            lo.x = acc[mf][nf][0] + b0; lo.y = acc[mf][nf][1] + b1;
            hi.x = acc[mf][nf][2] + b0; hi.y = acc[mf][nf][3] + b1;
            *(float2*)(C + (size_t)row * 512 + col) = lo;
            *(float2*)(C + (size_t)(row + 8) * 512 + col) = hi;
        }
    }
}

// ================= V transpose->fp16 build + vmean partials =================
__global__ __launch_bounds__(256) void v2t_build(const float* __restrict__ V,
                                                 __half* __restrict__ V2T,
                                                 float* __restrict__ part) {
    __shared__ float tr[64][65];
    const int cx = blockIdx.x;
    const int h = blockIdx.y, b = blockIdx.z;
    const int tid = threadIdx.x;
    const int t0 = cx * 64 - 128;
    const bool inr = (t0 >= 0) && (t0 + 64 <= S_);

    if (inr) {
        const int i = tid >> 2, dg = tid & 3;
        const float* vrow = V + ((size_t)(b * S_ + t0 + i)) * DM_ + h * D_ + dg * 16;
#pragma unroll
        for (int u = 0; u < 4; u++) {
            float4 f = *(const float4*)(vrow + u * 4);
            tr[dg * 16 + u * 4 + 0][i] = f.x;
            tr[dg * 16 + u * 4 + 1][i] = f.y;
            tr[dg * 16 + u * 4 + 2][i] = f.z;
            tr[dg * 16 + u * 4 + 3][i] = f.w;
        }
        __syncthreads();
    }

    const int d = tid >> 2, jg = tid & 3;
    uint32_t w[8];
    float s = 0.f;
    if (inr) {
#pragma unroll
        for (int t = 0; t < 8; t++) {
            const float va = tr[d][jg * 16 + 2 * t];
            const float vb = tr[d][jg * 16 + 2 * t + 1];
            w[t] = pack1(va, vb);
            s += va + vb;
        }
    } else {
#pragma unroll
        for (int t = 0; t < 8; t++) w[t] = 0;
    }
    uint4* dst = (uint4*)((char*)V2T + ((size_t)((b * 8 + h) * 64 + d) * 2304) * 2
                          + (size_t)cx * 128 + jg * 32);
    dst[0] = ((uint4*)w)[0];
    dst[1] = ((uint4*)w)[1];

    s += __shfl_xor_sync(0xffffffffu, s, 1);
    s += __shfl_xor_sync(0xffffffffu, s, 2);
    if (jg == 0)
        part[((size_t)(b * 512 + h * 64 + d)) * 36 + cx] = s;
}

__global__ __launch_bounds__(512) void vmean_final2(const float* __restrict__ part,
                                                    float* __restrict__ vm) {
    const int b = blockIdx.x, t = threadIdx.x;
    const float* p = part + ((size_t)(b * 512 + t)) * 36;
    float s = 0.f;
#pragma unroll
    for (int cx = 0; cx < 36; cx++) s += p[cx];
    vm[b * 512 + t] = s * (1.0f / 2048.0f);
}

// ================= HMMA banded attention (plain fp16, 3-phase) =================
#define AQ2 0
#define AK2 9216
#define AV2 18432
#define ASF 27648
#define AIL 110848
#define ATT_SMEM 111104

__global__ __launch_bounds__(256) void attn_mma2(const __half* __restrict__ Q2h,
                                                 const __half* __restrict__ K2h,
                                                 const __half* __restrict__ V2T,
                                                 const float* __restrict__ VMEAN,
                                                 const int* __restrict__ XLEN,
                                                 __half* __restrict__ C2) {
    extern __shared__ char smc[];
    const uint32_t sb = smem_u32(smc);
    float* Ss = (float*)(smc + ASF);
    float* invl = (float*)(smc + AIL);

    const int tid = threadIdx.x;
    const int wid = tid >> 5, lane = tid & 31;
    const int q0 = blockIdx.x * 64;
    const int h = blockIdx.y;
    const int b = blockIdx.z;
    const int xl = XLEN[b];

    const int wm = (wid & 3) * 16;
    const int wn = (wid >> 2) * 32;
    const int qr = lane >> 2, qc = (lane & 3) * 2;
    const int kbase0 = q0 - 128;

    const int lrow = tid >> 2;
    const int lcs = (tid & 3) * 2;

    {
        const char* qsrc = (const char*)Q2h + ((size_t)(b * S_ + q0 + lrow) * DM_ + h * 64) * 2;
#pragma unroll
        for (int u = 0; u < 2; u++)
            cp_async16(sb + AQ2 + lrow * 144 + (lcs + u) * 16, qsrc + (lcs + u) * 16);
    }
#pragma unroll
    for (int c = 0; c < 2; c++) {
        const int jabs = kbase0 + c * 64 + lrow;
        const bool valid = (jabs >= 0) && (jabs < S_);
        const char* ksrc = (const char*)K2h + ((size_t)(b * S_ + (valid ? jabs : 0)) * DM_ + h * 64) * 2;
        const uint32_t buf = sb + (c ? AV2 : AK2);
        const uint32_t n = valid ? 16u : 0u;
#pragma unroll
        for (int u = 0; u < 2; u++)
            cp_async16z(buf + lrow * 144 + (lcs + u) * 16, ksrc + (lcs + u) * 16, n);
        CP_COMMIT();
    }

#pragma unroll
    for (int c = 0; c < 5; c++) {
        if (c < 4) { CP_WAIT(1); } else { CP_WAIT(0); }
        __syncthreads();
        const uint32_t kbuf = sb + ((c & 1) ? AV2 : AK2);
        const int kb = kbase0 + c * 64;

        float acc[4][4];
#pragma unroll
        for (int nf = 0; nf < 4; nf++)
#pragma unroll
            for (int u = 0; u < 4; u++) acc[nf][u] = 0.f;

#pragma unroll
        for (int ks = 0; ks < 4; ks++) {
            const int cb = ks * 32 + (lane >> 4) * 16;
            uint32_t a[4];
            ldmx4(a[0], a[1], a[2], a[3], sb + AQ2 + (wm + (lane & 15)) * 144 + cb);
            uint32_t bf[2][4];
#pragma unroll
            for (int nh = 0; nh < 2; nh++) {
                const int r = wn + nh * 16 + (lane & 15);
                ldmx4(bf[nh][0], bf[nh][1], bf[nh][2], bf[nh][3], kbuf + r * 144 + cb);
            }
#pragma unroll
            for (int nf = 0; nf < 4; nf++) {
                const uint32_t b0 = bf[nf >> 1][(nf & 1)];
                const uint32_t b1 = bf[nf >> 1][(nf & 1) + 2];
                mma16816(acc[nf], a, b0, b1);
            }
        }

        const int i0 = wm + qr, iabs0 = q0 + i0;
        const int i1 = i0 + 8,  iabs1 = iabs0 + 8;
#pragma unroll
        for (int nf = 0; nf < 4; nf++) {
#pragma unroll
            for (int cc = 0; cc < 2; cc++) {
                const int col = wn + nf * 8 + qc + cc;
                const int jabs = kb + col;
                const bool jok = (jabs >= 0) && (jabs < xl);
                const bool v0 = jok && (jabs - iabs0 <= 128) && (iabs0 - jabs <= 128);
                const bool v1 = jok && (jabs - iabs1 <= 128) && (iabs1 - jabs <= 128);
                Ss[i0 * 325 + c * 64 + col] = v0 ? acc[nf][cc] * 0.125f : -1e30f;
                Ss[i1 * 325 + c * 64 + col] = v1 ? acc[nf][cc + 2] * 0.125f : -1e30f;
            }
        }
        __syncthreads();
        if (c + 2 < 5) {
            const int jabs = kbase0 + (c + 2) * 64 + lrow;
            const bool valid = (jabs >= 0) && (jabs < S_);
            const char* ksrc = (const char*)K2h + ((size_t)(b * S_ + (valid ? jabs : 0)) * DM_ + h * 64) * 2;
            const uint32_t buf = sb + ((c & 1) ? AV2 : AK2);
            const uint32_t n = valid ? 16u : 0u;
#pragma unroll
            for (int u = 0; u < 2; u++)
                cp_async16z(buf + lrow * 144 + (lcs + u) * 16, ksrc + (lcs + u) * 16, n);
        }
        CP_COMMIT();
    }

#pragma unroll
    for (int c = 0; c < 2; c++) {
        const char* vsrc = (const char*)V2T + ((size_t)((b * 8 + h) * 64 + lrow) * 2304) * 2
                           + (size_t)(q0 + c * 64) * 2;
        const uint32_t buf = sb + (c ? AV2 : AK2);
#pragma unroll
        for (int u = 0; u < 2; u++)
            cp_async16(buf + lrow * 144 + (lcs + u) * 16, vsrc + (lcs + u) * 16);
        CP_COMMIT();
    }

    {
        for (int rr = 0; rr < 8; rr++) {
            const int i = wid * 8 + rr;
            float* row = Ss + i * 325;
            float vals[10];
            float m = -3.0e38f;
#pragma unroll
            for (int t = 0; t < 10; t++) {
                vals[t] = row[lane + 32 * t];
                m = fmaxf(m, vals[t]);
            }
#pragma unroll
            for (int o = 16; o; o >>= 1) m = fmaxf(m, __shfl_xor_sync(0xffffffffu, m, o));
            float l = 0.f;
#pragma unroll
            for (int t = 0; t < 10; t++) {
                const float p = __expf(vals[t] - m);
                row[lane + 32 * t] = p;
                l += p;
            }
#pragma unroll
            for (int o = 16; o; o >>= 1) l += __shfl_xor_sync(0xffffffffu, l, o);
            if (lane == 0) invl[i] = 1.0f / l;
        }
    }
    __syncthreads();

    float oacc[4][4];
#pragma unroll
    for (int nf = 0; nf < 4; nf++)
#pragma unroll
        for (int u = 0; u < 4; u++) oacc[nf][u] = 0.f;

#pragma unroll
    for (int c = 0; c < 5; c++) {
        {
            const int row = tid & 63, jg = tid >> 6;
            const float* srow = Ss + row * 325 + c * 64 + jg * 16;
            uint32_t w[8];
#pragma unroll
            for (int t = 0; t < 8; t++) w[t] = pack1(srow[2 * t], srow[2 * t + 1]);
            uint4* dst = (uint4*)(smc + AQ2 + row * 144 + jg * 32);
            dst[0] = ((uint4*)w)[0];
            dst[1] = ((uint4*)w)[1];
        }
        if (c < 4) { CP_WAIT(1); } else { CP_WAIT(0); }
        __syncthreads();

        const uint32_t vbuf = sb + ((c & 1) ? AV2 : AK2);
#pragma unroll
        for (int ks = 0; ks < 4; ks++) {
            const int cb = ks * 32 + (lane >> 4) * 16;
            uint32_t a[4];
            ldmx4(a[0], a[1], a[2], a[3], sb + AQ2 + (wm + (lane & 15)) * 144 + cb);
            uint32_t bf[2][4];
#pragma unroll
            for (int nh = 0; nh < 2; nh++) {
                const int r = wn + nh * 16 + (lane & 15);
                ldmx4(bf[nh][0], bf[nh][1], bf[nh][2], bf[nh][3], vbuf + r * 144 + cb);
            }
#pragma unroll
            for (int nf = 0; nf < 4; nf++) {
                const uint32_t b0 = bf[nf >> 1][(nf & 1)];
                const uint32_t b1 = bf[nf >> 1][(nf & 1) + 2];
                mma16816(oacc[nf], a, b0, b1);
            }
        }
        __syncthreads();
        if (c + 2 < 5) {
            const char* vsrc = (const char*)V2T + ((size_t)((b * 8 + h) * 64 + lrow) * 2304) * 2
                               + (size_t)(q0 + (c + 2) * 64) * 2;
            const uint32_t buf = sb + ((c & 1) ? AV2 : AK2);
#pragma unroll
            for (int u = 0; u < 2; u++)
                cp_async16(buf + lrow * 144 + (lcs + u) * 16, vsrc + (lcs + u) * 16);
        }
        CP_COMMIT();
    }

    {
        const int i0 = wm + qr;
#pragma unroll
        for (int half = 0; half < 2; half++) {
            const int i = i0 + half * 8;
            const int iabs = q0 + i;
            int lo2 = iabs - 128;
            if (lo2 < 0) lo2 = 0;
            const bool deg = (lo2 >= xl);
            const float il = invl[i];
            uint32_t* crow = (uint32_t*)C2 + (size_t)(b * S_ + iabs) * 512 + h * 64;
            const float* vm = VMEAN + b * 512 + h * 64;
#pragma unroll
            for (int nf = 0; nf < 4; nf++) {
                const int col = wn + nf * 8 + qc;
                const float a = deg ? vm[col]      : oacc[nf][half * 2] * il;
                const float bb = deg ? vm[col + 1] : oacc[nf][half * 2 + 1] * il;
                uint32_t w[2];
                pack2A(a, bb, w);
                crow[col] = w[0]; crow[col + 1] = w[1];
            }
        }
    }
}

// ================= launch =================
extern "C" void kernel_launch(void* const* d_in, const int* in_sizes, int n_in,
                              void* d_out, int out_size) {
    const float* x  = (const float*)d_in[0];
    const float* Wq = (const float*)d_in[1];
    const float* bq = (const float*)d_in[2];
    const float* Wk = (const float*)d_in[3];
    const float* bk = (const float*)d_in[4];
    const float* Wv = (const float*)d_in[5];
    const float* bv = (const float*)d_in[6];
    const float* Wo = (const float*)d_in[7];
    const float* bo = (const float*)d_in[8];
    const int* xlen = (const int*)d_in[9];
    float* out = (float*)d_out;

    float *v, *part, *vmean;
    __half *x2, *xh, *q2h, *k2h, *w1t, *w2t, *v2t;
    cudaGetSymbolAddress((void**)&v, g_v);
    cudaGetSymbolAddress((void**)&part, g_part);
    cudaGetSymbolAddress((void**)&vmean, g_vmean);
    cudaGetSymbolAddress((void**)&x2, g_x2);
    cudaGetSymbolAddress((void**)&xh, g_xh);
    cudaGetSymbolAddress((void**)&q2h, g_q2h);
    cudaGetSymbolAddress((void**)&k2h, g_k2h);
    cudaGetSymbolAddress((void**)&w1t, g_w1t);
    cudaGetSymbolAddress((void**)&w2t, g_w2t);
    cudaGetSymbolAddress((void**)&v2t, g_v2t);

    cudaFuncSetAttribute(gemm_qkv, cudaFuncAttributeMaxDynamicSharedMemorySize, GEMM_SMEM);
    cudaFuncSetAttribute(gemm_out, cudaFuncAttributeMaxDynamicSharedMemorySize, GEMM_SMEM);
    cudaFuncSetAttribute(attn_mma2, cudaFuncAttributeMaxDynamicSharedMemorySize, ATT_SMEM);

    const dim3 qkv_grid(B_ * S_ / 256, DM_ / 128, 3);
    const dim3 out_grid(B_ * S_ / 256, DM_ / 128);

    split_act2<<<B_ * S_ * 64 / 256, 256>>>(x, x2, xh);
    split_w4<<<dim3(16, 16, 4), dim3(32, 32)>>>(Wq, Wk, Wv, Wo, w1t, w2t);

    gemm_qkv<<<qkv_grid, 256, GEMM_SMEM>>>(x2, xh, w1t, w2t, bq, bk, bv, q2h, k2h, v);

    v2t_build<<<dim3(36, H_, B_), 256>>>(v, v2t, part);
    vmean_final2<<<B_, 512>>>(part, vmean);

    attn_mma2<<<dim3(S_ / 64, H_, B_), 256, ATT_SMEM>>>(q2h, k2h, v2t, vmean, xlen, x2);

    gemm_out<<<out_grid, 256, GEMM_SMEM>>>(x2, w2t + (size_t)DM_ * K2_, bo, out);
}

// round 12
// speedup vs baseline: 1.9944x; 1.2693x over previous
#include <cuda_runtime.h>
#include <cuda_fp16.h>
#include <cstdint>

#define B_  4
#define S_  2048
#define DM_ 512
#define H_  8
#define D_  64

// ================= helpers =================
__device__ __forceinline__ uint32_t smem_u32(const void* p) {
    uint32_t a;
    asm("{ .reg .u64 t; cvta.to.shared.u64 t, %1; cvt.u32.u64 %0, t; }" : "=r"(a) : "l"(p));
    return a;
}
#define SWZ128(off) ((off) ^ (((off) >> 3) & 0x70))

__device__ __forceinline__ void cp_async16(uint32_t dst, const void* src) {
    asm volatile("cp.async.cg.shared.global [%0], [%1], 16;" :: "r"(dst), "l"(src));
}
__device__ __forceinline__ void cp_async16z(uint32_t dst, const void* src, uint32_t n) {
    asm volatile("cp.async.cg.shared.global [%0], [%1], 16, %2;" :: "r"(dst), "l"(src), "r"(n));
}
#define CP_COMMIT() asm volatile("cp.async.commit_group;" ::: "memory")
#define CP_WAIT(n)  asm volatile("cp.async.wait_group %0;" :: "n"(n) : "memory")

__device__ __forceinline__ void ldmx4(uint32_t& r0, uint32_t& r1, uint32_t& r2, uint32_t& r3,
                                      uint32_t addr) {
    asm volatile("ldmatrix.sync.aligned.m8n8.x4.shared.b16 {%0,%1,%2,%3}, [%4];"
                 : "=r"(r0), "=r"(r1), "=r"(r2), "=r"(r3) : "r"(addr));
}
__device__ __forceinline__ void mma16816(float* c, const uint32_t* a, uint32_t b0, uint32_t b1) {
    asm volatile(
        "mma.sync.aligned.m16n8k16.row.col.f32.f16.f16.f32 "
        "{%0,%1,%2,%3}, {%4,%5,%6,%7}, {%8,%9}, {%0,%1,%2,%3};"
        : "+f"(c[0]), "+f"(c[1]), "+f"(c[2]), "+f"(c[3])
        : "r"(a[0]), "r"(a[1]), "r"(a[2]), "r"(a[3]), "r"(b0), "r"(b1));
}
// single fp16 pair of values packed into one u32
__device__ __forceinline__ uint32_t pack1(float a, float b) {
    return (uint32_t)__half_as_ushort(__float2half_rn(a)) |
           ((uint32_t)__half_as_ushort(__float2half_rn(b)) << 16);
}

// ================= scratch =================
__device__ float g_v[B_ * S_ * DM_];
__device__ float g_part[B_ * DM_ * 36];       // per-chunk vmean partials
__device__ float g_vmean[B_ * DM_];
__device__ __half g_xh[B_ * S_ * DM_];        // x plain fp16; later reused as ctx fp16
__device__ __half g_q2h[B_ * S_ * DM_];       // q plain fp16
__device__ __half g_k2h[B_ * S_ * DM_];       // k plain fp16
__device__ __half g_w1t[4 * DM_ * DM_];       // Wq,Wk,Wv,Wo plain fp16 transposed [N,512]
__device__ __half g_v2t[2048 * 2304];         // V dims-major fp16, tokens padded [-128,2176)

// ================= split kernels =================
__global__ __launch_bounds__(256) void split_act1(const float* __restrict__ X,
                                                  __half* __restrict__ XH) {
    const int idx = blockIdx.x * 256 + threadIdx.x;
    const int m = idx >> 6, g = idx & 63;
    const float4 f0 = *(const float4*)(X + (size_t)m * 512 + g * 8);
    const float4 f1 = *(const float4*)(X + (size_t)m * 512 + g * 8 + 4);
    uint32_t p[4];
    p[0] = pack1(f0.x, f0.y); p[1] = pack1(f0.z, f0.w);
    p[2] = pack1(f1.x, f1.y); p[3] = pack1(f1.z, f1.w);
    *(uint4*)(XH + (size_t)m * 512 + g * 8) = *(uint4*)p;
}

// all weights -> plain fp16 transposed [N,512]
__global__ __launch_bounds__(1024) void split_w4(const float* __restrict__ W0,
                                                 const float* __restrict__ W1,
                                                 const float* __restrict__ W2,
                                                 const float* __restrict__ W3,
                                                 __half* __restrict__ W1T) {
    __shared__ float t[32][33];
    const int z = blockIdx.z;
    const float* W = (z == 0) ? W0 : (z == 1) ? W1 : (z == 2) ? W2 : W3;
    const int k0 = blockIdx.y * 32, n0 = blockIdx.x * 32;
    const int tx = threadIdx.x, ty = threadIdx.y;
    t[ty][tx] = W[(size_t)(k0 + ty) * 512 + n0 + tx];
    __syncthreads();
    W1T[(size_t)z * DM_ * DM_ + (size_t)(n0 + ty) * DM_ + (k0 + tx)] =
        __float2half_rn(t[tx][ty]);
}

// ================= 256x128 HMMA GEMM mainloop (K=512, 8 chunks) =================
#define GEMM_SMEM (3 * 49152 + 1024)
#define NCH8 8

#define GEMM_MAINLOOP256(APTR, BPTR)                                                      \
    extern __shared__ char smraw[];                                                       \
    const uint32_t sbase = (smem_u32(smraw) + 1023) & ~1023u;                             \
    const int tid = threadIdx.x;                                                          \
    const int wid = tid >> 5, lane = tid & 31;                                            \
    const int bm = blockIdx.x * 256, bn = blockIdx.y * 128;                               \
    const int wm0 = (wid & 3) * 64, wn0 = (wid >> 2) * 64;                                \
    const __half* l_srcA = (APTR) + (size_t)(bm + tid) * DM_;                             \
    const __half* l_srcB = (BPTR) + (size_t)(bn + (tid >> 1)) * DM_ + (tid & 1) * 32;     \
    const uint32_t a_doff = SWZ128(tid * 128);                                            \
    const uint32_t b_doff = 49152 - 16384 + SWZ128((tid >> 1) * 128 + (tid & 1) * 64);    \
    float acc[4][8][4];                                                                   \
    _Pragma("unroll")                                                                     \
    for (int a = 0; a < 4; a++)                                                           \
        _Pragma("unroll")                                                                 \
        for (int b = 0; b < 8; b++)                                                       \
            _Pragma("unroll")                                                             \
            for (int c = 0; c < 4; c++) acc[a][b][c] = 0.f;                               \
    _Pragma("unroll")                                                                     \
    for (int c = 0; c < 2; c++) {                                                         \
        const uint32_t st = sbase + c * 49152;                                            \
        _Pragma("unroll")                                                                 \
        for (int seg = 0; seg < 8; seg++)                                                 \
            cp_async16(st + (a_doff ^ (seg * 16)), l_srcA + c * 64 + seg * 8);            \
        _Pragma("unroll")                                                                 \
        for (int u = 0; u < 4; u++)                                                       \
            cp_async16(st + (b_doff ^ (u * 16)), l_srcB + c * 64 + u * 8);                \
        CP_COMMIT();                                                                      \
    }                                                                                     \
    for (int c = 0; c < NCH8; c++) {                                                      \
        CP_WAIT(1);                                                                       \
        __syncthreads();                                                                  \
        if (c + 2 < NCH8) {                                                               \
            const uint32_t st = sbase + ((c + 2) % 3) * 49152;                            \
            _Pragma("unroll")                                                             \
            for (int seg = 0; seg < 8; seg++)                                             \
                cp_async16(st + (a_doff ^ (seg * 16)), l_srcA + (c + 2) * 64 + seg * 8);  \
            _Pragma("unroll")                                                             \
            for (int u = 0; u < 4; u++)                                                   \
                cp_async16(st + (b_doff ^ (u * 16)), l_srcB + (c + 2) * 64 + u * 8);      \
        }                                                                                 \
        CP_COMMIT();                                                                      \
        const uint32_t abuf = sbase + (c % 3) * 49152;                                    \
        const uint32_t bbuf = abuf + 32768;                                               \
        _Pragma("unroll")                                                                 \
        for (int ks = 0; ks < 4; ks++) {                                                  \
            const int cb = ks * 32 + ((lane >> 4) * 16);                                  \
            uint32_t bf[4][4];                                                            \
            _Pragma("unroll")                                                             \
            for (int bh = 0; bh < 4; bh++) {                                              \
                const int r = wn0 + bh * 16 + (lane & 15);                                \
                ldmx4(bf[bh][0], bf[bh][1], bf[bh][2], bf[bh][3],                         \
                      bbuf + SWZ128(r * 128 + cb));                                       \
            }                                                                             \
            _Pragma("unroll")                                                             \
            for (int mf = 0; mf < 4; mf++) {                                              \
                uint32_t a[4];                                                            \
                const int r = wm0 + mf * 16 + (lane & 15);                                \
                ldmx4(a[0], a[1], a[2], a[3], abuf + SWZ128(r * 128 + cb));               \
                _Pragma("unroll")                                                         \
                for (int nf = 0; nf < 8; nf++) {                                          \
                    const uint32_t b0 = bf[nf >> 1][(nf & 1)];                            \
                    const uint32_t b1 = bf[nf >> 1][(nf & 1) + 2];                        \
                    mma16816(acc[mf][nf], a, b0, b1);                                     \
                }                                                                         \
            }                                                                             \
        }                                                                                 \
    }                                                                                     \
    const int qr = lane >> 2, qc = (lane & 3) * 2;

// unified QKV: z=0 -> Q fp16, z=1 -> K fp16, z=2 -> V fp32
__global__ __launch_bounds__(256, 1) void gemm_qkv(const __half* __restrict__ XH,
                                                   const __half* __restrict__ W1T,
                                                   const float* __restrict__ bq,
                                                   const float* __restrict__ bk,
                                                   const float* __restrict__ bv,
                                                   __half* __restrict__ Q2h,
                                                   __half* __restrict__ K2h,
                                                   float* __restrict__ Vf) {
    const int z = blockIdx.z;
    GEMM_MAINLOOP256(XH, W1T + (size_t)z * DM_ * DM_)
    const float* bias = (z == 0) ? bq : (z == 1) ? bk : bv;
    if (z == 2) {
#pragma unroll
        for (int mf = 0; mf < 4; mf++) {
            const int row = bm + wm0 + mf * 16 + qr;
#pragma unroll
            for (int nf = 0; nf < 8; nf++) {
                const int col = bn + wn0 + nf * 8 + qc;
                const float b0 = bias[col], b1 = bias[col + 1];
                float2 lo, hi;
                lo.x = acc[mf][nf][0] + b0; lo.y = acc[mf][nf][1] + b1;
                hi.x = acc[mf][nf][2] + b0; hi.y = acc[mf][nf][3] + b1;
                *(float2*)(Vf + (size_t)row * 512 + col) = lo;
                *(float2*)(Vf + (size_t)(row + 8) * 512 + col) = hi;
            }
        }
    } else {
        uint32_t* t32 = (uint32_t*)((z == 0) ? Q2h : K2h);
#pragma unroll
        for (int mf = 0; mf < 4; mf++) {
            const int row = bm + wm0 + mf * 16 + qr;
#pragma unroll
            for (int nf = 0; nf < 8; nf++) {
                const int col = bn + wn0 + nf * 8 + qc;
                const float b0 = bias[col], b1 = bias[col + 1];
                const uint32_t idx0 = (uint32_t)row * 256 + (col >> 1);
                const uint32_t idx1 = idx0 + 8 * 256;
                t32[idx0] = pack1(acc[mf][nf][0] + b0, acc[mf][nf][1] + b1);
                t32[idx1] = pack1(acc[mf][nf][2] + b0, acc[mf][nf][3] + b1);
            }
        }
    }
}

// output projection: ctx fp16 @ Wo fp16 -> fp32 out
__global__ __launch_bounds__(256, 1) void gemm_out(const __half* __restrict__ CTXH,
                                                   const __half* __restrict__ WOT,
                                                   const float* __restrict__ bias,
                                                   float* __restrict__ C) {
    GEMM_MAINLOOP256(CTXH, WOT)
#pragma unroll
    for (int mf = 0; mf < 4; mf++) {
        const int row = bm + wm0 + mf * 16 + qr;
#pragma unroll
        for (int nf = 0; nf < 8; nf++) {
            const int col = bn + wn0 + nf * 8 + qc;
            const float b0 = bias[col], b1 = bias[col + 1];
            float2 lo, hi;
            lo.x = acc[mf][nf][0] + b0; lo.y = acc[mf][nf][1] + b1;
            hi.x = acc[mf][nf][2] + b0; hi.y = acc[mf][nf][3] + b1;
            *(float2*)(C + (size_t)row * 512 + col) = lo;
            *(float2*)(C + (size_t)(row + 8) * 512 + col) = hi;
        }
    }
}

// ================= V transpose->fp16 build + vmean partials =================
__global__ __launch_bounds__(256) void v2t_build(const float* __restrict__ V,
                                                 __half* __restrict__ V2T,
                                                 float* __restrict__ part) {
    __shared__ float tr[64][65];
    const int cx = blockIdx.x;
    const int h = blockIdx.y, b = blockIdx.z;
    const int tid = threadIdx.x;
    const int t0 = cx * 64 - 128;
    const bool inr = (t0 >= 0) && (t0 + 64 <= S_);

    if (inr) {
        const int i = tid >> 2, dg = tid & 3;
        const float* vrow = V + ((size_t)(b * S_ + t0 + i)) * DM_ + h * D_ + dg * 16;
#pragma unroll
        for (int u = 0; u < 4; u++) {
            float4 f = *(const float4*)(vrow + u * 4);
            tr[dg * 16 + u * 4 + 0][i] = f.x;
            tr[dg * 16 + u * 4 + 1][i] = f.y;
            tr[dg * 16 + u * 4 + 2][i] = f.z;
            tr[dg * 16 + u * 4 + 3][i] = f.w;
        }
        __syncthreads();
    }

    const int d = tid >> 2, jg = tid & 3;
    uint32_t w[8];
    float s = 0.f;
    if (inr) {
#pragma unroll
        for (int t = 0; t < 8; t++) {
            const float va = tr[d][jg * 16 + 2 * t];
            const float vb = tr[d][jg * 16 + 2 * t + 1];
            w[t] = pack1(va, vb);
            s += va + vb;
        }
    } else {
#pragma unroll
        for (int t = 0; t < 8; t++) w[t] = 0;
    }
    uint4* dst = (uint4*)((char*)V2T + ((size_t)((b * 8 + h) * 64 + d) * 2304) * 2
                          + (size_t)cx * 128 + jg * 32);
    dst[0] = ((uint4*)w)[0];
    dst[1] = ((uint4*)w)[1];

    s += __shfl_xor_sync(0xffffffffu, s, 1);
    s += __shfl_xor_sync(0xffffffffu, s, 2);
    if (jg == 0)
        part[((size_t)(b * 512 + h * 64 + d)) * 36 + cx] = s;
}

__global__ __launch_bounds__(512) void vmean_final2(const float* __restrict__ part,
                                                    float* __restrict__ vm) {
    const int b = blockIdx.x, t = threadIdx.x;
    const float* p = part + ((size_t)(b * 512 + t)) * 36;
    float s = 0.f;
#pragma unroll
    for (int cx = 0; cx < 36; cx++) s += p[cx];
    vm[b * 512 + t] = s * (1.0f / 2048.0f);
}

// ================= HMMA banded attention (plain fp16, 3-phase) =================
#define AQ2 0
#define AK2 9216
#define AV2 18432
#define ASF 27648
#define AIL 110848
#define ATT_SMEM 111104

__global__ __launch_bounds__(256) void attn_mma2(const __half* __restrict__ Q2h,
                                                 const __half* __restrict__ K2h,
                                                 const __half* __restrict__ V2T,
                                                 const float* __restrict__ VMEAN,
                                                 const int* __restrict__ XLEN,
                                                 __half* __restrict__ CTXH) {
    extern __shared__ char smc[];
    const uint32_t sb = smem_u32(smc);
    float* Ss = (float*)(smc + ASF);
    float* invl = (float*)(smc + AIL);

    const int tid = threadIdx.x;
    const int wid = tid >> 5, lane = tid & 31;
    const int q0 = blockIdx.x * 64;
    const int h = blockIdx.y;
    const int b = blockIdx.z;
    const int xl = XLEN[b];

    const int wm = (wid & 3) * 16;
    const int wn = (wid >> 2) * 32;
    const int qr = lane >> 2, qc = (lane & 3) * 2;
    const int kbase0 = q0 - 128;

    const int lrow = tid >> 2;
    const int lcs = (tid & 3) * 2;

    {
        const char* qsrc = (const char*)Q2h + ((size_t)(b * S_ + q0 + lrow) * DM_ + h * 64) * 2;
#pragma unroll
        for (int u = 0; u < 2; u++)
            cp_async16(sb + AQ2 + lrow * 144 + (lcs + u) * 16, qsrc + (lcs + u) * 16);
    }
#pragma unroll
    for (int c = 0; c < 2; c++) {
        const int jabs = kbase0 + c * 64 + lrow;
        const bool valid = (jabs >= 0) && (jabs < S_);
        const char* ksrc = (const char*)K2h + ((size_t)(b * S_ + (valid ? jabs : 0)) * DM_ + h * 64) * 2;
        const uint32_t buf = sb + (c ? AV2 : AK2);
        const uint32_t n = valid ? 16u : 0u;
#pragma unroll
        for (int u = 0; u < 2; u++)
            cp_async16z(buf + lrow * 144 + (lcs + u) * 16, ksrc + (lcs + u) * 16, n);
        CP_COMMIT();
    }

#pragma unroll
    for (int c = 0; c < 5; c++) {
        if (c < 4) { CP_WAIT(1); } else { CP_WAIT(0); }
        __syncthreads();
        const uint32_t kbuf = sb + ((c & 1) ? AV2 : AK2);
        const int kb = kbase0 + c * 64;

        float acc[4][4];
#pragma unroll
        for (int nf = 0; nf < 4; nf++)
#pragma unroll
            for (int u = 0; u < 4; u++) acc[nf][u] = 0.f;

#pragma unroll
        for (int ks = 0; ks < 4; ks++) {
            const int cb = ks * 32 + (lane >> 4) * 16;
            uint32_t a[4];
            ldmx4(a[0], a[1], a[2], a[3], sb + AQ2 + (wm + (lane & 15)) * 144 + cb);
            uint32_t bf[2][4];
#pragma unroll
            for (int nh = 0; nh < 2; nh++) {
                const int r = wn + nh * 16 + (lane & 15);
                ldmx4(bf[nh][0], bf[nh][1], bf[nh][2], bf[nh][3], kbuf + r * 144 + cb);
            }
#pragma unroll
            for (int nf = 0; nf < 4; nf++) {
                const uint32_t b0 = bf[nf >> 1][(nf & 1)];
                const uint32_t b1 = bf[nf >> 1][(nf & 1) + 2];
                mma16816(acc[nf], a, b0, b1);
            }
        }

        const int i0 = wm + qr, iabs0 = q0 + i0;
        const int i1 = i0 + 8,  iabs1 = iabs0 + 8;
#pragma unroll
        for (int nf = 0; nf < 4; nf++) {
#pragma unroll
            for (int cc = 0; cc < 2; cc++) {
                const int col = wn + nf * 8 + qc + cc;
                const int jabs = kb + col;
                const bool jok = (jabs >= 0) && (jabs < xl);
                const bool v0 = jok && (jabs - iabs0 <= 128) && (iabs0 - jabs <= 128);
                const bool v1 = jok && (jabs - iabs1 <= 128) && (iabs1 - jabs <= 128);
                Ss[i0 * 325 + c * 64 + col] = v0 ? acc[nf][cc] * 0.125f : -1e30f;
                Ss[i1 * 325 + c * 64 + col] = v1 ? acc[nf][cc + 2] * 0.125f : -1e30f;
            }
        }
        __syncthreads();
        if (c + 2 < 5) {
            const int jabs = kbase0 + (c + 2) * 64 + lrow;
            const bool valid = (jabs >= 0) && (jabs < S_);
            const char* ksrc = (const char*)K2h + ((size_t)(b * S_ + (valid ? jabs : 0)) * DM_ + h * 64) * 2;
            const uint32_t buf = sb + ((c & 1) ? AV2 : AK2);
            const uint32_t n = valid ? 16u : 0u;
#pragma unroll
            for (int u = 0; u < 2; u++)
                cp_async16z(buf + lrow * 144 + (lcs + u) * 16, ksrc + (lcs + u) * 16, n);
        }
        CP_COMMIT();
    }

#pragma unroll
    for (int c = 0; c < 2; c++) {
        const char* vsrc = (const char*)V2T + ((size_t)((b * 8 + h) * 64 + lrow) * 2304) * 2
                           + (size_t)(q0 + c * 64) * 2;
        const uint32_t buf = sb + (c ? AV2 : AK2);
#pragma unroll
        for (int u = 0; u < 2; u++)
            cp_async16(buf + lrow * 144 + (lcs + u) * 16, vsrc + (lcs + u) * 16);
        CP_COMMIT();
    }

    {
        for (int rr = 0; rr < 8; rr++) {
            const int i = wid * 8 + rr;
            float* row = Ss + i * 325;
            float vals[10];
            float m = -3.0e38f;
#pragma unroll
            for (int t = 0; t < 10; t++) {
                vals[t] = row[lane + 32 * t];
                m = fmaxf(m, vals[t]);
            }
#pragma unroll
            for (int o = 16; o; o >>= 1) m = fmaxf(m, __shfl_xor_sync(0xffffffffu, m, o));
            float l = 0.f;
#pragma unroll
            for (int t = 0; t < 10; t++) {
                const float p = __expf(vals[t] - m);
                row[lane + 32 * t] = p;
                l += p;
            }
#pragma unroll
            for (int o = 16; o; o >>= 1) l += __shfl_xor_sync(0xffffffffu, l, o);
            if (lane == 0) invl[i] = 1.0f / l;
        }
    }
    __syncthreads();

    float oacc[4][4];
#pragma unroll
    for (int nf = 0; nf < 4; nf++)
#pragma unroll
        for (int u = 0; u < 4; u++) oacc[nf][u] = 0.f;

#pragma unroll
    for (int c = 0; c < 5; c++) {
        {
            const int row = tid & 63, jg = tid >> 6;
            const float* srow = Ss + row * 325 + c * 64 + jg * 16;
            uint32_t w[8];
#pragma unroll
            for (int t = 0; t < 8; t++) w[t] = pack1(srow[2 * t], srow[2 * t + 1]);
            uint4* dst = (uint4*)(smc + AQ2 + row * 144 + jg * 32);
            dst[0] = ((uint4*)w)[0];
            dst[1] = ((uint4*)w)[1];
        }
        if (c < 4) { CP_WAIT(1); } else { CP_WAIT(0); }
        __syncthreads();

        const uint32_t vbuf = sb + ((c & 1) ? AV2 : AK2);
#pragma unroll
        for (int ks = 0; ks < 4; ks++) {
            const int cb = ks * 32 + (lane >> 4) * 16;
            uint32_t a[4];
            ldmx4(a[0], a[1], a[2], a[3], sb + AQ2 + (wm + (lane & 15)) * 144 + cb);
            uint32_t bf[2][4];
#pragma unroll
            for (int nh = 0; nh < 2; nh++) {
                const int r = wn + nh * 16 + (lane & 15);
                ldmx4(bf[nh][0], bf[nh][1], bf[nh][2], bf[nh][3], vbuf + r * 144 + cb);
            }
#pragma unroll
            for (int nf = 0; nf < 4; nf++) {
                const uint32_t b0 = bf[nf >> 1][(nf & 1)];
                const uint32_t b1 = bf[nf >> 1][(nf & 1) + 2];
                mma16816(oacc[nf], a, b0, b1);
            }
        }
        __syncthreads();
        if (c + 2 < 5) {
            const char* vsrc = (const char*)V2T + ((size_t)((b * 8 + h) * 64 + lrow) * 2304) * 2
                               + (size_t)(q0 + (c + 2) * 64) * 2;
            const uint32_t buf = sb + ((c & 1) ? AV2 : AK2);
#pragma unroll
            for (int u = 0; u < 2; u++)
                cp_async16(buf + lrow * 144 + (lcs + u) * 16, vsrc + (lcs + u) * 16);
        }
        CP_COMMIT();
    }

    // ---- final write: normalize, plain fp16 ctx, deg override ----
    {
        const int i0 = wm + qr;
#pragma unroll
        for (int half = 0; half < 2; half++) {
            const int i = i0 + half * 8;
            const int iabs = q0 + i;
            int lo2 = iabs - 128;
            if (lo2 < 0) lo2 = 0;
            const bool deg = (lo2 >= xl);
            const float il = invl[i];
            uint32_t* crow = (uint32_t*)CTXH + (size_t)(b * S_ + iabs) * 256 + h * 32;
            const float* vm = VMEAN + b * 512 + h * 64;
#pragma unroll
            for (int nf = 0; nf < 4; nf++) {
                const int col = wn + nf * 8 + qc;
                const float a = deg ? vm[col]      : oacc[nf][half * 2] * il;
                const float bb = deg ? vm[col + 1] : oacc[nf][half * 2 + 1] * il;
                crow[col >> 1] = pack1(a, bb);
            }
        }
    }
}

// ================= launch =================
extern "C" void kernel_launch(void* const* d_in, const int* in_sizes, int n_in,
                              void* d_out, int out_size) {
    const float* x  = (const float*)d_in[0];
    const float* Wq = (const float*)d_in[1];
    const float* bq = (const float*)d_in[2];
    const float* Wk = (const float*)d_in[3];
    const float* bk = (const float*)d_in[4];
    const float* Wv = (const float*)d_in[5];
    const float* bv = (const float*)d_in[6];
    const float* Wo = (const float*)d_in[7];
    const float* bo = (const float*)d_in[8];
    const int* xlen = (const int*)d_in[9];
    float* out = (float*)d_out;

    float *v, *part, *vmean;
    __half *xh, *q2h, *k2h, *w1t, *v2t;
    cudaGetSymbolAddress((void**)&v, g_v);
    cudaGetSymbolAddress((void**)&part, g_part);
    cudaGetSymbolAddress((void**)&vmean, g_vmean);
    cudaGetSymbolAddress((void**)&xh, g_xh);
    cudaGetSymbolAddress((void**)&q2h, g_q2h);
    cudaGetSymbolAddress((void**)&k2h, g_k2h);
    cudaGetSymbolAddress((void**)&w1t, g_w1t);
    cudaGetSymbolAddress((void**)&v2t, g_v2t);

    cudaFuncSetAttribute(gemm_qkv, cudaFuncAttributeMaxDynamicSharedMemorySize, GEMM_SMEM);
    cudaFuncSetAttribute(gemm_out, cudaFuncAttributeMaxDynamicSharedMemorySize, GEMM_SMEM);
    cudaFuncSetAttribute(attn_mma2, cudaFuncAttributeMaxDynamicSharedMemorySize, ATT_SMEM);

    const dim3 qkv_grid(B_ * S_ / 256, DM_ / 128, 3);
    const dim3 out_grid(B_ * S_ / 256, DM_ / 128);

    split_act1<<<B_ * S_ * 64 / 256, 256>>>(x, xh);
    split_w4<<<dim3(16, 16, 4), dim3(32, 32)>>>(Wq, Wk, Wv, Wo, w1t);

    gemm_qkv<<<qkv_grid, 256, GEMM_SMEM>>>(xh, w1t, bq, bk, bv, q2h, k2h, v);

    v2t_build<<<dim3(36, H_, B_), 256>>>(v, v2t, part);
    vmean_final2<<<B_, 512>>>(part, vmean);

    // ctx reuses xh (x no longer needed after gemm_qkv)
    attn_mma2<<<dim3(S_ / 64, H_, B_), 256, ATT_SMEM>>>(q2h, k2h, v2t, vmean, xlen, xh);

    gemm_out<<<out_grid, 256, GEMM_SMEM>>>(xh, w1t + 3 * (size_t)DM_ * DM_, bo, out);
}

// round 13
// speedup vs baseline: 2.6985x; 1.3530x over previous
#include <cuda_runtime.h>
#include <cuda_fp16.h>
#include <cstdint>

#define B_  4
#define S_  2048
#define DM_ 512
#define H_  8
#define D_  64

// ================= helpers =================
__device__ __forceinline__ uint32_t smem_u32(const void* p) {
    uint32_t a;
    asm("{ .reg .u64 t; cvta.to.shared.u64 t, %1; cvt.u32.u64 %0, t; }" : "=r"(a) : "l"(p));
    return a;
}
#define SWZ128(off) ((off) ^ (((off) >> 3) & 0x70))

__device__ __forceinline__ void cp_async16(uint32_t dst, const void* src) {
    asm volatile("cp.async.cg.shared.global [%0], [%1], 16;" :: "r"(dst), "l"(src));
}
__device__ __forceinline__ void cp_async16z(uint32_t dst, const void* src, uint32_t n) {
    asm volatile("cp.async.cg.shared.global [%0], [%1], 16, %2;" :: "r"(dst), "l"(src), "r"(n));
}
#define CP_COMMIT() asm volatile("cp.async.commit_group;" ::: "memory")
#define CP_WAIT(n)  asm volatile("cp.async.wait_group %0;" :: "n"(n) : "memory")

__device__ __forceinline__ void ldmx4(uint32_t& r0, uint32_t& r1, uint32_t& r2, uint32_t& r3,
                                      uint32_t addr) {
    asm volatile("ldmatrix.sync.aligned.m8n8.x4.shared.b16 {%0,%1,%2,%3}, [%4];"
                 : "=r"(r0), "=r"(r1), "=r"(r2), "=r"(r3) : "r"(addr));
}
__device__ __forceinline__ void mma16816(float* c, const uint32_t* a, uint32_t b0, uint32_t b1) {
    asm volatile(
        "mma.sync.aligned.m16n8k16.row.col.f32.f16.f16.f32 "
        "{%0,%1,%2,%3}, {%4,%5,%6,%7}, {%8,%9}, {%0,%1,%2,%3};"
        : "+f"(c[0]), "+f"(c[1]), "+f"(c[2]), "+f"(c[3])
        : "r"(a[0]), "r"(a[1]), "r"(a[2]), "r"(a[3]), "r"(b0), "r"(b1));
}
// single fp16 pair of values packed into one u32
__device__ __forceinline__ uint32_t pack1(float a, float b) {
    return (uint32_t)__half_as_ushort(__float2half_rn(a)) |
           ((uint32_t)__half_as_ushort(__float2half_rn(b)) << 16);
}

// ================= scratch =================
__device__ float g_v[B_ * S_ * DM_];
__device__ float g_part[B_ * DM_ * 36];       // per-chunk vmean partials
__device__ float g_vmean[B_ * DM_];
__device__ __half g_xh[B_ * S_ * DM_];        // x plain fp16; later reused as ctx fp16
__device__ __half g_q2h[B_ * S_ * DM_];       // q plain fp16
__device__ __half g_k2h[B_ * S_ * DM_];       // k plain fp16
__device__ __half g_w1t[4 * DM_ * DM_];       // Wq,Wk,Wv,Wo plain fp16 transposed [N,512]
__device__ __half g_v2t[2048 * 2304];         // V dims-major fp16, tokens padded [-128,2176)

// ================= split kernels =================
__global__ __launch_bounds__(256) void split_act1(const float* __restrict__ X,
                                                  __half* __restrict__ XH) {
    const int idx = blockIdx.x * 256 + threadIdx.x;
    const int m = idx >> 6, g = idx & 63;
    const float4 f0 = *(const float4*)(X + (size_t)m * 512 + g * 8);
    const float4 f1 = *(const float4*)(X + (size_t)m * 512 + g * 8 + 4);
    uint32_t p[4];
    p[0] = pack1(f0.x, f0.y); p[1] = pack1(f0.z, f0.w);
    p[2] = pack1(f1.x, f1.y); p[3] = pack1(f1.z, f1.w);
    *(uint4*)(XH + (size_t)m * 512 + g * 8) = *(uint4*)p;
}

__global__ __launch_bounds__(1024) void split_w4(const float* __restrict__ W0,
                                                 const float* __restrict__ W1,
                                                 const float* __restrict__ W2,
                                                 const float* __restrict__ W3,
                                                 __half* __restrict__ W1T) {
    __shared__ float t[32][33];
    const int z = blockIdx.z;
    const float* W = (z == 0) ? W0 : (z == 1) ? W1 : (z == 2) ? W2 : W3;
    const int k0 = blockIdx.y * 32, n0 = blockIdx.x * 32;
    const int tx = threadIdx.x, ty = threadIdx.y;
    t[ty][tx] = W[(size_t)(k0 + ty) * 512 + n0 + tx];
    __syncthreads();
    W1T[(size_t)z * DM_ * DM_ + (size_t)(n0 + ty) * DM_ + (k0 + tx)] =
        __float2half_rn(t[tx][ty]);
}

// ================= 256x128 HMMA GEMM mainloop (K=512, 8 chunks) =================
#define GEMM_SMEM (3 * 49152 + 1024)
#define NCH8 8

#define GEMM_MAINLOOP256(APTR, BPTR)                                                      \
    extern __shared__ char smraw[];                                                       \
    const uint32_t sbase = (smem_u32(smraw) + 1023) & ~1023u;                             \
    const int tid = threadIdx.x;                                                          \
    const int wid = tid >> 5, lane = tid & 31;                                            \
    const int bm = blockIdx.x * 256, bn = blockIdx.y * 128;                               \
    const int wm0 = (wid & 3) * 64, wn0 = (wid >> 2) * 64;                                \
    const __half* l_srcA = (APTR) + (size_t)(bm + tid) * DM_;                             \
    const __half* l_srcB = (BPTR) + (size_t)(bn + (tid >> 1)) * DM_ + (tid & 1) * 32;     \
    const uint32_t a_doff = SWZ128(tid * 128);                                            \
    const uint32_t b_doff = 49152 - 16384 + SWZ128((tid >> 1) * 128 + (tid & 1) * 64);    \
    float acc[4][8][4];                                                                   \
    _Pragma("unroll")                                                                     \
    for (int a = 0; a < 4; a++)                                                           \
        _Pragma("unroll")                                                                 \
        for (int b = 0; b < 8; b++)                                                       \
            _Pragma("unroll")                                                             \
            for (int c = 0; c < 4; c++) acc[a][b][c] = 0.f;                               \
    _Pragma("unroll")                                                                     \
    for (int c = 0; c < 2; c++) {                                                         \
        const uint32_t st = sbase + c * 49152;                                            \
        _Pragma("unroll")                                                                 \
        for (int seg = 0; seg < 8; seg++)                                                 \
            cp_async16(st + (a_doff ^ (seg * 16)), l_srcA + c * 64 + seg * 8);            \
        _Pragma("unroll")                                                                 \
        for (int u = 0; u < 4; u++)                                                       \
            cp_async16(st + (b_doff ^ (u * 16)), l_srcB + c * 64 + u * 8);                \
        CP_COMMIT();                                                                      \
    }                                                                                     \
    for (int c = 0; c < NCH8; c++) {                                                      \
        CP_WAIT(1);                                                                       \
        __syncthreads();                                                                  \
        if (c + 2 < NCH8) {                                                               \
            const uint32_t st = sbase + ((c + 2) % 3) * 49152;                            \
            _Pragma("unroll")                                                             \
            for (int seg = 0; seg < 8; seg++)                                             \
                cp_async16(st + (a_doff ^ (seg * 16)), l_srcA + (c + 2) * 64 + seg * 8);  \
            _Pragma("unroll")                                                             \
            for (int u = 0; u < 4; u++)                                                   \
                cp_async16(st + (b_doff ^ (u * 16)), l_srcB + (c + 2) * 64 + u * 8);      \
        }                                                                                 \
        CP_COMMIT();                                                                      \
        const uint32_t abuf = sbase + (c % 3) * 49152;                                    \
        const uint32_t bbuf = abuf + 32768;                                               \
        _Pragma("unroll")                                                                 \
        for (int ks = 0; ks < 4; ks++) {                                                  \
            const int cb = ks * 32 + ((lane >> 4) * 16);                                  \
            uint32_t bf[4][4];                                                            \
            _Pragma("unroll")                                                             \
            for (int bh = 0; bh < 4; bh++) {                                              \
                const int r = wn0 + bh * 16 + (lane & 15);                                \
                ldmx4(bf[bh][0], bf[bh][1], bf[bh][2], bf[bh][3],                         \
                      bbuf + SWZ128(r * 128 + cb));                                       \
            }                                                                             \
            _Pragma("unroll")                                                             \
            for (int mf = 0; mf < 4; mf++) {                                              \
                uint32_t a[4];                                                            \
                const int r = wm0 + mf * 16 + (lane & 15);                                \
                ldmx4(a[0], a[1], a[2], a[3], abuf + SWZ128(r * 128 + cb));               \
                _Pragma("unroll")                                                         \
                for (int nf = 0; nf < 8; nf++) {                                          \
                    const uint32_t b0 = bf[nf >> 1][(nf & 1)];                            \
                    const uint32_t b1 = bf[nf >> 1][(nf & 1) + 2];                        \
                    mma16816(acc[mf][nf], a, b0, b1);                                     \
                }                                                                         \
            }                                                                             \
        }                                                                                 \
    }                                                                                     \
    const int qr = lane >> 2, qc = (lane & 3) * 2;

// unified QKV: z=0 -> Q fp16, z=1 -> K fp16 (skips fully-masked token blocks), z=2 -> V fp32
__global__ __launch_bounds__(256, 1) void gemm_qkv(const __half* __restrict__ XH,
                                                   const __half* __restrict__ W1T,
                                                   const float* __restrict__ bq,
                                                   const float* __restrict__ bk,
                                                   const float* __restrict__ bv,
                                                   const int* __restrict__ XLEN,
                                                   __half* __restrict__ Q2h,
                                                   __half* __restrict__ K2h,
                                                   float* __restrict__ Vf) {
    const int z = blockIdx.z;
    if (z == 1) {
        const int bm_pre = blockIdx.x * 256;
        if ((bm_pre & 2047) >= XLEN[bm_pre >> 11]) return;  // K rows never consumed
    }
    GEMM_MAINLOOP256(XH, W1T + (size_t)z * DM_ * DM_)
    const float* bias = (z == 0) ? bq : (z == 1) ? bk : bv;
    if (z == 2) {
#pragma unroll
        for (int mf = 0; mf < 4; mf++) {
            const int row = bm + wm0 + mf * 16 + qr;
#pragma unroll
            for (int nf = 0; nf < 8; nf++) {
                const int col = bn + wn0 + nf * 8 + qc;
                const float b0 = bias[col], b1 = bias[col + 1];
                float2 lo, hi;
                lo.x = acc[mf][nf][0] + b0; lo.y = acc[mf][nf][1] + b1;
                hi.x = acc[mf][nf][2] + b0; hi.y = acc[mf][nf][3] + b1;
                *(float2*)(Vf + (size_t)row * 512 + col) = lo;
                *(float2*)(Vf + (size_t)(row + 8) * 512 + col) = hi;
            }
        }
    } else {
        uint32_t* t32 = (uint32_t*)((z == 0) ? Q2h : K2h);
#pragma unroll
        for (int mf = 0; mf < 4; mf++) {
            const int row = bm + wm0 + mf * 16 + qr;
#pragma unroll
            for (int nf = 0; nf < 8; nf++) {
                const int col = bn + wn0 + nf * 8 + qc;
                const float b0 = bias[col], b1 = bias[col + 1];
                const uint32_t idx0 = (uint32_t)row * 256 + (col >> 1);
                const uint32_t idx1 = idx0 + 8 * 256;
                t32[idx0] = pack1(acc[mf][nf][0] + b0, acc[mf][nf][1] + b1);
                t32[idx1] = pack1(acc[mf][nf][2] + b0, acc[mf][nf][3] + b1);
            }
        }
    }
}

// output projection: ctx fp16 @ Wo fp16 -> fp32 out
__global__ __launch_bounds__(256, 1) void gemm_out(const __half* __restrict__ CTXH,
                                                   const __half* __restrict__ WOT,
                                                   const float* __restrict__ bias,
                                                   float* __restrict__ C) {
    GEMM_MAINLOOP256(CTXH, WOT)
#pragma unroll
    for (int mf = 0; mf < 4; mf++) {
        const int row = bm + wm0 + mf * 16 + qr;
#pragma unroll
        for (int nf = 0; nf < 8; nf++) {
            const int col = bn + wn0 + nf * 8 + qc;
            const float b0 = bias[col], b1 = bias[col + 1];
            float2 lo, hi;
            lo.x = acc[mf][nf][0] + b0; lo.y = acc[mf][nf][1] + b1;
            hi.x = acc[mf][nf][2] + b0; hi.y = acc[mf][nf][3] + b1;
            *(float2*)(C + (size_t)row * 512 + col) = lo;
            *(float2*)(C + (size_t)(row + 8) * 512 + col) = hi;
        }
    }
}

// ================= V transpose->fp16 build + vmean partials =================
__global__ __launch_bounds__(256) void v2t_build(const float* __restrict__ V,
                                                 __half* __restrict__ V2T,
                                                 float* __restrict__ part) {
    __shared__ float tr[64][65];
    const int cx = blockIdx.x;
    const int h = blockIdx.y, b = blockIdx.z;
    const int tid = threadIdx.x;
    const int t0 = cx * 64 - 128;
    const bool inr = (t0 >= 0) && (t0 + 64 <= S_);

    if (inr) {
        const int i = tid >> 2, dg = tid & 3;
        const float* vrow = V + ((size_t)(b * S_ + t0 + i)) * DM_ + h * D_ + dg * 16;
#pragma unroll
        for (int u = 0; u < 4; u++) {
            float4 f = *(const float4*)(vrow + u * 4);
            tr[dg * 16 + u * 4 + 0][i] = f.x;
            tr[dg * 16 + u * 4 + 1][i] = f.y;
            tr[dg * 16 + u * 4 + 2][i] = f.z;
            tr[dg * 16 + u * 4 + 3][i] = f.w;
        }
        __syncthreads();
    }

    const int d = tid >> 2, jg = tid & 3;
    uint32_t w[8];
    float s = 0.f;
    if (inr) {
#pragma unroll
        for (int t = 0; t < 8; t++) {
            const float va = tr[d][jg * 16 + 2 * t];
            const float vb = tr[d][jg * 16 + 2 * t + 1];
            w[t] = pack1(va, vb);
            s += va + vb;
        }
    } else {
#pragma unroll
        for (int t = 0; t < 8; t++) w[t] = 0;
    }
    uint4* dst = (uint4*)((char*)V2T + ((size_t)((b * 8 + h) * 64 + d) * 2304) * 2
                          + (size_t)cx * 128 + jg * 32);
    dst[0] = ((uint4*)w)[0];
    dst[1] = ((uint4*)w)[1];

    s += __shfl_xor_sync(0xffffffffu, s, 1);
    s += __shfl_xor_sync(0xffffffffu, s, 2);
    if (jg == 0)
        part[((size_t)(b * 512 + h * 64 + d)) * 36 + cx] = s;
}

__global__ __launch_bounds__(512) void vmean_final2(const float* __restrict__ part,
                                                    float* __restrict__ vm) {
    const int b = blockIdx.x, t = threadIdx.x;
    const float* p = part + ((size_t)(b * 512 + t)) * 36;
    float s = 0.f;
#pragma unroll
    for (int cx = 0; cx < 36; cx++) s += p[cx];
    vm[b * 512 + t] = s * (1.0f / 2048.0f);
}

// ================= HMMA banded attention (plain fp16, xl-aware skipping) =================
#define AQ2 0
#define AK2 9216
#define AV2 18432
#define ASF 27648
#define AIL 110848
#define ATT_SMEM 111104

__global__ __launch_bounds__(256) void attn_mma2(const __half* __restrict__ Q2h,
                                                 const __half* __restrict__ K2h,
                                                 const __half* __restrict__ V2T,
                                                 const float* __restrict__ VMEAN,
                                                 const int* __restrict__ XLEN,
                                                 __half* __restrict__ CTXH) {
    extern __shared__ char smc[];
    const uint32_t sb = smem_u32(smc);
    float* Ss = (float*)(smc + ASF);
    float* invl = (float*)(smc + AIL);

    const int tid = threadIdx.x;
    const int wid = tid >> 5, lane = tid & 31;
    const int q0 = blockIdx.x * 64;
    const int h = blockIdx.y;
    const int b = blockIdx.z;
    const int xl = XLEN[b];
    const int kbase0 = q0 - 128;

    // ---- degenerate block: every row's band fully masked -> vmean, exit ----
    {
        int blk_lo = kbase0 < 0 ? 0 : kbase0;
        if (blk_lo >= xl) {
            const int row = tid >> 2;
            const int cg = (tid & 3) * 16;
            uint32_t* crow = (uint32_t*)CTXH + (size_t)(b * S_ + q0 + row) * 256
                             + h * 32 + (cg >> 1);
            const float* vm = VMEAN + b * 512 + h * 64 + cg;
#pragma unroll
            for (int k = 0; k < 8; k++) crow[k] = pack1(vm[2 * k], vm[2 * k + 1]);
            return;
        }
    }

    // chunks with any key < xl
    int cmax = (xl - kbase0 + 63) >> 6;
    if (cmax > 5) cmax = 5;

    const int wm = (wid & 3) * 16;
    const int wn = (wid >> 2) * 32;
    const int qr = lane >> 2, qc = (lane & 3) * 2;
    const int lrow = tid >> 2;
    const int lcs = (tid & 3) * 2;

    // ---- issue Q + K0 (group 0), K1 (group 1) ----
    {
        const char* qsrc = (const char*)Q2h + ((size_t)(b * S_ + q0 + lrow) * DM_ + h * 64) * 2;
#pragma unroll
        for (int u = 0; u < 2; u++)
            cp_async16(sb + AQ2 + lrow * 144 + (lcs + u) * 16, qsrc + (lcs + u) * 16);
    }
#pragma unroll
    for (int c = 0; c < 2; c++) {
        if (c < cmax) {
            const int jabs = kbase0 + c * 64 + lrow;
            const bool valid = (jabs >= 0) && (jabs < S_);
            const char* ksrc = (const char*)K2h + ((size_t)(b * S_ + (valid ? jabs : 0)) * DM_ + h * 64) * 2;
            const uint32_t buf = sb + (c ? AV2 : AK2);
            const uint32_t n = valid ? 16u : 0u;
#pragma unroll
            for (int u = 0; u < 2; u++)
                cp_async16z(buf + lrow * 144 + (lcs + u) * 16, ksrc + (lcs + u) * 16, n);
        }
        CP_COMMIT();
    }

    // ---- phase 1: energies (chunks < cmax) ----
#pragma unroll
    for (int c = 0; c < 5; c++) {
        if (c < 4) { CP_WAIT(1); } else { CP_WAIT(0); }
        __syncthreads();
        if (c < cmax) {
            const uint32_t kbuf = sb + ((c & 1) ? AV2 : AK2);
            const int kb = kbase0 + c * 64;

            float acc[4][4];
#pragma unroll
            for (int nf = 0; nf < 4; nf++)
#pragma unroll
                for (int u = 0; u < 4; u++) acc[nf][u] = 0.f;

#pragma unroll
            for (int ks = 0; ks < 4; ks++) {
                const int cb = ks * 32 + (lane >> 4) * 16;
                uint32_t a[4];
                ldmx4(a[0], a[1], a[2], a[3], sb + AQ2 + (wm + (lane & 15)) * 144 + cb);
                uint32_t bf[2][4];
#pragma unroll
                for (int nh = 0; nh < 2; nh++) {
                    const int r = wn + nh * 16 + (lane & 15);
                    ldmx4(bf[nh][0], bf[nh][1], bf[nh][2], bf[nh][3], kbuf + r * 144 + cb);
                }
#pragma unroll
                for (int nf = 0; nf < 4; nf++) {
                    const uint32_t b0 = bf[nf >> 1][(nf & 1)];
                    const uint32_t b1 = bf[nf >> 1][(nf & 1) + 2];
                    mma16816(acc[nf], a, b0, b1);
                }
            }

            const int i0 = wm + qr, iabs0 = q0 + i0;
            const int i1 = i0 + 8,  iabs1 = iabs0 + 8;
#pragma unroll
            for (int nf = 0; nf < 4; nf++) {
#pragma unroll
                for (int cc = 0; cc < 2; cc++) {
                    const int col = wn + nf * 8 + qc + cc;
                    const int jabs = kb + col;
                    const bool jok = (jabs >= 0) && (jabs < xl);
                    const bool v0 = jok && (jabs - iabs0 <= 128) && (iabs0 - jabs <= 128);
                    const bool v1 = jok && (jabs - iabs1 <= 128) && (iabs1 - jabs <= 128);
                    Ss[i0 * 325 + c * 64 + col] = v0 ? acc[nf][cc] * 0.125f : -1e30f;
                    Ss[i1 * 325 + c * 64 + col] = v1 ? acc[nf][cc + 2] * 0.125f : -1e30f;
                }
            }
        }
        __syncthreads();
        if (c + 2 < cmax) {
            const int jabs = kbase0 + (c + 2) * 64 + lrow;
            const bool valid = (jabs >= 0) && (jabs < S_);
            const char* ksrc = (const char*)K2h + ((size_t)(b * S_ + (valid ? jabs : 0)) * DM_ + h * 64) * 2;
            const uint32_t buf = sb + ((c & 1) ? AV2 : AK2);
            const uint32_t n = valid ? 16u : 0u;
#pragma unroll
            for (int u = 0; u < 2; u++)
                cp_async16z(buf + lrow * 144 + (lcs + u) * 16, ksrc + (lcs + u) * 16, n);
        }
        CP_COMMIT();
    }

    // ---- preload V chunks 0,1 (only those < cmax) ----
#pragma unroll
    for (int c = 0; c < 2; c++) {
        if (c < cmax) {
            const char* vsrc = (const char*)V2T + ((size_t)((b * 8 + h) * 64 + lrow) * 2304) * 2
                               + (size_t)(q0 + c * 64) * 2;
            const uint32_t buf = sb + (c ? AV2 : AK2);
#pragma unroll
            for (int u = 0; u < 2; u++)
                cp_async16(buf + lrow * 144 + (lcs + u) * 16, vsrc + (lcs + u) * 16);
        }
        CP_COMMIT();
    }

    // ---- phase 2: softmax over cols < cmax*64 ----
    {
        const int limit = cmax * 64;
        for (int rr = 0; rr < 8; rr++) {
            const int i = wid * 8 + rr;
            float* row = Ss + i * 325;
            float vals[10];
            float m = -3.0e38f;
#pragma unroll
            for (int t = 0; t < 10; t++) {
                vals[t] = (lane + 32 * t < limit) ? row[lane + 32 * t] : -1e30f;
                m = fmaxf(m, vals[t]);
            }
#pragma unroll
            for (int o = 16; o; o >>= 1) m = fmaxf(m, __shfl_xor_sync(0xffffffffu, m, o));
            float l = 0.f;
#pragma unroll
            for (int t = 0; t < 10; t++) {
                const float p = __expf(vals[t] - m);
                if (lane + 32 * t < limit) row[lane + 32 * t] = p;
                l += p;
            }
#pragma unroll
            for (int o = 16; o; o >>= 1) l += __shfl_xor_sync(0xffffffffu, l, o);
            if (lane == 0) invl[i] = 1.0f / l;
        }
    }
    __syncthreads();

    // ---- phase 3: AV (chunks < cmax) ----
    float oacc[4][4];
#pragma unroll
    for (int nf = 0; nf < 4; nf++)
#pragma unroll
        for (int u = 0; u < 4; u++) oacc[nf][u] = 0.f;

#pragma unroll
    for (int c = 0; c < 5; c++) {
        if (c < cmax) {
            const int row = tid & 63, jg = tid >> 6;
            const float* srow = Ss + row * 325 + c * 64 + jg * 16;
            uint32_t w[8];
#pragma unroll
            for (int t = 0; t < 8; t++) w[t] = pack1(srow[2 * t], srow[2 * t + 1]);
            uint4* dst = (uint4*)(smc + AQ2 + row * 144 + jg * 32);
            dst[0] = ((uint4*)w)[0];
            dst[1] = ((uint4*)w)[1];
        }
        if (c < 4) { CP_WAIT(1); } else { CP_WAIT(0); }
        __syncthreads();

        if (c < cmax) {
            const uint32_t vbuf = sb + ((c & 1) ? AV2 : AK2);
#pragma unroll
            for (int ks = 0; ks < 4; ks++) {
                const int cb = ks * 32 + (lane >> 4) * 16;
                uint32_t a[4];
                ldmx4(a[0], a[1], a[2], a[3], sb + AQ2 + (wm + (lane & 15)) * 144 + cb);
                uint32_t bf[2][4];
#pragma unroll
                for (int nh = 0; nh < 2; nh++) {
                    const int r = wn + nh * 16 + (lane & 15);
                    ldmx4(bf[nh][0], bf[nh][1], bf[nh][2], bf[nh][3], vbuf + r * 144 + cb);
                }
#pragma unroll
                for (int nf = 0; nf < 4; nf++) {
                    const uint32_t b0 = bf[nf >> 1][(nf & 1)];
                    const uint32_t b1 = bf[nf >> 1][(nf & 1) + 2];
                    mma16816(oacc[nf], a, b0, b1);
                }
            }
        }
        __syncthreads();
        if (c + 2 < cmax) {
            const char* vsrc = (const char*)V2T + ((size_t)((b * 8 + h) * 64 + lrow) * 2304) * 2
                               + (size_t)(q0 + (c + 2) * 64) * 2;
            const uint32_t buf = sb + ((c & 1) ? AV2 : AK2);
#pragma unroll
            for (int u = 0; u < 2; u++)
                cp_async16(buf + lrow * 144 + (lcs + u) * 16, vsrc + (lcs + u) * 16);
        }
        CP_COMMIT();
    }

    // ---- final write: normalize, plain fp16 ctx, deg override ----
    {
        const int i0 = wm + qr;
#pragma unroll
        for (int half = 0; half < 2; half++) {
            const int i = i0 + half * 8;
            const int iabs = q0 + i;
            int lo2 = iabs - 128;
            if (lo2 < 0) lo2 = 0;
            const bool deg = (lo2 >= xl);
            const float il = invl[i];
            uint32_t* crow = (uint32_t*)CTXH + (size_t)(b * S_ + iabs) * 256 + h * 32;
            const float* vm = VMEAN + b * 512 + h * 64;
#pragma unroll
            for (int nf = 0; nf < 4; nf++) {
                const int col = wn + nf * 8 + qc;
                const float a = deg ? vm[col]      : oacc[nf][half * 2] * il;
                const float bb = deg ? vm[col + 1] : oacc[nf][half * 2 + 1] * il;
                crow[col >> 1] = pack1(a, bb);
            }
        }
    }
}

// ================= launch =================
extern "C" void kernel_launch(void* const* d_in, const int* in_sizes, int n_in,
                              void* d_out, int out_size) {
    const float* x  = (const float*)d_in[0];
    const float* Wq = (const float*)d_in[1];
    const float* bq = (const float*)d_in[2];
    const float* Wk = (const float*)d_in[3];
    const float* bk = (const float*)d_in[4];
    const float* Wv = (const float*)d_in[5];
    const float* bv = (const float*)d_in[6];
    const float* Wo = (const float*)d_in[7];
    const float* bo = (const float*)d_in[8];
    const int* xlen = (const int*)d_in[9];
    float* out = (float*)d_out;

    float *v, *part, *vmean;
    __half *xh, *q2h, *k2h, *w1t, *v2t;
    cudaGetSymbolAddress((void**)&v, g_v);
    cudaGetSymbolAddress((void**)&part, g_part);
    cudaGetSymbolAddress((void**)&vmean, g_vmean);
    cudaGetSymbolAddress((void**)&xh, g_xh);
    cudaGetSymbolAddress((void**)&q2h, g_q2h);
    cudaGetSymbolAddress((void**)&k2h, g_k2h);
    cudaGetSymbolAddress((void**)&w1t, g_w1t);
    cudaGetSymbolAddress((void**)&v2t, g_v2t);

    cudaFuncSetAttribute(gemm_qkv, cudaFuncAttributeMaxDynamicSharedMemorySize, GEMM_SMEM);
    cudaFuncSetAttribute(gemm_out, cudaFuncAttributeMaxDynamicSharedMemorySize, GEMM_SMEM);
    cudaFuncSetAttribute(attn_mma2, cudaFuncAttributeMaxDynamicSharedMemorySize, ATT_SMEM);

    const dim3 qkv_grid(B_ * S_ / 256, DM_ / 128, 3);
    const dim3 out_grid(B_ * S_ / 256, DM_ / 128);

    split_act1<<<B_ * S_ * 64 / 256, 256>>>(x, xh);
    split_w4<<<dim3(16, 16, 4), dim3(32, 32)>>>(Wq, Wk, Wv, Wo, w1t);

    gemm_qkv<<<qkv_grid, 256, GEMM_SMEM>>>(xh, w1t, bq, bk, bv, xlen, q2h, k2h, v);

    v2t_build<<<dim3(36, H_, B_), 256>>>(v, v2t, part);
    vmean_final2<<<B_, 512>>>(part, vmean);

    attn_mma2<<<dim3(S_ / 64, H_, B_), 256, ATT_SMEM>>>(q2h, k2h, v2t, vmean, xlen, xh);

    gemm_out<<<out_grid, 256, GEMM_SMEM>>>(xh, w1t + 3 * (size_t)DM_ * DM_, bo, out);
}

// round 14
// speedup vs baseline: 2.7894x; 1.0337x over previous
#include <cuda_runtime.h>
#include <cuda_fp16.h>
#include <cstdint>

#define B_  4
#define S_  2048
#define DM_ 512
#define H_  8
#define D_  64

// ================= helpers =================
__device__ __forceinline__ uint32_t smem_u32(const void* p) {
    uint32_t a;
    asm("{ .reg .u64 t; cvta.to.shared.u64 t, %1; cvt.u32.u64 %0, t; }" : "=r"(a) : "l"(p));
    return a;
}
#define SWZ128(off) ((off) ^ (((off) >> 3) & 0x70))

__device__ __forceinline__ void cp_async16(uint32_t dst, const void* src) {
    asm volatile("cp.async.cg.shared.global [%0], [%1], 16;" :: "r"(dst), "l"(src));
}
__device__ __forceinline__ void cp_async16z(uint32_t dst, const void* src, uint32_t n) {
    asm volatile("cp.async.cg.shared.global [%0], [%1], 16, %2;" :: "r"(dst), "l"(src), "r"(n));
}
#define CP_COMMIT() asm volatile("cp.async.commit_group;" ::: "memory")
#define CP_WAIT(n)  asm volatile("cp.async.wait_group %0;" :: "n"(n) : "memory")

__device__ __forceinline__ void ldmx4(uint32_t& r0, uint32_t& r1, uint32_t& r2, uint32_t& r3,
                                      uint32_t addr) {
    asm volatile("ldmatrix.sync.aligned.m8n8.x4.shared.b16 {%0,%1,%2,%3}, [%4];"
                 : "=r"(r0), "=r"(r1), "=r"(r2), "=r"(r3) : "r"(addr));
}
__device__ __forceinline__ void mma16816(float* c, const uint32_t* a, uint32_t b0, uint32_t b1) {
    asm volatile(
        "mma.sync.aligned.m16n8k16.row.col.f32.f16.f16.f32 "
        "{%0,%1,%2,%3}, {%4,%5,%6,%7}, {%8,%9}, {%0,%1,%2,%3};"
        : "+f"(c[0]), "+f"(c[1]), "+f"(c[2]), "+f"(c[3])
        : "r"(a[0]), "r"(a[1]), "r"(a[2]), "r"(a[3]), "r"(b0), "r"(b1));
}
__device__ __forceinline__ uint32_t pack1(float a, float b) {
    return (uint32_t)__half_as_ushort(__float2half_rn(a)) |
           ((uint32_t)__half_as_ushort(__float2half_rn(b)) << 16);
}

// ================= scratch =================
__device__ float g_v[B_ * S_ * DM_];
__device__ float g_part[B_ * DM_ * 36];
__device__ float g_vmean[B_ * DM_];
__device__ __half g_xh[B_ * S_ * DM_];        // x fp16; later ctx fp16
__device__ __half g_q2h[B_ * S_ * DM_];
__device__ __half g_k2h[B_ * S_ * DM_];
__device__ __half g_w1t[4 * DM_ * DM_];       // Wq,Wk,Wv,Wo fp16 transposed [N,512]
__device__ __half g_v2t[2048 * 2304];         // V dims-major fp16, tokens padded [-128,2176)

// ================= split kernels =================
__global__ __launch_bounds__(256) void split_act1(const float* __restrict__ X,
                                                  __half* __restrict__ XH) {
    const int idx = blockIdx.x * 256 + threadIdx.x;
    const int m = idx >> 6, g = idx & 63;
    const float4 f0 = *(const float4*)(X + (size_t)m * 512 + g * 8);
    const float4 f1 = *(const float4*)(X + (size_t)m * 512 + g * 8 + 4);
    uint32_t p[4];
    p[0] = pack1(f0.x, f0.y); p[1] = pack1(f0.z, f0.w);
    p[2] = pack1(f1.x, f1.y); p[3] = pack1(f1.z, f1.w);
    *(uint4*)(XH + (size_t)m * 512 + g * 8) = *(uint4*)p;
}

__global__ __launch_bounds__(1024) void split_w4(const float* __restrict__ W0,
                                                 const float* __restrict__ W1,
                                                 const float* __restrict__ W2,
                                                 const float* __restrict__ W3,
                                                 __half* __restrict__ W1T) {
    __shared__ float t[32][33];
    const int z = blockIdx.z;
    const float* W = (z == 0) ? W0 : (z == 1) ? W1 : (z == 2) ? W2 : W3;
    const int k0 = blockIdx.y * 32, n0 = blockIdx.x * 32;
    const int tx = threadIdx.x, ty = threadIdx.y;
    t[ty][tx] = W[(size_t)(k0 + ty) * 512 + n0 + tx];
    __syncthreads();
    W1T[(size_t)z * DM_ * DM_ + (size_t)(n0 + ty) * DM_ + (k0 + tx)] =
        __float2half_rn(t[tx][ty]);
}

// ================= 256x128 HMMA GEMM mainloop (BK=128, 2-stage, 4 chunks) =================
// stage layout: A0(32KB,k0-63) A1(32KB,k64-127) B0(16KB) B1(16KB) = 96KB
#define GSTAGE 98304
#define GEMM_SMEM (2 * GSTAGE + 1024)
#define NCH4 4

#define GEMM_LOADCHUNK(stg, coff)                                                          \
    do {                                                                                   \
        _Pragma("unroll")                                                                  \
        for (int seg = 0; seg < 8; seg++) {                                                \
            cp_async16((stg) + (a_doff ^ (seg * 16)), l_srcA + (coff) + seg * 8);          \
            cp_async16((stg) + 32768 + (a_doff ^ (seg * 16)), l_srcA + (coff) + 64 + seg * 8); \
        }                                                                                  \
        _Pragma("unroll")                                                                  \
        for (int u = 0; u < 4; u++) {                                                      \
            cp_async16((stg) + 65536 + (b_doff ^ (u * 16)), l_srcB + (coff) + u * 8);      \
            cp_async16((stg) + 81920 + (b_doff ^ (u * 16)), l_srcB + (coff) + 64 + u * 8); \
        }                                                                                  \
    } while (0)

#define GEMM_MAINLOOP256(APTR, BPTR)                                                       \
    extern __shared__ char smraw[];                                                       \
    const uint32_t sbase = (smem_u32(smraw) + 1023) & ~1023u;                             \
    const int tid = threadIdx.x;                                                          \
    const int wid = tid >> 5, lane = tid & 31;                                            \
    const int bm = blockIdx.x * 256, bn = blockIdx.y * 128;                               \
    const int wm0 = (wid & 3) * 64, wn0 = (wid >> 2) * 64;                                \
    const __half* l_srcA = (APTR) + (size_t)(bm + tid) * DM_;                             \
    const __half* l_srcB = (BPTR) + (size_t)(bn + (tid >> 1)) * DM_ + (tid & 1) * 32;     \
    const uint32_t a_doff = SWZ128(tid * 128);                                            \
    const uint32_t b_doff = SWZ128((tid >> 1) * 128 + (tid & 1) * 64);                    \
    float acc[4][8][4];                                                                   \
    _Pragma("unroll")                                                                     \
    for (int a = 0; a < 4; a++)                                                           \
        _Pragma("unroll")                                                                 \
        for (int b = 0; b < 8; b++)                                                       \
            _Pragma("unroll")                                                             \
            for (int c = 0; c < 4; c++) acc[a][b][c] = 0.f;                               \
    GEMM_LOADCHUNK(sbase, 0);                                                             \
    CP_COMMIT();                                                                          \
    for (int c = 0; c < NCH4; c++) {                                                      \
        CP_WAIT(0);                                                                       \
        __syncthreads();                                                                  \
        if (c + 1 < NCH4) {                                                               \
            const uint32_t st = sbase + ((c + 1) & 1) * GSTAGE;                           \
            GEMM_LOADCHUNK(st, (c + 1) * 128);                                            \
        }                                                                                 \
        CP_COMMIT();                                                                      \
        const uint32_t stg = sbase + (c & 1) * GSTAGE;                                    \
        _Pragma("unroll")                                                                 \
        for (int ks = 0; ks < 8; ks++) {                                                  \
            const uint32_t abuf = stg + (ks >> 2) * 32768;                                \
            const uint32_t bbuf = stg + 65536 + (ks >> 2) * 16384;                        \
            const int cb = (ks & 3) * 32 + ((lane >> 4) * 16);                            \
            uint32_t bf[4][4];                                                            \
            _Pragma("unroll")                                                             \
            for (int bh = 0; bh < 4; bh++) {                                              \
                const int r = wn0 + bh * 16 + (lane & 15);                                \
                ldmx4(bf[bh][0], bf[bh][1], bf[bh][2], bf[bh][3],                         \
                      bbuf + SWZ128(r * 128 + cb));                                       \
            }                                                                             \
            _Pragma("unroll")                                                             \
            for (int mf = 0; mf < 4; mf++) {                                              \
                uint32_t a[4];                                                            \
                const int r = wm0 + mf * 16 + (lane & 15);                                \
                ldmx4(a[0], a[1], a[2], a[3], abuf + SWZ128(r * 128 + cb));               \
                _Pragma("unroll")                                                         \
                for (int nf = 0; nf < 8; nf++) {                                          \
                    const uint32_t b0 = bf[nf >> 1][(nf & 1)];                            \
                    const uint32_t b1 = bf[nf >> 1][(nf & 1) + 2];                        \
                    mma16816(acc[mf][nf], a, b0, b1);                                     \
                }                                                                         \
            }                                                                             \
        }                                                                                 \
    }                                                                                     \
    const int qr = lane >> 2, qc = (lane & 3) * 2;

// unified QKV: z=0 Q fp16 (skip fully-degenerate blocks), z=1 K fp16 (skip masked), z=2 V fp32
__global__ __launch_bounds__(256, 1) void gemm_qkv(const __half* __restrict__ XH,
                                                   const __half* __restrict__ W1T,
                                                   const float* __restrict__ bq,
                                                   const float* __restrict__ bk,
                                                   const float* __restrict__ bv,
                                                   const int* __restrict__ XLEN,
                                                   __half* __restrict__ Q2h,
                                                   __half* __restrict__ K2h,
                                                   float* __restrict__ Vf) {
    const int z = blockIdx.z;
    {
        const int bm_pre = blockIdx.x * 256;
        const int xl = XLEN[bm_pre >> 11];
        const int tok = bm_pre & 2047;
        if (z == 1 && tok >= xl) return;            // K rows never consumed
        if (z == 0 && tok >= xl + 128) return;      // all queries degenerate -> vmean path
    }
    GEMM_MAINLOOP256(XH, W1T + (size_t)z * DM_ * DM_)
    const float* bias = (z == 0) ? bq : (z == 1) ? bk : bv;
    if (z == 2) {
#pragma unroll
        for (int mf = 0; mf < 4; mf++) {
            const int row = bm + wm0 + mf * 16 + qr;
#pragma unroll
            for (int nf = 0; nf < 8; nf++) {
                const int col = bn + wn0 + nf * 8 + qc;
                const float b0 = bias[col], b1 = bias[col + 1];
                float2 lo, hi;
                lo.x = acc[mf][nf][0] + b0; lo.y = acc[mf][nf][1] + b1;
                hi.x = acc[mf][nf][2] + b0; hi.y = acc[mf][nf][3] + b1;
                *(float2*)(Vf + (size_t)row * 512 + col) = lo;
                *(float2*)(Vf + (size_t)(row + 8) * 512 + col) = hi;
            }
        }
    } else {
        uint32_t* t32 = (uint32_t*)((z == 0) ? Q2h : K2h);
#pragma unroll
        for (int mf = 0; mf < 4; mf++) {
            const int row = bm + wm0 + mf * 16 + qr;
#pragma unroll
            for (int nf = 0; nf < 8; nf++) {
                const int col = bn + wn0 + nf * 8 + qc;
                const float b0 = bias[col], b1 = bias[col + 1];
                const uint32_t idx0 = (uint32_t)row * 256 + (col >> 1);
                const uint32_t idx1 = idx0 + 8 * 256;
                t32[idx0] = pack1(acc[mf][nf][0] + b0, acc[mf][nf][1] + b1);
                t32[idx1] = pack1(acc[mf][nf][2] + b0, acc[mf][nf][3] + b1);
            }
        }
    }
}

// output projection
__global__ __launch_bounds__(256, 1) void gemm_out(const __half* __restrict__ CTXH,
                                                   const __half* __restrict__ WOT,
                                                   const float* __restrict__ bias,
                                                   float* __restrict__ C) {
    GEMM_MAINLOOP256(CTXH, WOT)
#pragma unroll
    for (int mf = 0; mf < 4; mf++) {
        const int row = bm + wm0 + mf * 16 + qr;
#pragma unroll
        for (int nf = 0; nf < 8; nf++) {
            const int col = bn + wn0 + nf * 8 + qc;
            const float b0 = bias[col], b1 = bias[col + 1];
            float2 lo, hi;
            lo.x = acc[mf][nf][0] + b0; lo.y = acc[mf][nf][1] + b1;
            hi.x = acc[mf][nf][2] + b0; hi.y = acc[mf][nf][3] + b1;
            *(float2*)(C + (size_t)row * 512 + col) = lo;
            *(float2*)(C + (size_t)(row + 8) * 512 + col) = hi;
        }
    }
}

// ================= V transpose->fp16 build + vmean partials (store-skip past xl) =================
__global__ __launch_bounds__(256) void v2t_build(const float* __restrict__ V,
                                                 __half* __restrict__ V2T,
                                                 float* __restrict__ part,
                                                 const int* __restrict__ XLEN) {
    __shared__ float tr[64][65];
    const int cx = blockIdx.x;
    const int h = blockIdx.y, b = blockIdx.z;
    const int tid = threadIdx.x;
    const int t0 = cx * 64 - 128;
    const bool inr = (t0 >= 0) && (t0 + 64 <= S_);
    const int xl = XLEN[b];

    if (inr) {
        const int i = tid >> 2, dg = tid & 3;
        const float* vrow = V + ((size_t)(b * S_ + t0 + i)) * DM_ + h * D_ + dg * 16;
#pragma unroll
        for (int u = 0; u < 4; u++) {
            float4 f = *(const float4*)(vrow + u * 4);
            tr[dg * 16 + u * 4 + 0][i] = f.x;
            tr[dg * 16 + u * 4 + 1][i] = f.y;
            tr[dg * 16 + u * 4 + 2][i] = f.z;
            tr[dg * 16 + u * 4 + 3][i] = f.w;
        }
        __syncthreads();
    }

    const int d = tid >> 2, jg = tid & 3;
    uint32_t w[8];
    float s = 0.f;
    if (inr) {
#pragma unroll
        for (int t = 0; t < 8; t++) {
            const float va = tr[d][jg * 16 + 2 * t];
            const float vb = tr[d][jg * 16 + 2 * t + 1];
            w[t] = pack1(va, vb);
            s += va + vb;
        }
    } else {
#pragma unroll
        for (int t = 0; t < 8; t++) w[t] = 0;
    }
    if (t0 < xl + 64) {    // chunk consumed by some attention block
        uint4* dst = (uint4*)((char*)V2T + ((size_t)((b * 8 + h) * 64 + d) * 2304) * 2
                              + (size_t)cx * 128 + jg * 32);
        dst[0] = ((uint4*)w)[0];
        dst[1] = ((uint4*)w)[1];
    }

    s += __shfl_xor_sync(0xffffffffu, s, 1);
    s += __shfl_xor_sync(0xffffffffu, s, 2);
    if (jg == 0)
        part[((size_t)(b * 512 + h * 64 + d)) * 36 + cx] = s;
}

__global__ __launch_bounds__(512) void vmean_final2(const float* __restrict__ part,
                                                    float* __restrict__ vm) {
    const int b = blockIdx.x, t = threadIdx.x;
    const float* p = part + ((size_t)(b * 512 + t)) * 36;
    float s = 0.f;
#pragma unroll
    for (int cx = 0; cx < 36; cx++) s += p[cx];
    vm[b * 512 + t] = s * (1.0f / 2048.0f);
}

// ================= HMMA banded attention (plain fp16, xl-aware skipping) =================
#define AQ2 0
#define AK2 9216
#define AV2 18432
#define ASF 27648
#define AIL 110848
#define ATT_SMEM 111104

__global__ __launch_bounds__(256) void attn_mma2(const __half* __restrict__ Q2h,
                                                 const __half* __restrict__ K2h,
                                                 const __half* __restrict__ V2T,
                                                 const float* __restrict__ VMEAN,
                                                 const int* __restrict__ XLEN,
                                                 __half* __restrict__ CTXH) {
    extern __shared__ char smc[];
    const uint32_t sb = smem_u32(smc);
    float* Ss = (float*)(smc + ASF);
    float* invl = (float*)(smc + AIL);

    const int tid = threadIdx.x;
    const int wid = tid >> 5, lane = tid & 31;
    const int q0 = blockIdx.x * 64;
    const int h = blockIdx.y;
    const int b = blockIdx.z;
    const int xl = XLEN[b];
    const int kbase0 = q0 - 128;

    {
        int blk_lo = kbase0 < 0 ? 0 : kbase0;
        if (blk_lo >= xl) {
            const int row = tid >> 2;
            const int cg = (tid & 3) * 16;
            uint32_t* crow = (uint32_t*)CTXH + (size_t)(b * S_ + q0 + row) * 256
                             + h * 32 + (cg >> 1);
            const float* vm = VMEAN + b * 512 + h * 64 + cg;
#pragma unroll
            for (int k = 0; k < 8; k++) crow[k] = pack1(vm[2 * k], vm[2 * k + 1]);
            return;
        }
    }

    int cmax = (xl - kbase0 + 63) >> 6;
    if (cmax > 5) cmax = 5;

    const int wm = (wid & 3) * 16;
    const int wn = (wid >> 2) * 32;
    const int qr = lane >> 2, qc = (lane & 3) * 2;
    const int lrow = tid >> 2;
    const int lcs = (tid & 3) * 2;

    {
        const char* qsrc = (const char*)Q2h + ((size_t)(b * S_ + q0 + lrow) * DM_ + h * 64) * 2;
#pragma unroll
        for (int u = 0; u < 2; u++)
            cp_async16(sb + AQ2 + lrow * 144 + (lcs + u) * 16, qsrc + (lcs + u) * 16);
    }
#pragma unroll
    for (int c = 0; c < 2; c++) {
        if (c < cmax) {
            const int jabs = kbase0 + c * 64 + lrow;
            const bool valid = (jabs >= 0) && (jabs < S_);
            const char* ksrc = (const char*)K2h + ((size_t)(b * S_ + (valid ? jabs : 0)) * DM_ + h * 64) * 2;
            const uint32_t buf = sb + (c ? AV2 : AK2);
            const uint32_t n = valid ? 16u : 0u;
#pragma unroll
            for (int u = 0; u < 2; u++)
                cp_async16z(buf + lrow * 144 + (lcs + u) * 16, ksrc + (lcs + u) * 16, n);
        }
        CP_COMMIT();
    }

#pragma unroll
    for (int c = 0; c < 5; c++) {
        if (c < 4) { CP_WAIT(1); } else { CP_WAIT(0); }
        __syncthreads();
        if (c < cmax) {
            const uint32_t kbuf = sb + ((c & 1) ? AV2 : AK2);
            const int kb = kbase0 + c * 64;

            float acc[4][4];
#pragma unroll
            for (int nf = 0; nf < 4; nf++)
#pragma unroll
                for (int u = 0; u < 4; u++) acc[nf][u] = 0.f;

#pragma unroll
            for (int ks = 0; ks < 4; ks++) {
                const int cb = ks * 32 + (lane >> 4) * 16;
                uint32_t a[4];
                ldmx4(a[0], a[1], a[2], a[3], sb + AQ2 + (wm + (lane & 15)) * 144 + cb);
                uint32_t bf[2][4];
#pragma unroll
                for (int nh = 0; nh < 2; nh++) {
                    const int r = wn + nh * 16 + (lane & 15);
                    ldmx4(bf[nh][0], bf[nh][1], bf[nh][2], bf[nh][3], kbuf + r * 144 + cb);
                }
#pragma unroll
                for (int nf = 0; nf < 4; nf++) {
                    const uint32_t b0 = bf[nf >> 1][(nf & 1)];
                    const uint32_t b1 = bf[nf >> 1][(nf & 1) + 2];
                    mma16816(acc[nf], a, b0, b1);
                }
            }

            const int i0 = wm + qr, iabs0 = q0 + i0;
            const int i1 = i0 + 8,  iabs1 = iabs0 + 8;
#pragma unroll
            for (int nf = 0; nf < 4; nf++) {
#pragma unroll
                for (int cc = 0; cc < 2; cc++) {
                    const int col = wn + nf * 8 + qc + cc;
                    const int jabs = kb + col;
                    const bool jok = (jabs >= 0) && (jabs < xl);
                    const bool v0 = jok && (jabs - iabs0 <= 128) && (iabs0 - jabs <= 128);
                    const bool v1 = jok && (jabs - iabs1 <= 128) && (iabs1 - jabs <= 128);
                    Ss[i0 * 325 + c * 64 + col] = v0 ? acc[nf][cc] * 0.125f : -1e30f;
                    Ss[i1 * 325 + c * 64 + col] = v1 ? acc[nf][cc + 2] * 0.125f : -1e30f;
                }
            }
        }
        __syncthreads();
        if (c + 2 < cmax) {
            const int jabs = kbase0 + (c + 2) * 64 + lrow;
            const bool valid = (jabs >= 0) && (jabs < S_);
            const char* ksrc = (const char*)K2h + ((size_t)(b * S_ + (valid ? jabs : 0)) * DM_ + h * 64) * 2;
            const uint32_t buf = sb + ((c & 1) ? AV2 : AK2);
            const uint32_t n = valid ? 16u : 0u;
#pragma unroll
            for (int u = 0; u < 2; u++)
                cp_async16z(buf + lrow * 144 + (lcs + u) * 16, ksrc + (lcs + u) * 16, n);
        }
        CP_COMMIT();
    }

#pragma unroll
    for (int c = 0; c < 2; c++) {
        if (c < cmax) {
            const char* vsrc = (const char*)V2T + ((size_t)((b * 8 + h) * 64 + lrow) * 2304) * 2
                               + (size_t)(q0 + c * 64) * 2;
            const uint32_t buf = sb + (c ? AV2 : AK2);
#pragma unroll
            for (int u = 0; u < 2; u++)
                cp_async16(buf + lrow * 144 + (lcs + u) * 16, vsrc + (lcs + u) * 16);
        }
        CP_COMMIT();
    }

    {
        const int limit = cmax * 64;
        for (int rr = 0; rr < 8; rr++) {
            const int i = wid * 8 + rr;
            float* row = Ss + i * 325;
            float vals[10];
            float m = -3.0e38f;
#pragma unroll
            for (int t = 0; t < 10; t++) {
                vals[t] = (lane + 32 * t < limit) ? row[lane + 32 * t] : -1e30f;
                m = fmaxf(m, vals[t]);
            }
#pragma unroll
            for (int o = 16; o; o >>= 1) m = fmaxf(m, __shfl_xor_sync(0xffffffffu, m, o));
            float l = 0.f;
#pragma unroll
            for (int t = 0; t < 10; t++) {
                const float p = __expf(vals[t] - m);
                if (lane + 32 * t < limit) row[lane + 32 * t] = p;
                l += p;
            }
#pragma unroll
            for (int o = 16; o; o >>= 1) l += __shfl_xor_sync(0xffffffffu, l, o);
            if (lane == 0) invl[i] = 1.0f / l;
        }
    }
    __syncthreads();

    float oacc[4][4];
#pragma unroll
    for (int nf = 0; nf < 4; nf++)
#pragma unroll
        for (int u = 0; u < 4; u++) oacc[nf][u] = 0.f;

#pragma unroll
    for (int c = 0; c < 5; c++) {
        if (c < cmax) {
            const int row = tid & 63, jg = tid >> 6;
            const float* srow = Ss + row * 325 + c * 64 + jg * 16;
            uint32_t w[8];
#pragma unroll
            for (int t = 0; t < 8; t++) w[t] = pack1(srow[2 * t], srow[2 * t + 1]);
            uint4* dst = (uint4*)(smc + AQ2 + row * 144 + jg * 32);
            dst[0] = ((uint4*)w)[0];
            dst[1] = ((uint4*)w)[1];
        }
        if (c < 4) { CP_WAIT(1); } else { CP_WAIT(0); }
        __syncthreads();

        if (c < cmax) {
            const uint32_t vbuf = sb + ((c & 1) ? AV2 : AK2);
#pragma unroll
            for (int ks = 0; ks < 4; ks++) {
                const int cb = ks * 32 + (lane >> 4) * 16;
                uint32_t a[4];
                ldmx4(a[0], a[1], a[2], a[3], sb + AQ2 + (wm + (lane & 15)) * 144 + cb);
                uint32_t bf[2][4];
#pragma unroll
                for (int nh = 0; nh < 2; nh++) {
                    const int r = wn + nh * 16 + (lane & 15);
                    ldmx4(bf[nh][0], bf[nh][1], bf[nh][2], bf[nh][3], vbuf + r * 144 + cb);
                }
#pragma unroll
                for (int nf = 0; nf < 4; nf++) {
                    const uint32_t b0 = bf[nf >> 1][(nf & 1)];
                    const uint32_t b1 = bf[nf >> 1][(nf & 1) + 2];
                    mma16816(oacc[nf], a, b0, b1);
                }
            }
        }
        __syncthreads();
        if (c + 2 < cmax) {
            const char* vsrc = (const char*)V2T + ((size_t)((b * 8 + h) * 64 + lrow) * 2304) * 2
                               + (size_t)(q0 + (c + 2) * 64) * 2;
            const uint32_t buf = sb + ((c & 1) ? AV2 : AK2);
#pragma unroll
            for (int u = 0; u < 2; u++)
                cp_async16(buf + lrow * 144 + (lcs + u) * 16, vsrc + (lcs + u) * 16);
        }
        CP_COMMIT();
    }

    {
        const int i0 = wm + qr;
#pragma unroll
        for (int half = 0; half < 2; half++) {
            const int i = i0 + half * 8;
            const int iabs = q0 + i;
            int lo2 = iabs - 128;
            if (lo2 < 0) lo2 = 0;
            const bool deg = (lo2 >= xl);
            const float il = invl[i];
            uint32_t* crow = (uint32_t*)CTXH + (size_t)(b * S_ + iabs) * 256 + h * 32;
            const float* vm = VMEAN + b * 512 + h * 64;
#pragma unroll
            for (int nf = 0; nf < 4; nf++) {
                const int col = wn + nf * 8 + qc;
                const float a = deg ? vm[col]      : oacc[nf][half * 2] * il;
                const float bb = deg ? vm[col + 1] : oacc[nf][half * 2 + 1] * il;
                crow[col >> 1] = pack1(a, bb);
            }
        }
    }
}

// ================= launch =================
extern "C" void kernel_launch(void* const* d_in, const int* in_sizes, int n_in,
                              void* d_out, int out_size) {
    const float* x  = (const float*)d_in[0];
    const float* Wq = (const float*)d_in[1];
    const float* bq = (const float*)d_in[2];
    const float* Wk = (const float*)d_in[3];
    const float* bk = (const float*)d_in[4];
    const float* Wv = (const float*)d_in[5];
    const float* bv = (const float*)d_in[6];
    const float* Wo = (const float*)d_in[7];
    const float* bo = (const float*)d_in[8];
    const int* xlen = (const int*)d_in[9];
    float* out = (float*)d_out;

    float *v, *part, *vmean;
    __half *xh, *q2h, *k2h, *w1t, *v2t;
    cudaGetSymbolAddress((void**)&v, g_v);
    cudaGetSymbolAddress((void**)&part, g_part);
    cudaGetSymbolAddress((void**)&vmean, g_vmean);
    cudaGetSymbolAddress((void**)&xh, g_xh);
    cudaGetSymbolAddress((void**)&q2h, g_q2h);
    cudaGetSymbolAddress((void**)&k2h, g_k2h);
    cudaGetSymbolAddress((void**)&w1t, g_w1t);
    cudaGetSymbolAddress((void**)&v2t, g_v2t);

    cudaFuncSetAttribute(gemm_qkv, cudaFuncAttributeMaxDynamicSharedMemorySize, GEMM_SMEM);
    cudaFuncSetAttribute(gemm_out, cudaFuncAttributeMaxDynamicSharedMemorySize, GEMM_SMEM);
    cudaFuncSetAttribute(attn_mma2, cudaFuncAttributeMaxDynamicSharedMemorySize, ATT_SMEM);

    const dim3 qkv_grid(B_ * S_ / 256, DM_ / 128, 3);
    const dim3 out_grid(B_ * S_ / 256, DM_ / 128);

    split_act1<<<B_ * S_ * 64 / 256, 256>>>(x, xh);
    split_w4<<<dim3(16, 16, 4), dim3(32, 32)>>>(Wq, Wk, Wv, Wo, w1t);

    gemm_qkv<<<qkv_grid, 256, GEMM_SMEM>>>(xh, w1t, bq, bk, bv, xlen, q2h, k2h, v);

    v2t_build<<<dim3(36, H_, B_), 256>>>(v, v2t, part, xlen);
    vmean_final2<<<B_, 512>>>(part, vmean);

    attn_mma2<<<dim3(S_ / 64, H_, B_), 256, ATT_SMEM>>>(q2h, k2h, v2t, vmean, xlen, xh);

    gemm_out<<<out_grid, 256, GEMM_SMEM>>>(xh, w1t + 3 * (size_t)DM_ * DM_, bo, out);
}

// round 15
// speedup vs baseline: 2.9073x; 1.0423x over previous
#include <cuda_runtime.h>
#include <cuda_fp16.h>
#include <cstdint>

#define B_  4
#define S_  2048
#define DM_ 512
#define H_  8
#define D_  64

// ================= helpers =================
__device__ __forceinline__ uint32_t smem_u32(const void* p) {
    uint32_t a;
    asm("{ .reg .u64 t; cvta.to.shared.u64 t, %1; cvt.u32.u64 %0, t; }" : "=r"(a) : "l"(p));
    return a;
}
#define SWZ128(off) ((off) ^ (((off) >> 3) & 0x70))

__device__ __forceinline__ void cp_async16(uint32_t dst, const void* src) {
    asm volatile("cp.async.cg.shared.global [%0], [%1], 16;" :: "r"(dst), "l"(src));
}
__device__ __forceinline__ void cp_async16z(uint32_t dst, const void* src, uint32_t n) {
    asm volatile("cp.async.cg.shared.global [%0], [%1], 16, %2;" :: "r"(dst), "l"(src), "r"(n));
}
#define CP_COMMIT() asm volatile("cp.async.commit_group;" ::: "memory")
#define CP_WAIT(n)  asm volatile("cp.async.wait_group %0;" :: "n"(n) : "memory")

__device__ __forceinline__ void ldmx4(uint32_t& r0, uint32_t& r1, uint32_t& r2, uint32_t& r3,
                                      uint32_t addr) {
    asm volatile("ldmatrix.sync.aligned.m8n8.x4.shared.b16 {%0,%1,%2,%3}, [%4];"
                 : "=r"(r0), "=r"(r1), "=r"(r2), "=r"(r3) : "r"(addr));
}
__device__ __forceinline__ void mma16816(float* c, const uint32_t* a, uint32_t b0, uint32_t b1) {
    asm volatile(
        "mma.sync.aligned.m16n8k16.row.col.f32.f16.f16.f32 "
        "{%0,%1,%2,%3}, {%4,%5,%6,%7}, {%8,%9}, {%0,%1,%2,%3};"
        : "+f"(c[0]), "+f"(c[1]), "+f"(c[2]), "+f"(c[3])
        : "r"(a[0]), "r"(a[1]), "r"(a[2]), "r"(a[3]), "r"(b0), "r"(b1));
}
__device__ __forceinline__ uint32_t pack1(float a, float b) {
    return (uint32_t)__half_as_ushort(__float2half_rn(a)) |
           ((uint32_t)__half_as_ushort(__float2half_rn(b)) << 16);
}

// ================= scratch =================
__device__ float g_part[B_ * DM_ * 16];       // per-(256-token chunk, half) vmean partials
__device__ float g_vmean[B_ * DM_];
__device__ __half g_xh[B_ * S_ * DM_];        // x fp16; later ctx fp16
__device__ __half g_q2h[B_ * S_ * DM_];
__device__ __half g_k2h[B_ * S_ * DM_];
__device__ __half g_w1t[4 * DM_ * DM_];       // Wq,Wk,Wv,Wo fp16 transposed [N,512]
__device__ __half g_v2t[2048 * 2304];         // V dims-major fp16, tokens padded [-128,2176); pads stay zero

// ================= split kernels =================
__global__ __launch_bounds__(256) void split_act1(const float* __restrict__ X,
                                                  __half* __restrict__ XH) {
    const int idx = blockIdx.x * 256 + threadIdx.x;
    const int m = idx >> 6, g = idx & 63;
    const float4 f0 = *(const float4*)(X + (size_t)m * 512 + g * 8);
    const float4 f1 = *(const float4*)(X + (size_t)m * 512 + g * 8 + 4);
    uint32_t p[4];
    p[0] = pack1(f0.x, f0.y); p[1] = pack1(f0.z, f0.w);
    p[2] = pack1(f1.x, f1.y); p[3] = pack1(f1.z, f1.w);
    *(uint4*)(XH + (size_t)m * 512 + g * 8) = *(uint4*)p;
}

__global__ __launch_bounds__(1024) void split_w4(const float* __restrict__ W0,
                                                 const float* __restrict__ W1,
                                                 const float* __restrict__ W2,
                                                 const float* __restrict__ W3,
                                                 __half* __restrict__ W1T) {
    __shared__ float t[32][33];
    const int z = blockIdx.z;
    const float* W = (z == 0) ? W0 : (z == 1) ? W1 : (z == 2) ? W2 : W3;
    const int k0 = blockIdx.y * 32, n0 = blockIdx.x * 32;
    const int tx = threadIdx.x, ty = threadIdx.y;
    t[ty][tx] = W[(size_t)(k0 + ty) * 512 + n0 + tx];
    __syncthreads();
    W1T[(size_t)z * DM_ * DM_ + (size_t)(n0 + ty) * DM_ + (k0 + tx)] =
        __float2half_rn(t[tx][ty]);
}

// ================= 256x128 HMMA GEMM mainloop (BK=128, 2-stage, 4 chunks) =================
#define GSTAGE 98304
#define GEMM_SMEM (2 * GSTAGE + 1024)
#define NCH4 4

#define GEMM_LOADCHUNK(stg, coff)                                                          \
    do {                                                                                   \
        _Pragma("unroll")                                                                  \
        for (int seg = 0; seg < 8; seg++) {                                                \
            cp_async16((stg) + (a_doff ^ (seg * 16)), l_srcA + (coff) + seg * 8);          \
            cp_async16((stg) + 32768 + (a_doff ^ (seg * 16)), l_srcA + (coff) + 64 + seg * 8); \
        }                                                                                  \
        _Pragma("unroll")                                                                  \
        for (int u = 0; u < 4; u++) {                                                      \
            cp_async16((stg) + 65536 + (b_doff ^ (u * 16)), l_srcB + (coff) + u * 8);      \
            cp_async16((stg) + 81920 + (b_doff ^ (u * 16)), l_srcB + (coff) + 64 + u * 8); \
        }                                                                                  \
    } while (0)

#define GEMM_MAINLOOP256(APTR, BPTR)                                                       \
    extern __shared__ char smraw[];                                                       \
    const uint32_t sbase = (smem_u32(smraw) + 1023) & ~1023u;                             \
    const int tid = threadIdx.x;                                                          \
    const int wid = tid >> 5, lane = tid & 31;                                            \
    const int bm = blockIdx.x * 256, bn = blockIdx.y * 128;                               \
    const int wm0 = (wid & 3) * 64, wn0 = (wid >> 2) * 64;                                \
    const __half* l_srcA = (APTR) + (size_t)(bm + tid) * DM_;                             \
    const __half* l_srcB = (BPTR) + (size_t)(bn + (tid >> 1)) * DM_ + (tid & 1) * 32;     \
    const uint32_t a_doff = SWZ128(tid * 128);                                            \
    const uint32_t b_doff = SWZ128((tid >> 1) * 128 + (tid & 1) * 64);                    \
    float acc[4][8][4];                                                                   \
    _Pragma("unroll")                                                                     \
    for (int a = 0; a < 4; a++)                                                           \
        _Pragma("unroll")                                                                 \
        for (int b = 0; b < 8; b++)                                                       \
            _Pragma("unroll")                                                             \
            for (int c = 0; c < 4; c++) acc[a][b][c] = 0.f;                               \
    GEMM_LOADCHUNK(sbase, 0);                                                             \
    CP_COMMIT();                                                                          \
    for (int c = 0; c < NCH4; c++) {                                                      \
        CP_WAIT(0);                                                                       \
        __syncthreads();                                                                  \
        if (c + 1 < NCH4) {                                                               \
            const uint32_t st = sbase + ((c + 1) & 1) * GSTAGE;                           \
            GEMM_LOADCHUNK(st, (c + 1) * 128);                                            \
        }                                                                                 \
        CP_COMMIT();                                                                      \
        const uint32_t stg = sbase + (c & 1) * GSTAGE;                                    \
        _Pragma("unroll")                                                                 \
        for (int ks = 0; ks < 8; ks++) {                                                  \
            const uint32_t abuf = stg + (ks >> 2) * 32768;                                \
            const uint32_t bbuf = stg + 65536 + (ks >> 2) * 16384;                        \
            const int cb = (ks & 3) * 32 + ((lane >> 4) * 16);                            \
            uint32_t bf[4][4];                                                            \
            _Pragma("unroll")                                                             \
            for (int bh = 0; bh < 4; bh++) {                                              \
                const int r = wn0 + bh * 16 + (lane & 15);                                \
                ldmx4(bf[bh][0], bf[bh][1], bf[bh][2], bf[bh][3],                         \
                      bbuf + SWZ128(r * 128 + cb));                                       \
            }                                                                             \
            _Pragma("unroll")                                                             \
            for (int mf = 0; mf < 4; mf++) {                                              \
                uint32_t a[4];                                                            \
                const int r = wm0 + mf * 16 + (lane & 15);                                \
                ldmx4(a[0], a[1], a[2], a[3], abuf + SWZ128(r * 128 + cb));               \
                _Pragma("unroll")                                                         \
                for (int nf = 0; nf < 8; nf++) {                                          \
                    const uint32_t b0 = bf[nf >> 1][(nf & 1)];                            \
                    const uint32_t b1 = bf[nf >> 1][(nf & 1) + 2];                        \
                    mma16816(acc[mf][nf], a, b0, b1);                                     \
                }                                                                         \
            }                                                                             \
        }                                                                                 \
    }                                                                                     \
    const int qr = lane >> 2, qc = (lane & 3) * 2;

// unified QKV: z=0 Q fp16 (skip degenerate blocks), z=1 K fp16 (skip masked),
//              z=2 V -> fused transpose+fp16 V2T + vmean partials (no fp32 V buffer)
__global__ __launch_bounds__(256, 1) void gemm_qkv(const __half* __restrict__ XH,
                                                   const __half* __restrict__ W1T,
                                                   const float* __restrict__ bq,
                                                   const float* __restrict__ bk,
                                                   const float* __restrict__ bv,
                                                   const int* __restrict__ XLEN,
                                                   __half* __restrict__ Q2h,
                                                   __half* __restrict__ K2h,
                                                   __half* __restrict__ V2T,
                                                   float* __restrict__ part) {
    const int z = blockIdx.z;
    {
        const int bm_pre = blockIdx.x * 256;
        const int xl = XLEN[bm_pre >> 11];
        const int tok = bm_pre & 2047;
        if (z == 1 && tok >= xl) return;
        if (z == 0 && tok >= xl + 128) return;
    }
    GEMM_MAINLOOP256(XH, W1T + (size_t)z * DM_ * DM_)
    const float* bias = (z == 0) ? bq : (z == 1) ? bk : bv;
    if (z == 2) {
        // ---- fused: stage fp16-transposed V tile in smem ----
        __syncthreads();   // all warps done reading mainloop smem
        __half* hsm = (__half*)(smraw + (sbase - smem_u32(smraw)));
#pragma unroll
        for (int mf = 0; mf < 4; mf++) {
            const int row0 = wm0 + mf * 16 + qr;
#pragma unroll
            for (int nf = 0; nf < 8; nf++) {
                const int col = wn0 + nf * 8 + qc;
                const float b0 = bias[bn + col], b1 = bias[bn + col + 1];
                hsm[col * 264 + row0]           = __float2half_rn(acc[mf][nf][0] + b0);
                hsm[(col + 1) * 264 + row0]     = __float2half_rn(acc[mf][nf][1] + b1);
                hsm[col * 264 + row0 + 8]       = __float2half_rn(acc[mf][nf][2] + b0);
                hsm[(col + 1) * 264 + row0 + 8] = __float2half_rn(acc[mf][nf][3] + b1);
            }
        }
        __syncthreads();
        // ---- write V2T (coalesced 256B runs) + vmean partials ----
        const int tok0 = bm & 2047;
        const int bb = bm >> 11;
        const int chunk = tok0 >> 8;
        const int col = tid >> 1, seg = (tid & 1) * 128;
        const __half* src = hsm + col * 264 + seg;
        float s = 0.f;
#pragma unroll
        for (int k2 = 0; k2 < 128; k2++) s += __half2float(src[k2]);
        const int colg = bn + col;
        part[((size_t)(bb * 512 + colg)) * 16 + chunk * 2 + (tid & 1)] = s;
        if (tok0 < XLEN[bb] + 64) {
            __half* dst = V2T + ((size_t)((bb * 8 + (colg >> 6)) * 64 + (colg & 63))) * 2304
                          + 128 + tok0 + seg;
#pragma unroll
            for (int u = 0; u < 16; u++)
                ((uint4*)dst)[u] = ((const uint4*)src)[u];
        }
    } else {
        uint32_t* t32 = (uint32_t*)((z == 0) ? Q2h : K2h);
#pragma unroll
        for (int mf = 0; mf < 4; mf++) {
            const int row = bm + wm0 + mf * 16 + qr;
#pragma unroll
            for (int nf = 0; nf < 8; nf++) {
                const int col = bn + wn0 + nf * 8 + qc;
                const float b0 = bias[col], b1 = bias[col + 1];
                const uint32_t idx0 = (uint32_t)row * 256 + (col >> 1);
                const uint32_t idx1 = idx0 + 8 * 256;
                t32[idx0] = pack1(acc[mf][nf][0] + b0, acc[mf][nf][1] + b1);
                t32[idx1] = pack1(acc[mf][nf][2] + b0, acc[mf][nf][3] + b1);
            }
        }
    }
}

// output projection
__global__ __launch_bounds__(256, 1) void gemm_out(const __half* __restrict__ CTXH,
                                                   const __half* __restrict__ WOT,
                                                   const float* __restrict__ bias,
                                                   float* __restrict__ C) {
    GEMM_MAINLOOP256(CTXH, WOT)
#pragma unroll
    for (int mf = 0; mf < 4; mf++) {
        const int row = bm + wm0 + mf * 16 + qr;
#pragma unroll
        for (int nf = 0; nf < 8; nf++) {
            const int col = bn + wn0 + nf * 8 + qc;
            const float b0 = bias[col], b1 = bias[col + 1];
            float2 lo, hi;
            lo.x = acc[mf][nf][0] + b0; lo.y = acc[mf][nf][1] + b1;
            hi.x = acc[mf][nf][2] + b0; hi.y = acc[mf][nf][3] + b1;
            *(float2*)(C + (size_t)row * 512 + col) = lo;
            *(float2*)(C + (size_t)(row + 8) * 512 + col) = hi;
        }
    }
}

__global__ __launch_bounds__(512) void vmean_final2(const float* __restrict__ part,
                                                    float* __restrict__ vm) {
    const int b = blockIdx.x, t = threadIdx.x;
    const float* p = part + ((size_t)(b * 512 + t)) * 16;
    float s = 0.f;
#pragma unroll
    for (int cx = 0; cx < 16; cx++) s += p[cx];
    vm[b * 512 + t] = s * (1.0f / 2048.0f);
}

// ================= HMMA banded attention (plain fp16, xl-aware skipping) =================
#define AQ2 0
#define AK2 9216
#define AV2 18432
#define ASF 27648
#define AIL 110848
#define ATT_SMEM 111104

__global__ __launch_bounds__(256) void attn_mma2(const __half* __restrict__ Q2h,
                                                 const __half* __restrict__ K2h,
                                                 const __half* __restrict__ V2T,
                                                 const float* __restrict__ VMEAN,
                                                 const int* __restrict__ XLEN,
                                                 __half* __restrict__ CTXH) {
    extern __shared__ char smc[];
    const uint32_t sb = smem_u32(smc);
    float* Ss = (float*)(smc + ASF);
    float* invl = (float*)(smc + AIL);

    const int tid = threadIdx.x;
    const int wid = tid >> 5, lane = tid & 31;
    const int q0 = blockIdx.x * 64;
    const int h = blockIdx.y;
    const int b = blockIdx.z;
    const int xl = XLEN[b];
    const int kbase0 = q0 - 128;

    {
        int blk_lo = kbase0 < 0 ? 0 : kbase0;
        if (blk_lo >= xl) {
            const int row = tid >> 2;
            const int cg = (tid & 3) * 16;
            uint32_t* crow = (uint32_t*)CTXH + (size_t)(b * S_ + q0 + row) * 256
                             + h * 32 + (cg >> 1);
            const float* vm = VMEAN + b * 512 + h * 64 + cg;
#pragma unroll
            for (int k = 0; k < 8; k++) crow[k] = pack1(vm[2 * k], vm[2 * k + 1]);
            return;
        }
    }

    int cmax = (xl - kbase0 + 63) >> 6;
    if (cmax > 5) cmax = 5;

    const int wm = (wid & 3) * 16;
    const int wn = (wid >> 2) * 32;
    const int qr = lane >> 2, qc = (lane & 3) * 2;
    const int lrow = tid >> 2;
    const int lcs = (tid & 3) * 2;

    {
        const char* qsrc = (const char*)Q2h + ((size_t)(b * S_ + q0 + lrow) * DM_ + h * 64) * 2;
#pragma unroll
        for (int u = 0; u < 2; u++)
            cp_async16(sb + AQ2 + lrow * 144 + (lcs + u) * 16, qsrc + (lcs + u) * 16);
    }
#pragma unroll
    for (int c = 0; c < 2; c++) {
        if (c < cmax) {
            const int jabs = kbase0 + c * 64 + lrow;
            const bool valid = (jabs >= 0) && (jabs < S_);
            const char* ksrc = (const char*)K2h + ((size_t)(b * S_ + (valid ? jabs : 0)) * DM_ + h * 64) * 2;
            const uint32_t buf = sb + (c ? AV2 : AK2);
            const uint32_t n = valid ? 16u : 0u;
#pragma unroll
            for (int u = 0; u < 2; u++)
                cp_async16z(buf + lrow * 144 + (lcs + u) * 16, ksrc + (lcs + u) * 16, n);
        }
        CP_COMMIT();
    }

#pragma unroll
    for (int c = 0; c < 5; c++) {
        if (c < 4) { CP_WAIT(1); } else { CP_WAIT(0); }
        __syncthreads();
        if (c < cmax) {
            const uint32_t kbuf = sb + ((c & 1) ? AV2 : AK2);
            const int kb = kbase0 + c * 64;

            float acc[4][4];
#pragma unroll
            for (int nf = 0; nf < 4; nf++)
#pragma unroll
                for (int u = 0; u < 4; u++) acc[nf][u] = 0.f;

#pragma unroll
            for (int ks = 0; ks < 4; ks++) {
                const int cb = ks * 32 + (lane >> 4) * 16;
                uint32_t a[4];
                ldmx4(a[0], a[1], a[2], a[3], sb + AQ2 + (wm + (lane & 15)) * 144 + cb);
                uint32_t bf[2][4];
#pragma unroll
                for (int nh = 0; nh < 2; nh++) {
                    const int r = wn + nh * 16 + (lane & 15);
                    ldmx4(bf[nh][0], bf[nh][1], bf[nh][2], bf[nh][3], kbuf + r * 144 + cb);
                }
#pragma unroll
                for (int nf = 0; nf < 4; nf++) {
                    const uint32_t b0 = bf[nf >> 1][(nf & 1)];
                    const uint32_t b1 = bf[nf >> 1][(nf & 1) + 2];
                    mma16816(acc[nf], a, b0, b1);
                }
            }

            const int i0 = wm + qr, iabs0 = q0 + i0;
            const int i1 = i0 + 8,  iabs1 = iabs0 + 8;
#pragma unroll
            for (int nf = 0; nf < 4; nf++) {
#pragma unroll
                for (int cc = 0; cc < 2; cc++) {
                    const int col = wn + nf * 8 + qc + cc;
                    const int jabs = kb + col;
                    const bool jok = (jabs >= 0) && (jabs < xl);
                    const bool v0 = jok && (jabs - iabs0 <= 128) && (iabs0 - jabs <= 128);
                    const bool v1 = jok && (jabs - iabs1 <= 128) && (iabs1 - jabs <= 128);
                    Ss[i0 * 325 + c * 64 + col] = v0 ? acc[nf][cc] * 0.125f : -1e30f;
                    Ss[i1 * 325 + c * 64 + col] = v1 ? acc[nf][cc + 2] * 0.125f : -1e30f;
                }
            }
        }
        __syncthreads();
        if (c + 2 < cmax) {
            const int jabs = kbase0 + (c + 2) * 64 + lrow;
            const bool valid = (jabs >= 0) && (jabs < S_);
            const char* ksrc = (const char*)K2h + ((size_t)(b * S_ + (valid ? jabs : 0)) * DM_ + h * 64) * 2;
            const uint32_t buf = sb + ((c & 1) ? AV2 : AK2);
            const uint32_t n = valid ? 16u : 0u;
#pragma unroll
            for (int u = 0; u < 2; u++)
                cp_async16z(buf + lrow * 144 + (lcs + u) * 16, ksrc + (lcs + u) * 16, n);
        }
        CP_COMMIT();
    }

#pragma unroll
    for (int c = 0; c < 2; c++) {
        if (c < cmax) {
            const char* vsrc = (const char*)V2T + ((size_t)((b * 8 + h) * 64 + lrow) * 2304) * 2
                               + (size_t)(q0 + c * 64) * 2;
            const uint32_t buf = sb + (c ? AV2 : AK2);
#pragma unroll
            for (int u = 0; u < 2; u++)
                cp_async16(buf + lrow * 144 + (lcs + u) * 16, vsrc + (lcs + u) * 16);
        }
        CP_COMMIT();
    }

    {
        const int limit = cmax * 64;
        for (int rr = 0; rr < 8; rr++) {
            const int i = wid * 8 + rr;
            float* row = Ss + i * 325;
            float vals[10];
            float m = -3.0e38f;
#pragma unroll
            for (int t = 0; t < 10; t++) {
                vals[t] = (lane + 32 * t < limit) ? row[lane + 32 * t] : -1e30f;
                m = fmaxf(m, vals[t]);
            }
#pragma unroll
            for (int o = 16; o; o >>= 1) m = fmaxf(m, __shfl_xor_sync(0xffffffffu, m, o));
            float l = 0.f;
#pragma unroll
            for (int t = 0; t < 10; t++) {
                const float p = __expf(vals[t] - m);
                if (lane + 32 * t < limit) row[lane + 32 * t] = p;
                l += p;
            }
#pragma unroll
            for (int o = 16; o; o >>= 1) l += __shfl_xor_sync(0xffffffffu, l, o);
            if (lane == 0) invl[i] = 1.0f / l;
        }
    }
    __syncthreads();

    float oacc[4][4];
#pragma unroll
    for (int nf = 0; nf < 4; nf++)
#pragma unroll
        for (int u = 0; u < 4; u++) oacc[nf][u] = 0.f;

#pragma unroll
    for (int c = 0; c < 5; c++) {
        if (c < cmax) {
            const int row = tid & 63, jg = tid >> 6;
            const float* srow = Ss + row * 325 + c * 64 + jg * 16;
            uint32_t w[8];
#pragma unroll
            for (int t = 0; t < 8; t++) w[t] = pack1(srow[2 * t], srow[2 * t + 1]);
            uint4* dst = (uint4*)(smc + AQ2 + row * 144 + jg * 32);
            dst[0] = ((uint4*)w)[0];
            dst[1] = ((uint4*)w)[1];
        }
        if (c < 4) { CP_WAIT(1); } else { CP_WAIT(0); }
        __syncthreads();

        if (c < cmax) {
            const uint32_t vbuf = sb + ((c & 1) ? AV2 : AK2);
#pragma unroll
            for (int ks = 0; ks < 4; ks++) {
                const int cb = ks * 32 + (lane >> 4) * 16;
                uint32_t a[4];
                ldmx4(a[0], a[1], a[2], a[3], sb + AQ2 + (wm + (lane & 15)) * 144 + cb);
                uint32_t bf[2][4];
#pragma unroll
                for (int nh = 0; nh < 2; nh++) {
                    const int r = wn + nh * 16 + (lane & 15);
                    ldmx4(bf[nh][0], bf[nh][1], bf[nh][2], bf[nh][3], vbuf + r * 144 + cb);
                }
#pragma unroll
                for (int nf = 0; nf < 4; nf++) {
                    const uint32_t b0 = bf[nf >> 1][(nf & 1)];
                    const uint32_t b1 = bf[nf >> 1][(nf & 1) + 2];
                    mma16816(oacc[nf], a, b0, b1);
                }
            }
        }
        __syncthreads();
        if (c + 2 < cmax) {
            const char* vsrc = (const char*)V2T + ((size_t)((b * 8 + h) * 64 + lrow) * 2304) * 2
                               + (size_t)(q0 + (c + 2) * 64) * 2;
            const uint32_t buf = sb + ((c & 1) ? AV2 : AK2);
#pragma unroll
            for (int u = 0; u < 2; u++)
                cp_async16(buf + lrow * 144 + (lcs + u) * 16, vsrc + (lcs + u) * 16);
        }
        CP_COMMIT();
    }

    {
        const int i0 = wm + qr;
#pragma unroll
        for (int half = 0; half < 2; half++) {
            const int i = i0 + half * 8;
            const int iabs = q0 + i;
            int lo2 = iabs - 128;
            if (lo2 < 0) lo2 = 0;
            const bool deg = (lo2 >= xl);
            const float il = invl[i];
            uint32_t* crow = (uint32_t*)CTXH + (size_t)(b * S_ + iabs) * 256 + h * 32;
            const float* vm = VMEAN + b * 512 + h * 64;
#pragma unroll
            for (int nf = 0; nf < 4; nf++) {
                const int col = wn + nf * 8 + qc;
                const float a = deg ? vm[col]      : oacc[nf][half * 2] * il;
                const float bb = deg ? vm[col + 1] : oacc[nf][half * 2 + 1] * il;
                crow[col >> 1] = pack1(a, bb);
            }
        }
    }
}

// ================= launch =================
extern "C" void kernel_launch(void* const* d_in, const int* in_sizes, int n_in,
                              void* d_out, int out_size) {
    const float* x  = (const float*)d_in[0];
    const float* Wq = (const float*)d_in[1];
    const float* bq = (const float*)d_in[2];
    const float* Wk = (const float*)d_in[3];
    const float* bk = (const float*)d_in[4];
    const float* Wv = (const float*)d_in[5];
    const float* bv = (const float*)d_in[6];
    const float* Wo = (const float*)d_in[7];
    const float* bo = (const float*)d_in[8];
    const int* xlen = (const int*)d_in[9];
    float* out = (float*)d_out;

    float *part, *vmean;
    __half *xh, *q2h, *k2h, *w1t, *v2t;
    cudaGetSymbolAddress((void**)&part, g_part);
    cudaGetSymbolAddress((void**)&vmean, g_vmean);
    cudaGetSymbolAddress((void**)&xh, g_xh);
    cudaGetSymbolAddress((void**)&q2h, g_q2h);
    cudaGetSymbolAddress((void**)&k2h, g_k2h);
    cudaGetSymbolAddress((void**)&w1t, g_w1t);
    cudaGetSymbolAddress((void**)&v2t, g_v2t);

    cudaFuncSetAttribute(gemm_qkv, cudaFuncAttributeMaxDynamicSharedMemorySize, GEMM_SMEM);
    cudaFuncSetAttribute(gemm_out, cudaFuncAttributeMaxDynamicSharedMemorySize, GEMM_SMEM);
    cudaFuncSetAttribute(attn_mma2, cudaFuncAttributeMaxDynamicSharedMemorySize, ATT_SMEM);

    const dim3 qkv_grid(B_ * S_ / 256, DM_ / 128, 3);
    const dim3 out_grid(B_ * S_ / 256, DM_ / 128);

    split_act1<<<B_ * S_ * 64 / 256, 256>>>(x, xh);
    split_w4<<<dim3(16, 16, 4), dim3(32, 32)>>>(Wq, Wk, Wv, Wo, w1t);

    gemm_qkv<<<qkv_grid, 256, GEMM_SMEM>>>(xh, w1t, bq, bk, bv, xlen, q2h, k2h, v2t, part);

    vmean_final2<<<B_, 512>>>(part, vmean);

    attn_mma2<<<dim3(S_ / 64, H_, B_), 256, ATT_SMEM>>>(q2h, k2h, v2t, vmean, xlen, xh);

    gemm_out<<<out_grid, 256, GEMM_SMEM>>>(xh, w1t + 3 * (size_t)DM_ * DM_, bo, out);
}

// round 16
// speedup vs baseline: 3.1134x; 1.0709x over previous
#include <cuda_runtime.h>
#include <cuda_fp16.h>
#include <cstdint>

#define B_  4
#define S_  2048
#define DM_ 512
#define H_  8
#define D_  64

// ================= helpers =================
__device__ __forceinline__ uint32_t smem_u32(const void* p) {
    uint32_t a;
    asm("{ .reg .u64 t; cvta.to.shared.u64 t, %1; cvt.u32.u64 %0, t; }" : "=r"(a) : "l"(p));
    return a;
}
#define SWZ128(off) ((off) ^ (((off) >> 3) & 0x70))

__device__ __forceinline__ void cp_async16(uint32_t dst, const void* src) {
    asm volatile("cp.async.cg.shared.global [%0], [%1], 16;" :: "r"(dst), "l"(src));
}
__device__ __forceinline__ void cp_async16z(uint32_t dst, const void* src, uint32_t n) {
    asm volatile("cp.async.cg.shared.global [%0], [%1], 16, %2;" :: "r"(dst), "l"(src), "r"(n));
}
#define CP_COMMIT() asm volatile("cp.async.commit_group;" ::: "memory")
#define CP_WAIT(n)  asm volatile("cp.async.wait_group %0;" :: "n"(n) : "memory")

__device__ __forceinline__ void ldmx4(uint32_t& r0, uint32_t& r1, uint32_t& r2, uint32_t& r3,
                                      uint32_t addr) {
    asm volatile("ldmatrix.sync.aligned.m8n8.x4.shared.b16 {%0,%1,%2,%3}, [%4];"
                 : "=r"(r0), "=r"(r1), "=r"(r2), "=r"(r3) : "r"(addr));
}
__device__ __forceinline__ void mma16816(float* c, const uint32_t* a, uint32_t b0, uint32_t b1) {
    asm volatile(
        "mma.sync.aligned.m16n8k16.row.col.f32.f16.f16.f32 "
        "{%0,%1,%2,%3}, {%4,%5,%6,%7}, {%8,%9}, {%0,%1,%2,%3};"
        : "+f"(c[0]), "+f"(c[1]), "+f"(c[2]), "+f"(c[3])
        : "r"(a[0]), "r"(a[1]), "r"(a[2]), "r"(a[3]), "r"(b0), "r"(b1));
}
__device__ __forceinline__ uint32_t pack1(float a, float b) {
    return (uint32_t)__half_as_ushort(__float2half_rn(a)) |
           ((uint32_t)__half_as_ushort(__float2half_rn(b)) << 16);
}

// ================= scratch =================
__device__ float g_part[B_ * DM_ * 16];       // per-(256-token chunk, half) vmean partials
__device__ __half g_xh[B_ * S_ * DM_];        // x fp16; later ctx fp16
__device__ __half g_q2h[B_ * S_ * DM_];
__device__ __half g_k2h[B_ * S_ * DM_];
__device__ __half g_w1t[4 * DM_ * DM_];       // Wq,Wk,Wv,Wo fp16 transposed [N,512]
__device__ __half g_v2t[2048 * 2304];         // V dims-major fp16, tokens padded [-128,2176); pads stay zero

// ================= combined prep: act->fp16 + weight transpose->fp16 =================
// blocks [0,2048): act conversion; blocks [2048,3072): weight 32x32 transpose tiles
__global__ __launch_bounds__(256) void prep(const float* __restrict__ X,
                                            const float* __restrict__ W0,
                                            const float* __restrict__ W1,
                                            const float* __restrict__ W2,
                                            const float* __restrict__ W3,
                                            __half* __restrict__ XH,
                                            __half* __restrict__ W1T) {
    const int bid = blockIdx.x;
    const int tid = threadIdx.x;
    if (bid < 2048) {
        const int idx = bid * 256 + tid;
        const int m = idx >> 6, g = idx & 63;
        const float4 f0 = *(const float4*)(X + (size_t)m * 512 + g * 8);
        const float4 f1 = *(const float4*)(X + (size_t)m * 512 + g * 8 + 4);
        uint32_t p[4];
        p[0] = pack1(f0.x, f0.y); p[1] = pack1(f0.z, f0.w);
        p[2] = pack1(f1.x, f1.y); p[3] = pack1(f1.z, f1.w);
        *(uint4*)(XH + (size_t)m * 512 + g * 8) = *(uint4*)p;
    } else {
        __shared__ float t[32][33];
        const int wb = bid - 2048;             // 0..1023
        const int z = wb >> 8;                 // weight index
        const int tl = wb & 255;
        const int n0 = (tl & 15) * 32, k0 = (tl >> 4) * 32;
        const float* W = (z == 0) ? W0 : (z == 1) ? W1 : (z == 2) ? W2 : W3;
        const int tx = tid & 31, ty8 = tid >> 5;
#pragma unroll
        for (int r = 0; r < 4; r++)
            t[ty8 + 8 * r][tx] = W[(size_t)(k0 + ty8 + 8 * r) * 512 + n0 + tx];
        __syncthreads();
#pragma unroll
        for (int r = 0; r < 4; r++)
            W1T[(size_t)z * DM_ * DM_ + (size_t)(n0 + ty8 + 8 * r) * DM_ + (k0 + tx)] =
                __float2half_rn(t[tx][ty8 + 8 * r]);
    }
}

// ================= 256x128 HMMA GEMM mainloop (BK=128, 2-stage, 4 chunks) =================
#define GSTAGE 98304
#define GEMM_SMEM (2 * GSTAGE + 1024)
#define NCH4 4

#define GEMM_LOADCHUNK(stg, coff)                                                          \
    do {                                                                                   \
        _Pragma("unroll")                                                                  \
        for (int seg = 0; seg < 8; seg++) {                                                \
            cp_async16((stg) + (a_doff ^ (seg * 16)), l_srcA + (coff) + seg * 8);          \
            cp_async16((stg) + 32768 + (a_doff ^ (seg * 16)), l_srcA + (coff) + 64 + seg * 8); \
        }                                                                                  \
        _Pragma("unroll")                                                                  \
        for (int u = 0; u < 4; u++) {                                                      \
            cp_async16((stg) + 65536 + (b_doff ^ (u * 16)), l_srcB + (coff) + u * 8);      \
            cp_async16((stg) + 81920 + (b_doff ^ (u * 16)), l_srcB + (coff) + 64 + u * 8); \
        }                                                                                  \
    } while (0)

#define GEMM_MAINLOOP256(APTR, BPTR)                                                       \
    extern __shared__ char smraw[];                                                       \
    const uint32_t sbase = (smem_u32(smraw) + 1023) & ~1023u;                             \
    const int tid = threadIdx.x;                                                          \
    const int wid = tid >> 5, lane = tid & 31;                                            \
    const int bm = blockIdx.x * 256, bn = blockIdx.y * 128;                               \
    const int wm0 = (wid & 3) * 64, wn0 = (wid >> 2) * 64;                                \
    const __half* l_srcA = (APTR) + (size_t)(bm + tid) * DM_;                             \
    const __half* l_srcB = (BPTR) + (size_t)(bn + (tid >> 1)) * DM_ + (tid & 1) * 32;     \
    const uint32_t a_doff = SWZ128(tid * 128);                                            \
    const uint32_t b_doff = SWZ128((tid >> 1) * 128 + (tid & 1) * 64);                    \
    float acc[4][8][4];                                                                   \
    _Pragma("unroll")                                                                     \
    for (int a = 0; a < 4; a++)                                                           \
        _Pragma("unroll")                                                                 \
        for (int b = 0; b < 8; b++)                                                       \
            _Pragma("unroll")                                                             \
            for (int c = 0; c < 4; c++) acc[a][b][c] = 0.f;                               \
    GEMM_LOADCHUNK(sbase, 0);                                                             \
    CP_COMMIT();                                                                          \
    for (int c = 0; c < NCH4; c++) {                                                      \
        CP_WAIT(0);                                                                       \
        __syncthreads();                                                                  \
        if (c + 1 < NCH4) {                                                               \
            const uint32_t st = sbase + ((c + 1) & 1) * GSTAGE;                           \
            GEMM_LOADCHUNK(st, (c + 1) * 128);                                            \
        }                                                                                 \
        CP_COMMIT();                                                                      \
        const uint32_t stg = sbase + (c & 1) * GSTAGE;                                    \
        _Pragma("unroll")                                                                 \
        for (int ks = 0; ks < 8; ks++) {                                                  \
            const uint32_t abuf = stg + (ks >> 2) * 32768;                                \
            const uint32_t bbuf = stg + 65536 + (ks >> 2) * 16384;                        \
            const int cb = (ks & 3) * 32 + ((lane >> 4) * 16);                            \
            uint32_t bf[4][4];                                                            \
            _Pragma("unroll")                                                             \
            for (int bh = 0; bh < 4; bh++) {                                              \
                const int r = wn0 + bh * 16 + (lane & 15);                                \
                ldmx4(bf[bh][0], bf[bh][1], bf[bh][2], bf[bh][3],                         \
                      bbuf + SWZ128(r * 128 + cb));                                       \
            }                                                                             \
            _Pragma("unroll")                                                             \
            for (int mf = 0; mf < 4; mf++) {                                              \
                uint32_t a[4];                                                            \
                const int r = wm0 + mf * 16 + (lane & 15);                                \
                ldmx4(a[0], a[1], a[2], a[3], abuf + SWZ128(r * 128 + cb));               \
                _Pragma("unroll")                                                         \
                for (int nf = 0; nf < 8; nf++) {                                          \
                    const uint32_t b0 = bf[nf >> 1][(nf & 1)];                            \
                    const uint32_t b1 = bf[nf >> 1][(nf & 1) + 2];                        \
                    mma16816(acc[mf][nf], a, b0, b1);                                     \
                }                                                                         \
            }                                                                             \
        }                                                                                 \
    }                                                                                     \
    const int qr = lane >> 2, qc = (lane & 3) * 2;

// unified QKV: z=0 Q fp16 (skip degenerate blocks), z=1 K fp16 (skip masked),
//              z=2 V -> fused transpose+fp16 V2T + vmean partials
__global__ __launch_bounds__(256, 1) void gemm_qkv(const __half* __restrict__ XH,
                                                   const __half* __restrict__ W1T,
                                                   const float* __restrict__ bq,
                                                   const float* __restrict__ bk,
                                                   const float* __restrict__ bv,
                                                   const int* __restrict__ XLEN,
                                                   __half* __restrict__ Q2h,
                                                   __half* __restrict__ K2h,
                                                   __half* __restrict__ V2T,
                                                   float* __restrict__ part) {
    const int z = blockIdx.z;
    {
        const int bm_pre = blockIdx.x * 256;
        const int xl = XLEN[bm_pre >> 11];
        const int tok = bm_pre & 2047;
        if (z == 1 && tok >= xl) return;
        if (z == 0 && tok >= xl + 128) return;
    }
    GEMM_MAINLOOP256(XH, W1T + (size_t)z * DM_ * DM_)
    const float* bias = (z == 0) ? bq : (z == 1) ? bk : bv;
    if (z == 2) {
        __syncthreads();
        __half* hsm = (__half*)(smraw + (sbase - smem_u32(smraw)));
#pragma unroll
        for (int mf = 0; mf < 4; mf++) {
            const int row0 = wm0 + mf * 16 + qr;
#pragma unroll
            for (int nf = 0; nf < 8; nf++) {
                const int col = wn0 + nf * 8 + qc;
                const float b0 = bias[bn + col], b1 = bias[bn + col + 1];
                hsm[col * 264 + row0]           = __float2half_rn(acc[mf][nf][0] + b0);
                hsm[(col + 1) * 264 + row0]     = __float2half_rn(acc[mf][nf][1] + b1);
                hsm[col * 264 + row0 + 8]       = __float2half_rn(acc[mf][nf][2] + b0);
                hsm[(col + 1) * 264 + row0 + 8] = __float2half_rn(acc[mf][nf][3] + b1);
            }
        }
        __syncthreads();
        const int tok0 = bm & 2047;
        const int bb = bm >> 11;
        const int chunk = tok0 >> 8;
        const int col = tid >> 1, seg = (tid & 1) * 128;
        const __half* src = hsm + col * 264 + seg;
        float s = 0.f;
#pragma unroll
        for (int k2 = 0; k2 < 128; k2++) s += __half2float(src[k2]);
        const int colg = bn + col;
        part[((size_t)(bb * 512 + colg)) * 16 + chunk * 2 + (tid & 1)] = s;
        if (tok0 < XLEN[bb] + 64) {
            __half* dst = V2T + ((size_t)((bb * 8 + (colg >> 6)) * 64 + (colg & 63))) * 2304
                          + 128 + tok0 + seg;
#pragma unroll
            for (int u = 0; u < 16; u++)
                ((uint4*)dst)[u] = ((const uint4*)src)[u];
        }
    } else {
        uint32_t* t32 = (uint32_t*)((z == 0) ? Q2h : K2h);
#pragma unroll
        for (int mf = 0; mf < 4; mf++) {
            const int row = bm + wm0 + mf * 16 + qr;
#pragma unroll
            for (int nf = 0; nf < 8; nf++) {
                const int col = bn + wn0 + nf * 8 + qc;
                const float b0 = bias[col], b1 = bias[col + 1];
                const uint32_t idx0 = (uint32_t)row * 256 + (col >> 1);
                const uint32_t idx1 = idx0 + 8 * 256;
                t32[idx0] = pack1(acc[mf][nf][0] + b0, acc[mf][nf][1] + b1);
                t32[idx1] = pack1(acc[mf][nf][2] + b0, acc[mf][nf][3] + b1);
            }
        }
    }
}

// output projection
__global__ __launch_bounds__(256, 1) void gemm_out(const __half* __restrict__ CTXH,
                                                   const __half* __restrict__ WOT,
                                                   const float* __restrict__ bias,
                                                   float* __restrict__ C) {
    GEMM_MAINLOOP256(CTXH, WOT)
#pragma unroll
    for (int mf = 0; mf < 4; mf++) {
        const int row = bm + wm0 + mf * 16 + qr;
#pragma unroll
        for (int nf = 0; nf < 8; nf++) {
            const int col = bn + wn0 + nf * 8 + qc;
            const float b0 = bias[col], b1 = bias[col + 1];
            float2 lo, hi;
            lo.x = acc[mf][nf][0] + b0; lo.y = acc[mf][nf][1] + b1;
            hi.x = acc[mf][nf][2] + b0; hi.y = acc[mf][nf][3] + b1;
            *(float2*)(C + (size_t)row * 512 + col) = lo;
            *(float2*)(C + (size_t)(row + 8) * 512 + col) = hi;
        }
    }
}

// ================= HMMA banded attention (inline vmean, xl-aware skipping) =================
#define AQ2 0
#define AK2 9216
#define AV2 18432
#define ASF 27648
#define AIL 110848
#define AVM 111104
#define ATT_SMEM 111360

__global__ __launch_bounds__(256) void attn_mma2(const __half* __restrict__ Q2h,
                                                 const __half* __restrict__ K2h,
                                                 const __half* __restrict__ V2T,
                                                 const float* __restrict__ part,
                                                 const int* __restrict__ XLEN,
                                                 __half* __restrict__ CTXH) {
    extern __shared__ char smc[];
    const uint32_t sb = smem_u32(smc);
    float* Ss = (float*)(smc + ASF);
    float* invl = (float*)(smc + AIL);
    float* vm_sm = (float*)(smc + AVM);

    const int tid = threadIdx.x;
    const int wid = tid >> 5, lane = tid & 31;
    const int q0 = blockIdx.x * 64;
    const int h = blockIdx.y;
    const int b = blockIdx.z;
    const int xl = XLEN[b];
    const int kbase0 = q0 - 128;

    // does any row of this block take the vmean path?
    int maxlo = q0 + 63 - 128; if (maxlo < 0) maxlo = 0;
    const bool need_vm = (maxlo >= xl);
    if (need_vm) {
        const int d = tid >> 2, pi = tid & 3;
        const float* p = part + ((size_t)(b * 512 + h * 64 + d)) * 16 + pi * 4;
        float s = p[0] + p[1] + p[2] + p[3];
        s += __shfl_xor_sync(0xffffffffu, s, 1);
        s += __shfl_xor_sync(0xffffffffu, s, 2);
        if (pi == 0) vm_sm[d] = s * (1.0f / 2048.0f);
        __syncthreads();
    }

    // fully-degenerate block: vmean everywhere, exit
    {
        int blk_lo = kbase0 < 0 ? 0 : kbase0;
        if (blk_lo >= xl) {
            const int row = tid >> 2;
            const int cg = (tid & 3) * 16;
            uint32_t* crow = (uint32_t*)CTXH + (size_t)(b * S_ + q0 + row) * 256
                             + h * 32 + (cg >> 1);
#pragma unroll
            for (int k = 0; k < 8; k++)
                crow[k] = pack1(vm_sm[cg + 2 * k], vm_sm[cg + 2 * k + 1]);
            return;
        }
    }

    int cmax = (xl - kbase0 + 63) >> 6;
    if (cmax > 5) cmax = 5;

    const int wm = (wid & 3) * 16;
    const int wn = (wid >> 2) * 32;
    const int qr = lane >> 2, qc = (lane & 3) * 2;
    const int lrow = tid >> 2;
    const int lcs = (tid & 3) * 2;

    {
        const char* qsrc = (const char*)Q2h + ((size_t)(b * S_ + q0 + lrow) * DM_ + h * 64) * 2;
#pragma unroll
        for (int u = 0; u < 2; u++)
            cp_async16(sb + AQ2 + lrow * 144 + (lcs + u) * 16, qsrc + (lcs + u) * 16);
    }
#pragma unroll
    for (int c = 0; c < 2; c++) {
        if (c < cmax) {
            const int jabs = kbase0 + c * 64 + lrow;
            const bool valid = (jabs >= 0) && (jabs < S_);
            const char* ksrc = (const char*)K2h + ((size_t)(b * S_ + (valid ? jabs : 0)) * DM_ + h * 64) * 2;
            const uint32_t buf = sb + (c ? AV2 : AK2);
            const uint32_t n = valid ? 16u : 0u;
#pragma unroll
            for (int u = 0; u < 2; u++)
                cp_async16z(buf + lrow * 144 + (lcs + u) * 16, ksrc + (lcs + u) * 16, n);
        }
        CP_COMMIT();
    }

#pragma unroll
    for (int c = 0; c < 5; c++) {
        if (c < 4) { CP_WAIT(1); } else { CP_WAIT(0); }
        __syncthreads();
        if (c < cmax) {
            const uint32_t kbuf = sb + ((c & 1) ? AV2 : AK2);
            const int kb = kbase0 + c * 64;

            float acc[4][4];
#pragma unroll
            for (int nf = 0; nf < 4; nf++)
#pragma unroll
                for (int u = 0; u < 4; u++) acc[nf][u] = 0.f;

#pragma unroll
            for (int ks = 0; ks < 4; ks++) {
                const int cb = ks * 32 + (lane >> 4) * 16;
                uint32_t a[4];
                ldmx4(a[0], a[1], a[2], a[3], sb + AQ2 + (wm + (lane & 15)) * 144 + cb);
                uint32_t bf[2][4];
#pragma unroll
                for (int nh = 0; nh < 2; nh++) {
                    const int r = wn + nh * 16 + (lane & 15);
                    ldmx4(bf[nh][0], bf[nh][1], bf[nh][2], bf[nh][3], kbuf + r * 144 + cb);
                }
#pragma unroll
                for (int nf = 0; nf < 4; nf++) {
                    const uint32_t b0 = bf[nf >> 1][(nf & 1)];
                    const uint32_t b1 = bf[nf >> 1][(nf & 1) + 2];
                    mma16816(acc[nf], a, b0, b1);
                }
            }

            const int i0 = wm + qr, iabs0 = q0 + i0;
            const int i1 = i0 + 8,  iabs1 = iabs0 + 8;
#pragma unroll
            for (int nf = 0; nf < 4; nf++) {
#pragma unroll
                for (int cc = 0; cc < 2; cc++) {
                    const int col = wn + nf * 8 + qc + cc;
                    const int jabs = kb + col;
                    const bool jok = (jabs >= 0) && (jabs < xl);
                    const bool v0 = jok && (jabs - iabs0 <= 128) && (iabs0 - jabs <= 128);
                    const bool v1 = jok && (jabs - iabs1 <= 128) && (iabs1 - jabs <= 128);
                    Ss[i0 * 325 + c * 64 + col] = v0 ? acc[nf][cc] * 0.125f : -1e30f;
                    Ss[i1 * 325 + c * 64 + col] = v1 ? acc[nf][cc + 2] * 0.125f : -1e30f;
                }
            }
        }
        __syncthreads();
        if (c + 2 < cmax) {
            const int jabs = kbase0 + (c + 2) * 64 + lrow;
            const bool valid = (jabs >= 0) && (jabs < S_);
            const char* ksrc = (const char*)K2h + ((size_t)(b * S_ + (valid ? jabs : 0)) * DM_ + h * 64) * 2;
            const uint32_t buf = sb + ((c & 1) ? AV2 : AK2);
            const uint32_t n = valid ? 16u : 0u;
#pragma unroll
            for (int u = 0; u < 2; u++)
                cp_async16z(buf + lrow * 144 + (lcs + u) * 16, ksrc + (lcs + u) * 16, n);
        }
        CP_COMMIT();
    }

#pragma unroll
    for (int c = 0; c < 2; c++) {
        if (c < cmax) {
            const char* vsrc = (const char*)V2T + ((size_t)((b * 8 + h) * 64 + lrow) * 2304) * 2
                               + (size_t)(q0 + c * 64) * 2;
            const uint32_t buf = sb + (c ? AV2 : AK2);
#pragma unroll
            for (int u = 0; u < 2; u++)
                cp_async16(buf + lrow * 144 + (lcs + u) * 16, vsrc + (lcs + u) * 16);
        }
        CP_COMMIT();
    }

    {
        const int limit = cmax * 64;
        for (int rr = 0; rr < 8; rr++) {
            const int i = wid * 8 + rr;
            float* row = Ss + i * 325;
            float vals[10];
            float m = -3.0e38f;
#pragma unroll
            for (int t = 0; t < 10; t++) {
                vals[t] = (lane + 32 * t < limit) ? row[lane + 32 * t] : -1e30f;
                m = fmaxf(m, vals[t]);
            }
#pragma unroll
            for (int o = 16; o; o >>= 1) m = fmaxf(m, __shfl_xor_sync(0xffffffffu, m, o));
            float l = 0.f;
#pragma unroll
            for (int t = 0; t < 10; t++) {
                const float p = __expf(vals[t] - m);
                if (lane + 32 * t < limit) row[lane + 32 * t] = p;
                l += p;
            }
#pragma unroll
            for (int o = 16; o; o >>= 1) l += __shfl_xor_sync(0xffffffffu, l, o);
            if (lane == 0) invl[i] = 1.0f / l;
        }
    }
    __syncthreads();

    float oacc[4][4];
#pragma unroll
    for (int nf = 0; nf < 4; nf++)
#pragma unroll
        for (int u = 0; u < 4; u++) oacc[nf][u] = 0.f;

#pragma unroll
    for (int c = 0; c < 5; c++) {
        if (c < cmax) {
            const int row = tid & 63, jg = tid >> 6;
            const float* srow = Ss + row * 325 + c * 64 + jg * 16;
            uint32_t w[8];
#pragma unroll
            for (int t = 0; t < 8; t++) w[t] = pack1(srow[2 * t], srow[2 * t + 1]);
            uint4* dst = (uint4*)(smc + AQ2 + row * 144 + jg * 32);
            dst[0] = ((uint4*)w)[0];
            dst[1] = ((uint4*)w)[1];
        }
        if (c < 4) { CP_WAIT(1); } else { CP_WAIT(0); }
        __syncthreads();

        if (c < cmax) {
            const uint32_t vbuf = sb + ((c & 1) ? AV2 : AK2);
#pragma unroll
            for (int ks = 0; ks < 4; ks++) {
                const int cb = ks * 32 + (lane >> 4) * 16;
                uint32_t a[4];
                ldmx4(a[0], a[1], a[2], a[3], sb + AQ2 + (wm + (lane & 15)) * 144 + cb);
                uint32_t bf[2][4];
#pragma unroll
                for (int nh = 0; nh < 2; nh++) {
                    const int r = wn + nh * 16 + (lane & 15);
                    ldmx4(bf[nh][0], bf[nh][1], bf[nh][2], bf[nh][3], vbuf + r * 144 + cb);
                }
#pragma unroll
                for (int nf = 0; nf < 4; nf++) {
                    const uint32_t b0 = bf[nf >> 1][(nf & 1)];
                    const uint32_t b1 = bf[nf >> 1][(nf & 1) + 2];
                    mma16816(oacc[nf], a, b0, b1);
                }
            }
        }
        __syncthreads();
        if (c + 2 < cmax) {
            const char* vsrc = (const char*)V2T + ((size_t)((b * 8 + h) * 64 + lrow) * 2304) * 2
                               + (size_t)(q0 + (c + 2) * 64) * 2;
            const uint32_t buf = sb + ((c & 1) ? AV2 : AK2);
#pragma unroll
            for (int u = 0; u < 2; u++)
                cp_async16(buf + lrow * 144 + (lcs + u) * 16, vsrc + (lcs + u) * 16);
        }
        CP_COMMIT();
    }

    {
        const int i0 = wm + qr;
#pragma unroll
        for (int half = 0; half < 2; half++) {
            const int i = i0 + half * 8;
            const int iabs = q0 + i;
            int lo2 = iabs - 128;
            if (lo2 < 0) lo2 = 0;
            const bool deg = (lo2 >= xl);
            const float il = invl[i];
            uint32_t* crow = (uint32_t*)CTXH + (size_t)(b * S_ + iabs) * 256 + h * 32;
#pragma unroll
            for (int nf = 0; nf < 4; nf++) {
                const int col = wn + nf * 8 + qc;
                const float a = deg ? vm_sm[col]      : oacc[nf][half * 2] * il;
                const float bb = deg ? vm_sm[col + 1] : oacc[nf][half * 2 + 1] * il;
                crow[col >> 1] = pack1(a, bb);
            }
        }
    }
}

// ================= launch =================
extern "C" void kernel_launch(void* const* d_in, const int* in_sizes, int n_in,
                              void* d_out, int out_size) {
    const float* x  = (const float*)d_in[0];
    const float* Wq = (const float*)d_in[1];
    const float* bq = (const float*)d_in[2];
    const float* Wk = (const float*)d_in[3];
    const float* bk = (const float*)d_in[4];
    const float* Wv = (const float*)d_in[5];
    const float* bv = (const float*)d_in[6];
    const float* Wo = (const float*)d_in[7];
    const float* bo = (const float*)d_in[8];
    const int* xlen = (const int*)d_in[9];
    float* out = (float*)d_out;

    float *part;
    __half *xh, *q2h, *k2h, *w1t, *v2t;
    cudaGetSymbolAddress((void**)&part, g_part);
    cudaGetSymbolAddress((void**)&xh, g_xh);
    cudaGetSymbolAddress((void**)&q2h, g_q2h);
    cudaGetSymbolAddress((void**)&k2h, g_k2h);
    cudaGetSymbolAddress((void**)&w1t, g_w1t);
    cudaGetSymbolAddress((void**)&v2t, g_v2t);

    cudaFuncSetAttribute(gemm_qkv, cudaFuncAttributeMaxDynamicSharedMemorySize, GEMM_SMEM);
    cudaFuncSetAttribute(gemm_out, cudaFuncAttributeMaxDynamicSharedMemorySize, GEMM_SMEM);
    cudaFuncSetAttribute(attn_mma2, cudaFuncAttributeMaxDynamicSharedMemorySize, ATT_SMEM);

    const dim3 qkv_grid(B_ * S_ / 256, DM_ / 128, 3);
    const dim3 out_grid(B_ * S_ / 256, DM_ / 128);

    prep<<<3072, 256>>>(x, Wq, Wk, Wv, Wo, xh, w1t);

    gemm_qkv<<<qkv_grid, 256, GEMM_SMEM>>>(xh, w1t, bq, bk, bv, xlen, q2h, k2h, v2t, part);

    attn_mma2<<<dim3(S_ / 64, H_, B_), 256, ATT_SMEM>>>(q2h, k2h, v2t, part, xlen, xh);

    gemm_out<<<out_grid, 256, GEMM_SMEM>>>(xh, w1t + 3 * (size_t)DM_ * DM_, bo, out);
}

// round 17
// speedup vs baseline: 3.2351x; 1.0391x over previous
#include <cuda_runtime.h>
#include <cuda_fp16.h>
#include <cstdint>

#define B_  4
#define S_  2048
#define DM_ 512
#define H_  8
#define D_  64

// ================= helpers =================
__device__ __forceinline__ uint32_t smem_u32(const void* p) {
    uint32_t a;
    asm("{ .reg .u64 t; cvta.to.shared.u64 t, %1; cvt.u32.u64 %0, t; }" : "=r"(a) : "l"(p));
    return a;
}
#define SWZ128(off) ((off) ^ (((off) >> 3) & 0x70))

__device__ __forceinline__ void cp_async16(uint32_t dst, const void* src) {
    asm volatile("cp.async.cg.shared.global [%0], [%1], 16;" :: "r"(dst), "l"(src));
}
__device__ __forceinline__ void cp_async16z(uint32_t dst, const void* src, uint32_t n) {
    asm volatile("cp.async.cg.shared.global [%0], [%1], 16, %2;" :: "r"(dst), "l"(src), "r"(n));
}
#define CP_COMMIT() asm volatile("cp.async.commit_group;" ::: "memory")
#define CP_WAIT(n)  asm volatile("cp.async.wait_group %0;" :: "n"(n) : "memory")

__device__ __forceinline__ void ldmx4(uint32_t& r0, uint32_t& r1, uint32_t& r2, uint32_t& r3,
                                      uint32_t addr) {
    asm volatile("ldmatrix.sync.aligned.m8n8.x4.shared.b16 {%0,%1,%2,%3}, [%4];"
                 : "=r"(r0), "=r"(r1), "=r"(r2), "=r"(r3) : "r"(addr));
}
__device__ __forceinline__ void mma16816(float* c, const uint32_t* a, uint32_t b0, uint32_t b1) {
    asm volatile(
        "mma.sync.aligned.m16n8k16.row.col.f32.f16.f16.f32 "
        "{%0,%1,%2,%3}, {%4,%5,%6,%7}, {%8,%9}, {%0,%1,%2,%3};"
        : "+f"(c[0]), "+f"(c[1]), "+f"(c[2]), "+f"(c[3])
        : "r"(a[0]), "r"(a[1]), "r"(a[2]), "r"(a[3]), "r"(b0), "r"(b1));
}
__device__ __forceinline__ uint32_t pack1(float a, float b) {
    return (uint32_t)__half_as_ushort(__float2half_rn(a)) |
           ((uint32_t)__half_as_ushort(__float2half_rn(b)) << 16);
}

// ================= scratch =================
__device__ float g_part[B_ * DM_ * 16];
__device__ __half g_xh[B_ * S_ * DM_];        // x fp16; later ctx fp16
__device__ __half g_q2h[B_ * S_ * DM_];
__device__ __half g_k2h[B_ * S_ * DM_];
__device__ __half g_w1t[4 * DM_ * DM_];       // Wq,Wk,Wv,Wo fp16 transposed [N,512]
__device__ __half g_v2t[2048 * 2304];         // V dims-major fp16, tokens padded

// ================= combined prep =================
__global__ __launch_bounds__(256) void prep(const float* __restrict__ X,
                                            const float* __restrict__ W0,
                                            const float* __restrict__ W1,
                                            const float* __restrict__ W2,
                                            const float* __restrict__ W3,
                                            __half* __restrict__ XH,
                                            __half* __restrict__ W1T) {
    const int bid = blockIdx.x;
    const int tid = threadIdx.x;
    if (bid < 2048) {
        const int idx = bid * 256 + tid;
        const int m = idx >> 6, g = idx & 63;
        const float4 f0 = *(const float4*)(X + (size_t)m * 512 + g * 8);
        const float4 f1 = *(const float4*)(X + (size_t)m * 512 + g * 8 + 4);
        uint32_t p[4];
        p[0] = pack1(f0.x, f0.y); p[1] = pack1(f0.z, f0.w);
        p[2] = pack1(f1.x, f1.y); p[3] = pack1(f1.z, f1.w);
        *(uint4*)(XH + (size_t)m * 512 + g * 8) = *(uint4*)p;
    } else {
        __shared__ float t[32][33];
        const int wb = bid - 2048;
        const int z = wb >> 8;
        const int tl = wb & 255;
        const int n0 = (tl & 15) * 32, k0 = (tl >> 4) * 32;
        const float* W = (z == 0) ? W0 : (z == 1) ? W1 : (z == 2) ? W2 : W3;
        const int tx = tid & 31, ty8 = tid >> 5;
#pragma unroll
        for (int r = 0; r < 4; r++)
            t[ty8 + 8 * r][tx] = W[(size_t)(k0 + ty8 + 8 * r) * 512 + n0 + tx];
        __syncthreads();
#pragma unroll
        for (int r = 0; r < 4; r++)
            W1T[(size_t)z * DM_ * DM_ + (size_t)(n0 + ty8 + 8 * r) * DM_ + (k0 + tx)] =
                __float2half_rn(t[tx][ty8 + 8 * r]);
    }
}

// ================= 256x128 HMMA GEMM mainloop (BK=128, 2-stage) — QKV =================
#define GSTAGE 98304
#define GEMM_SMEM (2 * GSTAGE + 1024)
#define NCH4 4

#define GEMM_LOADCHUNK(stg, coff)                                                          \
    do {                                                                                   \
        _Pragma("unroll")                                                                  \
        for (int seg = 0; seg < 8; seg++) {                                                \
            cp_async16((stg) + (a_doff ^ (seg * 16)), l_srcA + (coff) + seg * 8);          \
            cp_async16((stg) + 32768 + (a_doff ^ (seg * 16)), l_srcA + (coff) + 64 + seg * 8); \
        }                                                                                  \
        _Pragma("unroll")                                                                  \
        for (int u = 0; u < 4; u++) {                                                      \
            cp_async16((stg) + 65536 + (b_doff ^ (u * 16)), l_srcB + (coff) + u * 8);      \
            cp_async16((stg) + 81920 + (b_doff ^ (u * 16)), l_srcB + (coff) + 64 + u * 8); \
        }                                                                                  \
    } while (0)

#define GEMM_MAINLOOP256(APTR, BPTR)                                                       \
    extern __shared__ char smraw[];                                                       \
    const uint32_t sbase = (smem_u32(smraw) + 1023) & ~1023u;                             \
    const int tid = threadIdx.x;                                                          \
    const int wid = tid >> 5, lane = tid & 31;                                            \
    const int bm = blockIdx.x * 256, bn = blockIdx.y * 128;                               \
    const int wm0 = (wid & 3) * 64, wn0 = (wid >> 2) * 64;                                \
    const __half* l_srcA = (APTR) + (size_t)(bm + tid) * DM_;                             \
    const __half* l_srcB = (BPTR) + (size_t)(bn + (tid >> 1)) * DM_ + (tid & 1) * 32;     \
    const uint32_t a_doff = SWZ128(tid * 128);                                            \
    const uint32_t b_doff = SWZ128((tid >> 1) * 128 + (tid & 1) * 64);                    \
    float acc[4][8][4];                                                                   \
    _Pragma("unroll")                                                                     \
    for (int a = 0; a < 4; a++)                                                           \
        _Pragma("unroll")                                                                 \
        for (int b = 0; b < 8; b++)                                                       \
            _Pragma("unroll")                                                             \
            for (int c = 0; c < 4; c++) acc[a][b][c] = 0.f;                               \
    GEMM_LOADCHUNK(sbase, 0);                                                             \
    CP_COMMIT();                                                                          \
    for (int c = 0; c < NCH4; c++) {                                                      \
        CP_WAIT(0);                                                                       \
        __syncthreads();                                                                  \
        if (c + 1 < NCH4) {                                                               \
            const uint32_t st = sbase + ((c + 1) & 1) * GSTAGE;                           \
            GEMM_LOADCHUNK(st, (c + 1) * 128);                                            \
        }                                                                                 \
        CP_COMMIT();                                                                      \
        const uint32_t stg = sbase + (c & 1) * GSTAGE;                                    \
        _Pragma("unroll")                                                                 \
        for (int ks = 0; ks < 8; ks++) {                                                  \
            const uint32_t abuf = stg + (ks >> 2) * 32768;                                \
            const uint32_t bbuf = stg + 65536 + (ks >> 2) * 16384;                        \
            const int cb = (ks & 3) * 32 + ((lane >> 4) * 16);                            \
            uint32_t bf[4][4];                                                            \
            _Pragma("unroll")                                                             \
            for (int bh = 0; bh < 4; bh++) {                                              \
                const int r = wn0 + bh * 16 + (lane & 15);                                \
                ldmx4(bf[bh][0], bf[bh][1], bf[bh][2], bf[bh][3],                         \
                      bbuf + SWZ128(r * 128 + cb));                                       \
            }                                                                             \
            _Pragma("unroll")                                                             \
            for (int mf = 0; mf < 4; mf++) {                                              \
                uint32_t a[4];                                                            \
                const int r = wm0 + mf * 16 + (lane & 15);                                \
                ldmx4(a[0], a[1], a[2], a[3], abuf + SWZ128(r * 128 + cb));               \
                _Pragma("unroll")                                                         \
                for (int nf = 0; nf < 8; nf++) {                                          \
                    const uint32_t b0 = bf[nf >> 1][(nf & 1)];                            \
                    const uint32_t b1 = bf[nf >> 1][(nf & 1) + 2];                        \
                    mma16816(acc[mf][nf], a, b0, b1);                                     \
                }                                                                         \
            }                                                                             \
        }                                                                                 \
    }                                                                                     \
    const int qr = lane >> 2, qc = (lane & 3) * 2;

// unified QKV (unchanged shape)
__global__ __launch_bounds__(256, 1) void gemm_qkv(const __half* __restrict__ XH,
                                                   const __half* __restrict__ W1T,
                                                   const float* __restrict__ bq,
                                                   const float* __restrict__ bk,
                                                   const float* __restrict__ bv,
                                                   const int* __restrict__ XLEN,
                                                   __half* __restrict__ Q2h,
                                                   __half* __restrict__ K2h,
                                                   __half* __restrict__ V2T,
                                                   float* __restrict__ part) {
    const int z = blockIdx.z;
    {
        const int bm_pre = blockIdx.x * 256;
        const int xl = XLEN[bm_pre >> 11];
        const int tok = bm_pre & 2047;
        if (z == 1 && tok >= xl) return;
        if (z == 0 && tok >= xl + 128) return;
    }
    GEMM_MAINLOOP256(XH, W1T + (size_t)z * DM_ * DM_)
    const float* bias = (z == 0) ? bq : (z == 1) ? bk : bv;
    if (z == 2) {
        __syncthreads();
        __half* hsm = (__half*)(smraw + (sbase - smem_u32(smraw)));
#pragma unroll
        for (int mf = 0; mf < 4; mf++) {
            const int row0 = wm0 + mf * 16 + qr;
#pragma unroll
            for (int nf = 0; nf < 8; nf++) {
                const int col = wn0 + nf * 8 + qc;
                const float b0 = bias[bn + col], b1 = bias[bn + col + 1];
                hsm[col * 264 + row0]           = __float2half_rn(acc[mf][nf][0] + b0);
                hsm[(col + 1) * 264 + row0]     = __float2half_rn(acc[mf][nf][1] + b1);
                hsm[col * 264 + row0 + 8]       = __float2half_rn(acc[mf][nf][2] + b0);
                hsm[(col + 1) * 264 + row0 + 8] = __float2half_rn(acc[mf][nf][3] + b1);
            }
        }
        __syncthreads();
        const int tok0 = bm & 2047;
        const int bb = bm >> 11;
        const int chunk = tok0 >> 8;
        const int col = tid >> 1, seg = (tid & 1) * 128;
        const __half* src = hsm + col * 264 + seg;
        float s = 0.f;
#pragma unroll
        for (int k2 = 0; k2 < 128; k2++) s += __half2float(src[k2]);
        const int colg = bn + col;
        part[((size_t)(bb * 512 + colg)) * 16 + chunk * 2 + (tid & 1)] = s;
        if (tok0 < XLEN[bb] + 64) {
            __half* dst = V2T + ((size_t)((bb * 8 + (colg >> 6)) * 64 + (colg & 63))) * 2304
                          + 128 + tok0 + seg;
#pragma unroll
            for (int u = 0; u < 16; u++)
                ((uint4*)dst)[u] = ((const uint4*)src)[u];
        }
    } else {
        uint32_t* t32 = (uint32_t*)((z == 0) ? Q2h : K2h);
#pragma unroll
        for (int mf = 0; mf < 4; mf++) {
            const int row = bm + wm0 + mf * 16 + qr;
#pragma unroll
            for (int nf = 0; nf < 8; nf++) {
                const int col = bn + wn0 + nf * 8 + qc;
                const float b0 = bias[col], b1 = bias[col + 1];
                const uint32_t idx0 = (uint32_t)row * 256 + (col >> 1);
                const uint32_t idx1 = idx0 + 8 * 256;
                t32[idx0] = pack1(acc[mf][nf][0] + b0, acc[mf][nf][1] + b1);
                t32[idx1] = pack1(acc[mf][nf][2] + b0, acc[mf][nf][3] + b1);
            }
        }
    }
}

// ================= 128x128 output GEMM (BK=64, 2-stage, 64KB smem -> 3 CTAs/SM) =================
#define G128_STAGE 32768
#define G128_SMEM (2 * G128_STAGE + 1024)

__global__ __launch_bounds__(256, 2) void gemm_out(const __half* __restrict__ CTXH,
                                                   const __half* __restrict__ WOT,
                                                   const float* __restrict__ bias,
                                                   float* __restrict__ C) {
    extern __shared__ char smraw[];
    const uint32_t sbase = (smem_u32(smraw) + 1023) & ~1023u;
    const int tid = threadIdx.x;
    const int wid = tid >> 5, lane = tid & 31;
    const int bm = blockIdx.x * 128, bn = blockIdx.y * 128;
    const int wm0 = (wid & 3) * 32, wn0 = (wid >> 2) * 64;

    const __half* l_srcA = CTXH + (size_t)(bm + (tid >> 1)) * DM_ + (tid & 1) * 32;
    const __half* l_srcB = WOT + (size_t)(bn + (tid >> 1)) * DM_ + (tid & 1) * 32;
    const uint32_t ab_doff = SWZ128((tid >> 1) * 128 + (tid & 1) * 64);

    float acc[2][8][4];
#pragma unroll
    for (int a = 0; a < 2; a++)
#pragma unroll
        for (int b = 0; b < 8; b++)
#pragma unroll
            for (int c = 0; c < 4; c++) acc[a][b][c] = 0.f;

    // preload chunk 0
#pragma unroll
    for (int u = 0; u < 4; u++) {
        cp_async16(sbase + (ab_doff ^ (u * 16)), l_srcA + u * 8);
        cp_async16(sbase + 16384 + (ab_doff ^ (u * 16)), l_srcB + u * 8);
    }
    CP_COMMIT();

    for (int c = 0; c < 8; c++) {
        CP_WAIT(0);
        __syncthreads();
        if (c + 1 < 8) {
            const uint32_t st = sbase + ((c + 1) & 1) * G128_STAGE;
#pragma unroll
            for (int u = 0; u < 4; u++) {
                cp_async16(st + (ab_doff ^ (u * 16)), l_srcA + (c + 1) * 64 + u * 8);
                cp_async16(st + 16384 + (ab_doff ^ (u * 16)), l_srcB + (c + 1) * 64 + u * 8);
            }
        }
        CP_COMMIT();
        const uint32_t stg = sbase + (c & 1) * G128_STAGE;
#pragma unroll
        for (int ks = 0; ks < 4; ks++) {
            const int cb = ks * 32 + ((lane >> 4) * 16);
            uint32_t bf[4][4];
#pragma unroll
            for (int bh = 0; bh < 4; bh++) {
                const int r = wn0 + bh * 16 + (lane & 15);
                ldmx4(bf[bh][0], bf[bh][1], bf[bh][2], bf[bh][3],
                      stg + 16384 + SWZ128(r * 128 + cb));
            }
#pragma unroll
            for (int mf = 0; mf < 2; mf++) {
                uint32_t a[4];
                const int r = wm0 + mf * 16 + (lane & 15);
                ldmx4(a[0], a[1], a[2], a[3], stg + SWZ128(r * 128 + cb));
#pragma unroll
                for (int nf = 0; nf < 8; nf++) {
                    const uint32_t b0 = bf[nf >> 1][(nf & 1)];
                    const uint32_t b1 = bf[nf >> 1][(nf & 1) + 2];
                    mma16816(acc[mf][nf], a, b0, b1);
                }
            }
        }
    }

    const int qr = lane >> 2, qc = (lane & 3) * 2;
#pragma unroll
    for (int mf = 0; mf < 2; mf++) {
        const int row = bm + wm0 + mf * 16 + qr;
#pragma unroll
        for (int nf = 0; nf < 8; nf++) {
            const int col = bn + wn0 + nf * 8 + qc;
            const float b0 = bias[col], b1 = bias[col + 1];
            float2 lo, hi;
            lo.x = acc[mf][nf][0] + b0; lo.y = acc[mf][nf][1] + b1;
            hi.x = acc[mf][nf][2] + b0; hi.y = acc[mf][nf][3] + b1;
            *(float2*)(C + (size_t)row * 512 + col) = lo;
            *(float2*)(C + (size_t)(row + 8) * 512 + col) = hi;
        }
    }
}

// ================= HMMA banded attention (inline vmean, xl-aware skipping) =================
#define AQ2 0
#define AK2 9216
#define AV2 18432
#define ASF 27648
#define AIL 110848
#define AVM 111104
#define ATT_SMEM 111360

__global__ __launch_bounds__(256) void attn_mma2(const __half* __restrict__ Q2h,
                                                 const __half* __restrict__ K2h,
                                                 const __half* __restrict__ V2T,
                                                 const float* __restrict__ part,
                                                 const int* __restrict__ XLEN,
                                                 __half* __restrict__ CTXH) {
    extern __shared__ char smc[];
    const uint32_t sb = smem_u32(smc);
    float* Ss = (float*)(smc + ASF);
    float* invl = (float*)(smc + AIL);
    float* vm_sm = (float*)(smc + AVM);

    const int tid = threadIdx.x;
    const int wid = tid >> 5, lane = tid & 31;
    const int q0 = blockIdx.x * 64;
    const int h = blockIdx.y;
    const int b = blockIdx.z;
    const int xl = XLEN[b];
    const int kbase0 = q0 - 128;

    int maxlo = q0 + 63 - 128; if (maxlo < 0) maxlo = 0;
    const bool need_vm = (maxlo >= xl);
    if (need_vm) {
        const int d = tid >> 2, pi = tid & 3;
        const float* p = part + ((size_t)(b * 512 + h * 64 + d)) * 16 + pi * 4;
        float s = p[0] + p[1] + p[2] + p[3];
        s += __shfl_xor_sync(0xffffffffu, s, 1);
        s += __shfl_xor_sync(0xffffffffu, s, 2);
        if (pi == 0) vm_sm[d] = s * (1.0f / 2048.0f);
        __syncthreads();
    }

    {
        int blk_lo = kbase0 < 0 ? 0 : kbase0;
        if (blk_lo >= xl) {
            const int row = tid >> 2;
            const int cg = (tid & 3) * 16;
            uint32_t* crow = (uint32_t*)CTXH + (size_t)(b * S_ + q0 + row) * 256
                             + h * 32 + (cg >> 1);
#pragma unroll
            for (int k = 0; k < 8; k++)
                crow[k] = pack1(vm_sm[cg + 2 * k], vm_sm[cg + 2 * k + 1]);
            return;
        }
    }

    int cmax = (xl - kbase0 + 63) >> 6;
    if (cmax > 5) cmax = 5;

    const int wm = (wid & 3) * 16;
    const int wn = (wid >> 2) * 32;
    const int qr = lane >> 2, qc = (lane & 3) * 2;
    const int lrow = tid >> 2;
    const int lcs = (tid & 3) * 2;

    {
        const char* qsrc = (const char*)Q2h + ((size_t)(b * S_ + q0 + lrow) * DM_ + h * 64) * 2;
#pragma unroll
        for (int u = 0; u < 2; u++)
            cp_async16(sb + AQ2 + lrow * 144 + (lcs + u) * 16, qsrc + (lcs + u) * 16);
    }
#pragma unroll
    for (int c = 0; c < 2; c++) {
        if (c < cmax) {
            const int jabs = kbase0 + c * 64 + lrow;
            const bool valid = (jabs >= 0) && (jabs < S_);
            const char* ksrc = (const char*)K2h + ((size_t)(b * S_ + (valid ? jabs : 0)) * DM_ + h * 64) * 2;
            const uint32_t buf = sb + (c ? AV2 : AK2);
            const uint32_t n = valid ? 16u : 0u;
#pragma unroll
            for (int u = 0; u < 2; u++)
                cp_async16z(buf + lrow * 144 + (lcs + u) * 16, ksrc + (lcs + u) * 16, n);
        }
        CP_COMMIT();
    }

#pragma unroll
    for (int c = 0; c < 5; c++) {
        if (c < 4) { CP_WAIT(1); } else { CP_WAIT(0); }
        __syncthreads();
        if (c < cmax) {
            const uint32_t kbuf = sb + ((c & 1) ? AV2 : AK2);
            const int kb = kbase0 + c * 64;

            float acc[4][4];
#pragma unroll
            for (int nf = 0; nf < 4; nf++)
#pragma unroll
                for (int u = 0; u < 4; u++) acc[nf][u] = 0.f;

#pragma unroll
            for (int ks = 0; ks < 4; ks++) {
                const int cb = ks * 32 + (lane >> 4) * 16;
                uint32_t a[4];
                ldmx4(a[0], a[1], a[2], a[3], sb + AQ2 + (wm + (lane & 15)) * 144 + cb);
                uint32_t bf[2][4];
#pragma unroll
                for (int nh = 0; nh < 2; nh++) {
                    const int r = wn + nh * 16 + (lane & 15);
                    ldmx4(bf[nh][0], bf[nh][1], bf[nh][2], bf[nh][3], kbuf + r * 144 + cb);
                }
#pragma unroll
                for (int nf = 0; nf < 4; nf++) {
                    const uint32_t b0 = bf[nf >> 1][(nf & 1)];
                    const uint32_t b1 = bf[nf >> 1][(nf & 1) + 2];
                    mma16816(acc[nf], a, b0, b1);
                }
            }

            const int i0 = wm + qr, iabs0 = q0 + i0;
            const int i1 = i0 + 8,  iabs1 = iabs0 + 8;
#pragma unroll
            for (int nf = 0; nf < 4; nf++) {
#pragma unroll
                for (int cc = 0; cc < 2; cc++) {
                    const int col = wn + nf * 8 + qc + cc;
                    const int jabs = kb + col;
                    const bool jok = (jabs >= 0) && (jabs < xl);
                    const bool v0 = jok && (jabs - iabs0 <= 128) && (iabs0 - jabs <= 128);
                    const bool v1 = jok && (jabs - iabs1 <= 128) && (iabs1 - jabs <= 128);
                    Ss[i0 * 325 + c * 64 + col] = v0 ? acc[nf][cc] * 0.125f : -1e30f;
                    Ss[i1 * 325 + c * 64 + col] = v1 ? acc[nf][cc + 2] * 0.125f : -1e30f;
                }
            }
        }
        __syncthreads();
        if (c + 2 < cmax) {
            const int jabs = kbase0 + (c + 2) * 64 + lrow;
            const bool valid = (jabs >= 0) && (jabs < S_);
            const char* ksrc = (const char*)K2h + ((size_t)(b * S_ + (valid ? jabs : 0)) * DM_ + h * 64) * 2;
            const uint32_t buf = sb + ((c & 1) ? AV2 : AK2);
            const uint32_t n = valid ? 16u : 0u;
#pragma unroll
            for (int u = 0; u < 2; u++)
                cp_async16z(buf + lrow * 144 + (lcs + u) * 16, ksrc + (lcs + u) * 16, n);
        }
        CP_COMMIT();
    }

#pragma unroll
    for (int c = 0; c < 2; c++) {
        if (c < cmax) {
            const char* vsrc = (const char*)V2T + ((size_t)((b * 8 + h) * 64 + lrow) * 2304) * 2
                               + (size_t)(q0 + c * 64) * 2;
            const uint32_t buf = sb + (c ? AV2 : AK2);
#pragma unroll
            for (int u = 0; u < 2; u++)
                cp_async16(buf + lrow * 144 + (lcs + u) * 16, vsrc + (lcs + u) * 16);
        }
        CP_COMMIT();
    }

    {
        const int limit = cmax * 64;
        for (int rr = 0; rr < 8; rr++) {
            const int i = wid * 8 + rr;
            float* row = Ss + i * 325;
            float vals[10];
            float m = -3.0e38f;
#pragma unroll
            for (int t = 0; t < 10; t++) {
                vals[t] = (lane + 32 * t < limit) ? row[lane + 32 * t] : -1e30f;
                m = fmaxf(m, vals[t]);
            }
#pragma unroll
            for (int o = 16; o; o >>= 1) m = fmaxf(m, __shfl_xor_sync(0xffffffffu, m, o));
            float l = 0.f;
#pragma unroll
            for (int t = 0; t < 10; t++) {
                const float p = __expf(vals[t] - m);
                if (lane + 32 * t < limit) row[lane + 32 * t] = p;
                l += p;
            }
#pragma unroll
            for (int o = 16; o; o >>= 1) l += __shfl_xor_sync(0xffffffffu, l, o);
            if (lane == 0) invl[i] = 1.0f / l;
        }
    }
    __syncthreads();

    float oacc[4][4];
#pragma unroll
    for (int nf = 0; nf < 4; nf++)
#pragma unroll
        for (int u = 0; u < 4; u++) oacc[nf][u] = 0.f;

#pragma unroll
    for (int c = 0; c < 5; c++) {
        if (c < cmax) {
            const int row = tid & 63, jg = tid >> 6;
            const float* srow = Ss + row * 325 + c * 64 + jg * 16;
            uint32_t w[8];
#pragma unroll
            for (int t = 0; t < 8; t++) w[t] = pack1(srow[2 * t], srow[2 * t + 1]);
            uint4* dst = (uint4*)(smc + AQ2 + row * 144 + jg * 32);
            dst[0] = ((uint4*)w)[0];
            dst[1] = ((uint4*)w)[1];
        }
        if (c < 4) { CP_WAIT(1); } else { CP_WAIT(0); }
        __syncthreads();

        if (c < cmax) {
            const uint32_t vbuf = sb + ((c & 1) ? AV2 : AK2);
#pragma unroll
            for (int ks = 0; ks < 4; ks++) {
                const int cb = ks * 32 + (lane >> 4) * 16;
                uint32_t a[4];
                ldmx4(a[0], a[1], a[2], a[3], sb + AQ2 + (wm + (lane & 15)) * 144 + cb);
                uint32_t bf[2][4];
#pragma unroll
                for (int nh = 0; nh < 2; nh++) {
                    const int r = wn + nh * 16 + (lane & 15);
                    ldmx4(bf[nh][0], bf[nh][1], bf[nh][2], bf[nh][3], vbuf + r * 144 + cb);
                }
#pragma unroll
                for (int nf = 0; nf < 4; nf++) {
                    const uint32_t b0 = bf[nf >> 1][(nf & 1)];
                    const uint32_t b1 = bf[nf >> 1][(nf & 1) + 2];
                    mma16816(oacc[nf], a, b0, b1);
                }
            }
        }
        __syncthreads();
        if (c + 2 < cmax) {
            const char* vsrc = (const char*)V2T + ((size_t)((b * 8 + h) * 64 + lrow) * 2304) * 2
                               + (size_t)(q0 + (c + 2) * 64) * 2;
            const uint32_t buf = sb + ((c & 1) ? AV2 : AK2);
#pragma unroll
            for (int u = 0; u < 2; u++)
                cp_async16(buf + lrow * 144 + (lcs + u) * 16, vsrc + (lcs + u) * 16);
        }
        CP_COMMIT();
    }

    {
        const int i0 = wm + qr;
#pragma unroll
        for (int half = 0; half < 2; half++) {
            const int i = i0 + half * 8;
            const int iabs = q0 + i;
            int lo2 = iabs - 128;
            if (lo2 < 0) lo2 = 0;
            const bool deg = (lo2 >= xl);
            const float il = invl[i];
            uint32_t* crow = (uint32_t*)CTXH + (size_t)(b * S_ + iabs) * 256 + h * 32;
#pragma unroll
            for (int nf = 0; nf < 4; nf++) {
                const int col = wn + nf * 8 + qc;
                const float a = deg ? vm_sm[col]      : oacc[nf][half * 2] * il;
                const float bb = deg ? vm_sm[col + 1] : oacc[nf][half * 2 + 1] * il;
                crow[col >> 1] = pack1(a, bb);
            }
        }
    }
}

// ================= launch =================
extern "C" void kernel_launch(void* const* d_in, const int* in_sizes, int n_in,
                              void* d_out, int out_size) {
    const float* x  = (const float*)d_in[0];
    const float* Wq = (const float*)d_in[1];
    const float* bq = (const float*)d_in[2];
    const float* Wk = (const float*)d_in[3];
    const float* bk = (const float*)d_in[4];
    const float* Wv = (const float*)d_in[5];
    const float* bv = (const float*)d_in[6];
    const float* Wo = (const float*)d_in[7];
    const float* bo = (const float*)d_in[8];
    const int* xlen = (const int*)d_in[9];
    float* out = (float*)d_out;

    float *part;
    __half *xh, *q2h, *k2h, *w1t, *v2t;
    cudaGetSymbolAddress((void**)&part, g_part);
    cudaGetSymbolAddress((void**)&xh, g_xh);
    cudaGetSymbolAddress((void**)&q2h, g_q2h);
    cudaGetSymbolAddress((void**)&k2h, g_k2h);
    cudaGetSymbolAddress((void**)&w1t, g_w1t);
    cudaGetSymbolAddress((void**)&v2t, g_v2t);

    cudaFuncSetAttribute(gemm_qkv, cudaFuncAttributeMaxDynamicSharedMemorySize, GEMM_SMEM);
    cudaFuncSetAttribute(gemm_out, cudaFuncAttributeMaxDynamicSharedMemorySize, G128_SMEM);
    cudaFuncSetAttribute(attn_mma2, cudaFuncAttributeMaxDynamicSharedMemorySize, ATT_SMEM);

    const dim3 qkv_grid(B_ * S_ / 256, DM_ / 128, 3);
    const dim3 out_grid(B_ * S_ / 128, DM_ / 128);

    prep<<<3072, 256>>>(x, Wq, Wk, Wv, Wo, xh, w1t);

    gemm_qkv<<<qkv_grid, 256, GEMM_SMEM>>>(xh, w1t, bq, bk, bv, xlen, q2h, k2h, v2t, part);

    attn_mma2<<<dim3(S_ / 64, H_, B_), 256, ATT_SMEM>>>(q2h, k2h, v2t, part, xlen, xh);

    gemm_out<<<out_grid, 256, G128_SMEM>>>(xh, w1t + 3 * (size_t)DM_ * DM_, bo, out);
}